// round 1
// baseline (speedup 1.0000x reference)
#include <cuda_runtime.h>
#include <math.h>

#define BATCH 8
#define CDIM 192
#define C3 576
#define HWD 16384
#define HEADS 4
#define CH 48
#define NCHUNK 16
#define CHUNK 1024

// ---- scratch (device globals; no allocations allowed) ----
__device__ float g_qkv [(size_t)BATCH * C3 * HWD];   // after 1x1 qkv conv
__device__ float g_qkv2[(size_t)BATCH * C3 * HWD];   // after depthwise 3x3
__device__ float g_part_gram[(size_t)BATCH * HEADS * NCHUNK * CH * CH];
__device__ float g_part_nq  [(size_t)BATCH * HEADS * NCHUNK * CH];
__device__ float g_part_nk  [(size_t)BATCH * HEADS * NCHUNK * CH];
__device__ float g_attn     [(size_t)BATCH * HEADS * CH * CH];
__device__ float g_av [(size_t)BATCH * CDIM * HWD];  // attention output

// ============================================================
// Pointwise 1x1 conv = batched GEMM: Y[b,m,n] = sum_k W[m,k] X[b,k,n]
// K = CDIM = 192 always. Block tile 64(M) x 128(N), BK=16, 256 thr, 4x8/thr.
// ============================================================
__global__ __launch_bounds__(256) void pw_conv_kernel(
    const float* __restrict__ Wt, const float* __restrict__ X,
    float* __restrict__ Y, int Mdim)
{
    __shared__ float As[16][64];
    __shared__ float Bs[16][128];
    const int tid = threadIdx.x;
    const int tx = tid & 15, ty = tid >> 4;
    const int n0 = blockIdx.x * 128;
    const int m0 = blockIdx.y * 64;
    const size_t boffX = (size_t)blockIdx.z * CDIM * HWD;
    const size_t boffY = (size_t)blockIdx.z * (size_t)Mdim * HWD;

    float acc[4][8];
#pragma unroll
    for (int i = 0; i < 4; i++)
#pragma unroll
        for (int j = 0; j < 8; j++) acc[i][j] = 0.f;

    for (int k0 = 0; k0 < CDIM; k0 += 16) {
        // A tile: 64x16 of W (row-major [M,K]) stored transposed As[k][m]
        {
            int am = tid >> 2;
            int ak = (tid & 3) << 2;
            float4 a4 = *(const float4*)(Wt + (size_t)(m0 + am) * CDIM + k0 + ak);
            As[ak + 0][am] = a4.x; As[ak + 1][am] = a4.y;
            As[ak + 2][am] = a4.z; As[ak + 3][am] = a4.w;
        }
        // B tile: 16x128 of X (row-major [K,N])
        {
            int br = tid >> 4;
            int bc = (tid & 15) << 3;
            const float* src = X + boffX + (size_t)(k0 + br) * HWD + n0 + bc;
            float4 b0 = *(const float4*)(src);
            float4 b1 = *(const float4*)(src + 4);
            *(float4*)&Bs[br][bc]     = b0;
            *(float4*)&Bs[br][bc + 4] = b1;
        }
        __syncthreads();
#pragma unroll
        for (int k = 0; k < 16; k++) {
            float4 a = *(const float4*)&As[k][ty << 2];
            float4 p = *(const float4*)&Bs[k][tx << 3];
            float4 q = *(const float4*)&Bs[k][(tx << 3) + 4];
            float av4[4] = {a.x, a.y, a.z, a.w};
            float bv[8]  = {p.x, p.y, p.z, p.w, q.x, q.y, q.z, q.w};
#pragma unroll
            for (int i = 0; i < 4; i++)
#pragma unroll
                for (int j = 0; j < 8; j++)
                    acc[i][j] = fmaf(av4[i], bv[j], acc[i][j]);
        }
        __syncthreads();
    }
#pragma unroll
    for (int i = 0; i < 4; i++) {
        float* dst = Y + boffY + (size_t)(m0 + (ty << 2) + i) * HWD + n0 + (tx << 3);
        *(float4*)(dst)     = make_float4(acc[i][0], acc[i][1], acc[i][2], acc[i][3]);
        *(float4*)(dst + 4) = make_float4(acc[i][4], acc[i][5], acc[i][6], acc[i][7]);
    }
}

// ============================================================
// Depthwise 3x3, pad 1. One thread per output pixel; each block lives
// entirely inside one (b,c) image (256 pixels = 2 rows), weights in smem.
// ============================================================
__global__ __launch_bounds__(256) void dw_conv_kernel(
    const float* __restrict__ in, const float* __restrict__ wts,
    float* __restrict__ out)
{
    __shared__ float w[9];
    const size_t base = (size_t)blockIdx.x * 256;
    const int c = (int)((base >> 14) % C3);
    if (threadIdx.x < 9) w[threadIdx.x] = wts[c * 9 + threadIdx.x];
    __syncthreads();

    const size_t idx = base + threadIdx.x;
    const int px = (int)(idx & 127);
    const int py = (int)((idx >> 7) & 127);
    const float* ip = in + (idx & ~(size_t)16383);

    float s = 0.f;
#pragma unroll
    for (int dy = -1; dy <= 1; dy++) {
        int yy = py + dy;
        if (yy < 0 || yy > 127) continue;
#pragma unroll
        for (int dx = -1; dx <= 1; dx++) {
            int xx = px + dx;
            if (xx < 0 || xx > 127) continue;
            s = fmaf(ip[yy * 128 + xx], w[(dy + 1) * 3 + dx + 1], s);
        }
    }
    out[idx] = s;
}

// ============================================================
// Gram partials: per (b,h), per n-chunk of 1024: S[c,d] += q[c,n]k[d,n],
// plus partial sum-of-squares for the L2 norms. No atomics (deterministic).
// ============================================================
__global__ __launch_bounds__(256) void gram_kernel()
{
    const int chunk = blockIdx.x;
    const int bh = blockIdx.y;
    const int b = bh >> 2, h = bh & 3;
    const float* qb = g_qkv2 + ((size_t)b * C3 + h * CH) * HWD;
    const float* kb = g_qkv2 + ((size_t)b * C3 + CDIM + h * CH) * HWD;
    __shared__ float qs[CH][68];
    __shared__ float ks[CH][68];
    const int tid = threadIdx.x;
    const int tx = tid & 15, ty = tid >> 4;

    float acc[3][3] = {};
    float nacc = 0.f;
    const int n0 = chunk * CHUNK;

    for (int t0 = 0; t0 < CHUNK; t0 += 64) {
#pragma unroll
        for (int i = 0; i < 3; i++) {
            int vid = tid + i * 256;
            int row = vid >> 4;
            int col = (vid & 15) << 2;
            *(float4*)&qs[row][col] = *(const float4*)(qb + (size_t)row * HWD + n0 + t0 + col);
            *(float4*)&ks[row][col] = *(const float4*)(kb + (size_t)row * HWD + n0 + t0 + col);
        }
        __syncthreads();
#pragma unroll 4
        for (int n = 0; n < 64; n++) {
            float q0 = qs[ty * 3 + 0][n], q1 = qs[ty * 3 + 1][n], q2 = qs[ty * 3 + 2][n];
            float k0 = ks[tx * 3 + 0][n], k1 = ks[tx * 3 + 1][n], k2 = ks[tx * 3 + 2][n];
            acc[0][0] = fmaf(q0, k0, acc[0][0]); acc[0][1] = fmaf(q0, k1, acc[0][1]); acc[0][2] = fmaf(q0, k2, acc[0][2]);
            acc[1][0] = fmaf(q1, k0, acc[1][0]); acc[1][1] = fmaf(q1, k1, acc[1][1]); acc[1][2] = fmaf(q1, k2, acc[1][2]);
            acc[2][0] = fmaf(q2, k0, acc[2][0]); acc[2][1] = fmaf(q2, k1, acc[2][1]); acc[2][2] = fmaf(q2, k2, acc[2][2]);
        }
        if (tid < CH) {
#pragma unroll 8
            for (int n = 0; n < 64; n++) { float v = qs[tid][n]; nacc = fmaf(v, v, nacc); }
        } else if (tid < 2 * CH) {
#pragma unroll 8
            for (int n = 0; n < 64; n++) { float v = ks[tid - CH][n]; nacc = fmaf(v, v, nacc); }
        }
        __syncthreads();
    }

    float* gp = g_part_gram + ((size_t)bh * NCHUNK + chunk) * CH * CH;
#pragma unroll
    for (int i = 0; i < 3; i++)
#pragma unroll
        for (int j = 0; j < 3; j++)
            gp[(ty * 3 + i) * CH + tx * 3 + j] = acc[i][j];
    if (tid < CH)
        g_part_nq[((size_t)bh * NCHUNK + chunk) * CH + tid] = nacc;
    else if (tid < 2 * CH)
        g_part_nk[((size_t)bh * NCHUNK + chunk) * CH + (tid - CH)] = nacc;
}

// ============================================================
// Reduce partials -> normalize -> temperature -> row softmax (48x48 per bh)
// ============================================================
__global__ __launch_bounds__(256) void attn_kernel(const float* __restrict__ temperature)
{
    const int bh = blockIdx.x;
    const int h = bh & 3;
    __shared__ float S[CH * CH];
    __shared__ float rq[CH];
    __shared__ float rk[CH];
    const int tid = threadIdx.x;

    for (int e = tid; e < CH * CH; e += 256) {
        float s = 0.f;
#pragma unroll
        for (int p = 0; p < NCHUNK; p++)
            s += g_part_gram[((size_t)bh * NCHUNK + p) * CH * CH + e];
        S[e] = s;
    }
    if (tid < CH) {
        float s = 0.f;
#pragma unroll
        for (int p = 0; p < NCHUNK; p++) s += g_part_nq[((size_t)bh * NCHUNK + p) * CH + tid];
        rq[tid] = fmaxf(sqrtf(s), 1e-12f);
    } else if (tid < 2 * CH) {
        float s = 0.f;
#pragma unroll
        for (int p = 0; p < NCHUNK; p++) s += g_part_nk[((size_t)bh * NCHUNK + p) * CH + (tid - CH)];
        rk[tid - CH] = fmaxf(sqrtf(s), 1e-12f);
    }
    __syncthreads();

    if (tid < CH) {
        const float t = temperature[h];
        const float fq = t / rq[tid];
        float row[CH];
        float mx = -1e30f;
#pragma unroll
        for (int d = 0; d < CH; d++) {
            float v = S[tid * CH + d] * fq / rk[d];
            row[d] = v;
            mx = fmaxf(mx, v);
        }
        float sum = 0.f;
#pragma unroll
        for (int d = 0; d < CH; d++) { float e = expf(row[d] - mx); row[d] = e; sum += e; }
        float inv = 1.f / sum;
#pragma unroll
        for (int d = 0; d < CH; d++)
            g_attn[(size_t)bh * CH * CH + tid * CH + d] = row[d] * inv;
    }
}

// ============================================================
// out[c,n] = sum_d attn[c,d] v[d,n]; one thread per pixel, v in regs,
// attn broadcast from smem (float4 reads).
// ============================================================
__global__ __launch_bounds__(256) void av_kernel()
{
    const int bh = blockIdx.y;
    const int b = bh >> 2, h = bh & 3;
    __shared__ float at[CH * CH];
    const int tid = threadIdx.x;
    for (int e = tid; e < CH * CH; e += 256)
        at[e] = g_attn[(size_t)bh * CH * CH + e];
    __syncthreads();

    const int p = blockIdx.x * 256 + tid;
    const float* vb = g_qkv2 + ((size_t)b * C3 + 2 * CDIM + h * CH) * HWD + p;
    float v[CH];
#pragma unroll
    for (int d = 0; d < CH; d++) v[d] = vb[(size_t)d * HWD];

    float* ob = g_av + ((size_t)b * CDIM + h * CH) * HWD + p;
    for (int c = 0; c < CH; c++) {
        float s = 0.f;
#pragma unroll
        for (int d = 0; d < CH; d += 4) {
            float4 a4 = *(const float4*)&at[c * CH + d];
            s = fmaf(a4.x, v[d + 0], s);
            s = fmaf(a4.y, v[d + 1], s);
            s = fmaf(a4.z, v[d + 2], s);
            s = fmaf(a4.w, v[d + 3], s);
        }
        ob[(size_t)c * HWD] = s;
    }
}

// ============================================================
extern "C" void kernel_launch(void* const* d_in, const int* in_sizes, int n_in,
                              void* d_out, int out_size)
{
    const float* x      = (const float*)d_in[0];
    const float* qkv_w  = (const float*)d_in[1];
    const float* dw_w   = (const float*)d_in[2];
    const float* proj_w = (const float*)d_in[3];
    const float* temp   = (const float*)d_in[4];
    float* out = (float*)d_out;

    float *qkv, *qkv2, *av;
    cudaGetSymbolAddress((void**)&qkv,  g_qkv);
    cudaGetSymbolAddress((void**)&qkv2, g_qkv2);
    cudaGetSymbolAddress((void**)&av,   g_av);

    dim3 blk(256);
    // 1) qkv = 1x1 conv (GEMM M=576)
    pw_conv_kernel<<<dim3(HWD / 128, C3 / 64, BATCH), blk>>>(qkv_w, x, qkv, C3);
    // 2) depthwise 3x3
    dw_conv_kernel<<<(unsigned)((size_t)BATCH * C3 * HWD / 256), blk>>>(qkv, dw_w, qkv2);
    // 3) gram partials (QK^T + norms)
    gram_kernel<<<dim3(NCHUNK, BATCH * HEADS), blk>>>();
    // 4) reduce + normalize + softmax
    attn_kernel<<<BATCH * HEADS, blk>>>(temp);
    // 5) attn @ V
    av_kernel<<<dim3(HWD / 256, BATCH * HEADS), blk>>>();
    // 6) proj 1x1 conv (GEMM M=192) -> d_out
    pw_conv_kernel<<<dim3(HWD / 128, CDIM / 64, BATCH), blk>>>(proj_w, av, out, CDIM);
}

// round 2
// speedup vs baseline: 1.4226x; 1.4226x over previous
#include <cuda_runtime.h>
#include <math.h>

#define BATCH 8
#define CDIM 192
#define C3 576
#define HWD 16384
#define HEADS 4
#define CH 48
#define NCHUNK 16
#define CHUNK 1024

typedef unsigned long long ull;

// ---- packed f32x2 helpers (Blackwell dual-rate fp32) ----
__device__ __forceinline__ ull fma2(ull a, ull b, ull c) {
    ull d;
    asm("fma.rn.f32x2 %0, %1, %2, %3;" : "=l"(d) : "l"(a), "l"(b), "l"(c));
    return d;
}
__device__ __forceinline__ ull dup2(float x) {
    ull d; unsigned u = __float_as_uint(x);
    asm("mov.b64 %0, {%1, %1};" : "=l"(d) : "r"(u));
    return d;
}
__device__ __forceinline__ ull pack2(float x, float y) {
    ull d;
    asm("mov.b64 %0, {%1, %2};" : "=l"(d) : "r"(__float_as_uint(x)), "r"(__float_as_uint(y)));
    return d;
}
__device__ __forceinline__ float lo2(ull a) { return __uint_as_float((unsigned)a); }
__device__ __forceinline__ float hi2(ull a) { return __uint_as_float((unsigned)(a >> 32)); }

// ---- scratch (device globals; no allocations allowed) ----
__device__ float g_qkv [(size_t)BATCH * C3 * HWD];   // after 1x1 qkv conv
__device__ float g_qkv2[(size_t)BATCH * C3 * HWD];   // after depthwise 3x3
__device__ float g_part_gram[(size_t)BATCH * HEADS * NCHUNK * CH * CH];
__device__ float g_part_nq  [(size_t)BATCH * HEADS * NCHUNK * CH];
__device__ float g_part_nk  [(size_t)BATCH * HEADS * NCHUNK * CH];
__device__ float g_attn     [(size_t)BATCH * HEADS * CH * CH];
__device__ float g_av [(size_t)BATCH * CDIM * HWD];  // attention output

// ============================================================
// Pointwise 1x1 conv = batched GEMM: Y[b,m,n] = sum_k W[m,k] X[b,k,n]
// K = 192. Block tile 128(M) x 128(N), BK=16, 256 thr, 8x8/thr via f32x2.
// M tiles padded with predication (576 -> 5 tiles, 192 -> 2 tiles).
// ============================================================
__global__ __launch_bounds__(256) void pw_conv_kernel(
    const float* __restrict__ Wt, const float* __restrict__ X,
    float* __restrict__ Y, int Mdim)
{
    __shared__ __align__(16) float As[16][128];
    __shared__ __align__(16) float Bs[16][128];
    const int tid = threadIdx.x;
    const int tx = tid & 15, ty = tid >> 4;
    const int n0 = blockIdx.x * 128;
    const int m0 = blockIdx.y * 128;
    const size_t boffX = (size_t)blockIdx.z * CDIM * HWD;
    const size_t boffY = (size_t)blockIdx.z * (size_t)Mdim * HWD;

    ull acc[8][4];
#pragma unroll
    for (int i = 0; i < 8; i++)
#pragma unroll
        for (int j = 0; j < 4; j++) acc[i][j] = 0ull;

    const int am = tid >> 1;            // 0..127 (M row within tile)
    const int ak = (tid & 1) * 8;       // 0 or 8 (k sub-offset)
    const int br = tid >> 4;            // 0..15  (k row)
    const int bc = (tid & 15) * 8;      // n sub-offset
    const bool a_ok = (m0 + am) < Mdim;

    for (int k0 = 0; k0 < CDIM; k0 += 16) {
        // A tile (predicated): W row-major [M,192] -> As[k][m] transposed
        float4 w0 = make_float4(0.f, 0.f, 0.f, 0.f);
        float4 w1 = make_float4(0.f, 0.f, 0.f, 0.f);
        if (a_ok) {
            const float* wp = Wt + (size_t)(m0 + am) * CDIM + k0 + ak;
            w0 = *(const float4*)(wp);
            w1 = *(const float4*)(wp + 4);
        }
        As[ak + 0][am] = w0.x; As[ak + 1][am] = w0.y;
        As[ak + 2][am] = w0.z; As[ak + 3][am] = w0.w;
        As[ak + 4][am] = w1.x; As[ak + 5][am] = w1.y;
        As[ak + 6][am] = w1.z; As[ak + 7][am] = w1.w;
        // B tile: X[k, n] coalesced
        {
            const float* src = X + boffX + (size_t)(k0 + br) * HWD + n0 + bc;
            *(float4*)&Bs[br][bc]     = *(const float4*)(src);
            *(float4*)&Bs[br][bc + 4] = *(const float4*)(src + 4);
        }
        __syncthreads();
#pragma unroll
        for (int k = 0; k < 16; k++) {
            float4 a0 = *(const float4*)&As[k][ty * 4];
            float4 a1 = *(const float4*)&As[k][64 + ty * 4];
            ulonglong2 b0 = *(const ulonglong2*)&Bs[k][tx * 4];
            ulonglong2 b1 = *(const ulonglong2*)&Bs[k][64 + tx * 4];
            ull bp[4] = { b0.x, b0.y, b1.x, b1.y };
            ull ad[8] = { dup2(a0.x), dup2(a0.y), dup2(a0.z), dup2(a0.w),
                          dup2(a1.x), dup2(a1.y), dup2(a1.z), dup2(a1.w) };
#pragma unroll
            for (int i = 0; i < 8; i++)
#pragma unroll
                for (int j = 0; j < 4; j++)
                    acc[i][j] = fma2(ad[i], bp[j], acc[i][j]);
        }
        __syncthreads();
    }

#pragma unroll
    for (int i = 0; i < 8; i++) {
        int mr = (i < 4) ? (ty * 4 + i) : (64 + ty * 4 + i - 4);
        if (m0 + mr < Mdim) {
            float* dst = Y + boffY + (size_t)(m0 + mr) * HWD + n0;
            *(float4*)(dst + tx * 4) =
                make_float4(lo2(acc[i][0]), hi2(acc[i][0]), lo2(acc[i][1]), hi2(acc[i][1]));
            *(float4*)(dst + 64 + tx * 4) =
                make_float4(lo2(acc[i][2]), hi2(acc[i][2]), lo2(acc[i][3]), hi2(acc[i][3]));
        }
    }
}

// ============================================================
// Depthwise 3x3, pad 1. One thread per output pixel; each block lives
// entirely inside one (b,c) image (256 pixels = 2 rows), weights in smem.
// ============================================================
__global__ __launch_bounds__(256) void dw_conv_kernel(
    const float* __restrict__ in, const float* __restrict__ wts,
    float* __restrict__ out)
{
    __shared__ float w[9];
    const size_t base = (size_t)blockIdx.x * 256;
    const int c = (int)((base >> 14) % C3);
    if (threadIdx.x < 9) w[threadIdx.x] = wts[c * 9 + threadIdx.x];
    __syncthreads();

    const size_t idx = base + threadIdx.x;
    const int px = (int)(idx & 127);
    const int py = (int)((idx >> 7) & 127);
    const float* ip = in + (idx & ~(size_t)16383);

    float s = 0.f;
#pragma unroll
    for (int dy = -1; dy <= 1; dy++) {
        int yy = py + dy;
        if (yy < 0 || yy > 127) continue;
#pragma unroll
        for (int dx = -1; dx <= 1; dx++) {
            int xx = px + dx;
            if (xx < 0 || xx > 127) continue;
            s = fmaf(ip[yy * 128 + xx], w[(dy + 1) * 3 + dx + 1], s);
        }
    }
    out[idx] = s;
}

// ============================================================
// Gram partials: per (b,h), per n-chunk of 1024: S[c,d] += q[c,n]k[d,n],
// plus partial sum-of-squares for the L2 norms. f32x2 along n.
// ============================================================
__global__ __launch_bounds__(256) void gram_kernel()
{
    const int chunk = blockIdx.x;
    const int bh = blockIdx.y;
    const int b = bh >> 2, h = bh & 3;
    const float* qb = g_qkv2 + ((size_t)b * C3 + h * CH) * HWD;
    const float* kb = g_qkv2 + ((size_t)b * C3 + CDIM + h * CH) * HWD;
    __shared__ __align__(16) float qs[CH][68];
    __shared__ __align__(16) float ks[CH][68];
    const int tid = threadIdx.x;
    const int tx = tid & 15, ty = tid >> 4;

    ull acc2[3][3];
#pragma unroll
    for (int i = 0; i < 3; i++)
#pragma unroll
        for (int j = 0; j < 3; j++) acc2[i][j] = 0ull;
    ull nacc2 = 0ull;
    const int n0 = chunk * CHUNK;

    for (int t0 = 0; t0 < CHUNK; t0 += 64) {
#pragma unroll
        for (int i = 0; i < 3; i++) {
            int vid = tid + i * 256;
            int row = vid >> 4;
            int col = (vid & 15) << 2;
            *(float4*)&qs[row][col] = *(const float4*)(qb + (size_t)row * HWD + n0 + t0 + col);
            *(float4*)&ks[row][col] = *(const float4*)(kb + (size_t)row * HWD + n0 + t0 + col);
        }
        __syncthreads();
#pragma unroll 4
        for (int n2 = 0; n2 < 32; n2++) {
            ull q0 = *(const ull*)&qs[ty * 3 + 0][2 * n2];
            ull q1 = *(const ull*)&qs[ty * 3 + 1][2 * n2];
            ull q2 = *(const ull*)&qs[ty * 3 + 2][2 * n2];
            ull k0 = *(const ull*)&ks[tx * 3 + 0][2 * n2];
            ull k1 = *(const ull*)&ks[tx * 3 + 1][2 * n2];
            ull k2 = *(const ull*)&ks[tx * 3 + 2][2 * n2];
            acc2[0][0] = fma2(q0, k0, acc2[0][0]); acc2[0][1] = fma2(q0, k1, acc2[0][1]); acc2[0][2] = fma2(q0, k2, acc2[0][2]);
            acc2[1][0] = fma2(q1, k0, acc2[1][0]); acc2[1][1] = fma2(q1, k1, acc2[1][1]); acc2[1][2] = fma2(q1, k2, acc2[1][2]);
            acc2[2][0] = fma2(q2, k0, acc2[2][0]); acc2[2][1] = fma2(q2, k1, acc2[2][1]); acc2[2][2] = fma2(q2, k2, acc2[2][2]);
        }
        if (tid < CH) {
#pragma unroll 8
            for (int n2 = 0; n2 < 32; n2++) {
                ull v = *(const ull*)&qs[tid][2 * n2];
                nacc2 = fma2(v, v, nacc2);
            }
        } else if (tid < 2 * CH) {
#pragma unroll 8
            for (int n2 = 0; n2 < 32; n2++) {
                ull v = *(const ull*)&ks[tid - CH][2 * n2];
                nacc2 = fma2(v, v, nacc2);
            }
        }
        __syncthreads();
    }

    float* gp = g_part_gram + ((size_t)bh * NCHUNK + chunk) * CH * CH;
#pragma unroll
    for (int i = 0; i < 3; i++)
#pragma unroll
        for (int j = 0; j < 3; j++)
            gp[(ty * 3 + i) * CH + tx * 3 + j] = lo2(acc2[i][j]) + hi2(acc2[i][j]);
    float nacc = lo2(nacc2) + hi2(nacc2);
    if (tid < CH)
        g_part_nq[((size_t)bh * NCHUNK + chunk) * CH + tid] = nacc;
    else if (tid < 2 * CH)
        g_part_nk[((size_t)bh * NCHUNK + chunk) * CH + (tid - CH)] = nacc;
}

// ============================================================
// Reduce partials -> normalize -> temperature -> row softmax (48x48 per bh)
// ============================================================
__global__ __launch_bounds__(256) void attn_kernel(const float* __restrict__ temperature)
{
    const int bh = blockIdx.x;
    const int h = bh & 3;
    __shared__ float S[CH * CH];
    __shared__ float rq[CH];
    __shared__ float rk[CH];
    const int tid = threadIdx.x;

    for (int e = tid; e < CH * CH; e += 256) {
        float s = 0.f;
#pragma unroll
        for (int p = 0; p < NCHUNK; p++)
            s += g_part_gram[((size_t)bh * NCHUNK + p) * CH * CH + e];
        S[e] = s;
    }
    if (tid < CH) {
        float s = 0.f;
#pragma unroll
        for (int p = 0; p < NCHUNK; p++) s += g_part_nq[((size_t)bh * NCHUNK + p) * CH + tid];
        rq[tid] = fmaxf(sqrtf(s), 1e-12f);
    } else if (tid < 2 * CH) {
        float s = 0.f;
#pragma unroll
        for (int p = 0; p < NCHUNK; p++) s += g_part_nk[((size_t)bh * NCHUNK + p) * CH + (tid - CH)];
        rk[tid - CH] = fmaxf(sqrtf(s), 1e-12f);
    }
    __syncthreads();

    if (tid < CH) {
        const float t = temperature[h];
        const float fq = t / rq[tid];
        float row[CH];
        float mx = -1e30f;
#pragma unroll
        for (int d = 0; d < CH; d++) {
            float v = S[tid * CH + d] * fq / rk[d];
            row[d] = v;
            mx = fmaxf(mx, v);
        }
        float sum = 0.f;
#pragma unroll
        for (int d = 0; d < CH; d++) { float e = expf(row[d] - mx); row[d] = e; sum += e; }
        float inv = 1.f / sum;
#pragma unroll
        for (int d = 0; d < CH; d++)
            g_attn[(size_t)bh * CH * CH + tid * CH + d] = row[d] * inv;
    }
}

// ============================================================
// out[c,n] = sum_d attn[c,d] v[d,n]; one thread per pixel, v packed in
// f32x2 register pairs, attn broadcast from smem.
// ============================================================
__global__ __launch_bounds__(256) void av_kernel()
{
    const int bh = blockIdx.y;
    const int b = bh >> 2, h = bh & 3;
    __shared__ __align__(16) float at[CH * CH];
    const int tid = threadIdx.x;
    for (int e = tid; e < CH * CH; e += 256)
        at[e] = g_attn[(size_t)bh * CH * CH + e];
    __syncthreads();

    const int p = blockIdx.x * 256 + tid;
    const float* vb = g_qkv2 + ((size_t)b * C3 + 2 * CDIM + h * CH) * HWD + p;
    ull vp[CH / 2];
#pragma unroll
    for (int d2 = 0; d2 < CH / 2; d2++)
        vp[d2] = pack2(vb[(size_t)(2 * d2) * HWD], vb[(size_t)(2 * d2 + 1) * HWD]);

    float* ob = g_av + ((size_t)b * CDIM + h * CH) * HWD + p;
    for (int c = 0; c < CH; c++) {
        ull s2 = 0ull;
#pragma unroll
        for (int d2 = 0; d2 < CH / 2; d2++) {
            ull a = *(const ull*)&at[c * CH + 2 * d2];
            s2 = fma2(a, vp[d2], s2);
        }
        ob[(size_t)c * HWD] = lo2(s2) + hi2(s2);
    }
}

// ============================================================
extern "C" void kernel_launch(void* const* d_in, const int* in_sizes, int n_in,
                              void* d_out, int out_size)
{
    const float* x      = (const float*)d_in[0];
    const float* qkv_w  = (const float*)d_in[1];
    const float* dw_w   = (const float*)d_in[2];
    const float* proj_w = (const float*)d_in[3];
    const float* temp   = (const float*)d_in[4];
    float* out = (float*)d_out;

    float *qkv, *qkv2, *av;
    cudaGetSymbolAddress((void**)&qkv,  g_qkv);
    cudaGetSymbolAddress((void**)&qkv2, g_qkv2);
    cudaGetSymbolAddress((void**)&av,   g_av);

    dim3 blk(256);
    // 1) qkv = 1x1 conv (GEMM M=576, 5 predicated M-tiles of 128)
    pw_conv_kernel<<<dim3(HWD / 128, (C3 + 127) / 128, BATCH), blk>>>(qkv_w, x, qkv, C3);
    // 2) depthwise 3x3
    dw_conv_kernel<<<(unsigned)((size_t)BATCH * C3 * HWD / 256), blk>>>(qkv, dw_w, qkv2);
    // 3) gram partials (QK^T + norms)
    gram_kernel<<<dim3(NCHUNK, BATCH * HEADS), blk>>>();
    // 4) reduce + normalize + softmax
    attn_kernel<<<BATCH * HEADS, blk>>>(temp);
    // 5) attn @ V
    av_kernel<<<dim3(HWD / 256, BATCH * HEADS), blk>>>();
    // 6) proj 1x1 conv (GEMM M=192, 2 predicated M-tiles) -> d_out
    pw_conv_kernel<<<dim3(HWD / 128, (CDIM + 127) / 128, BATCH), blk>>>(proj_w, av, out, CDIM);
}

// round 4
// speedup vs baseline: 2.2321x; 1.5691x over previous
#include <cuda_runtime.h>
#include <math.h>
#include <stdint.h>

#define BATCH 8
#define CDIM 192
#define C3 576
#define HWD 16384
#define HEADS 4
#define CH 48
#define NCHUNK 16
#define CHUNK 1024

typedef unsigned long long ull;

// ---- packed f32x2 helpers ----
__device__ __forceinline__ ull fma2(ull a, ull b, ull c) {
    ull d;
    asm("fma.rn.f32x2 %0, %1, %2, %3;" : "=l"(d) : "l"(a), "l"(b), "l"(c));
    return d;
}
__device__ __forceinline__ ull pack2(float x, float y) {
    ull d;
    asm("mov.b64 %0, {%1, %2};" : "=l"(d) : "r"(__float_as_uint(x)), "r"(__float_as_uint(y)));
    return d;
}
__device__ __forceinline__ float lo2(ull a) { return __uint_as_float((unsigned)a); }
__device__ __forceinline__ float hi2(ull a) { return __uint_as_float((unsigned)(a >> 32)); }

// ---- tf32 helpers (sm_80+ baseline features; compile on compute_103) ----
__device__ __forceinline__ uint32_t f2tf32(float x) {
    uint32_t r;
    asm("cvt.rna.tf32.f32 %0, %1;" : "=r"(r) : "f"(x));
    return r;
}
__device__ __forceinline__ void mma_tf32(float* c, uint4 a, uint2 b) {
    asm volatile(
        "mma.sync.aligned.m16n8k8.row.col.f32.tf32.tf32.f32 "
        "{%0,%1,%2,%3}, {%4,%5,%6,%7}, {%8,%9}, {%0,%1,%2,%3};"
        : "+f"(c[0]), "+f"(c[1]), "+f"(c[2]), "+f"(c[3])
        : "r"(a.x), "r"(a.y), "r"(a.z), "r"(a.w), "r"(b.x), "r"(b.y));
}

// ---- scratch (device globals; no allocations allowed) ----
__device__ float g_qkv [(size_t)BATCH * C3 * HWD];
__device__ float g_qkv2[(size_t)BATCH * C3 * HWD];
__device__ float g_part_gram[(size_t)BATCH * HEADS * NCHUNK * CH * CH];
__device__ float g_part_nq  [(size_t)BATCH * HEADS * NCHUNK * CH];
__device__ float g_part_nk  [(size_t)BATCH * HEADS * NCHUNK * CH];
__device__ float g_attn     [(size_t)BATCH * HEADS * CH * CH];
__device__ float g_av [(size_t)BATCH * CDIM * HWD];
__device__ uint32_t g_apq[5 * 24 * 8 * 32 * 4];  // qkv W, fragment-permuted tf32
__device__ uint32_t g_app[2 * 24 * 8 * 32 * 4];  // proj W

// ============================================================
// Permute W[M,192] into mma fragment order + tf32 convert.
// Layout: [mt][k8(24)][m16(8)][lane(32)][reg(4)], zero-filled past Mdim.
// frag: reg r -> A[g + (r&1)*8][t + (r>>1)*4], g=lane>>2, t=lane&3.
// ============================================================
__global__ __launch_bounds__(256) void prep_a(
    const float* __restrict__ W, uint32_t* __restrict__ Ap, int Mdim)
{
    const int idx = blockIdx.x * 256 + threadIdx.x;
    const int lane = idx & 31;
    int rest = idx >> 5;
    const int m16 = rest & 7; rest >>= 3;
    const int k8 = rest % 24;
    const int mt = rest / 24;
    const int g = lane >> 2, t = lane & 3;
    const int row = mt * 128 + m16 * 16 + g;
    const int k = k8 * 8 + t;
    float v0 = 0.f, v1 = 0.f, v2 = 0.f, v3 = 0.f;
    if (row < Mdim)     { v0 = W[(size_t)row * CDIM + k];       v2 = W[(size_t)row * CDIM + k + 4]; }
    if (row + 8 < Mdim) { v1 = W[(size_t)(row + 8) * CDIM + k]; v3 = W[(size_t)(row + 8) * CDIM + k + 4]; }
    uint4 o;
    o.x = f2tf32(v0); o.y = f2tf32(v1); o.z = f2tf32(v2); o.w = f2tf32(v3);
    *(uint4*)(Ap + (size_t)idx * 4) = o;
}

// ============================================================
// Pointwise 1x1 conv via mma.sync tf32: Y[b,m,n] = sum_k W[m,k] X[b,k,n]
// 128(M) x 128(N) block, 8 warps (4Mx2N), BK=16, double-buffered smem.
// ============================================================
__global__ __launch_bounds__(256) void pw_mma(
    const uint32_t* __restrict__ Ap, const float* __restrict__ X,
    float* __restrict__ Y, int Mdim)
{
    __shared__ __align__(16) uint32_t As[2][2048];      // [k8(2)][m16(8)][lane][4]
    __shared__ __align__(16) uint32_t Bs[2][16 * 132];  // [k(16)][n(128)+pad]
    const int tid = threadIdx.x;
    const int lane = tid & 31, wid = tid >> 5;
    const int mt = blockIdx.x;
    const int n0 = blockIdx.y * 128;
    const size_t boffX = (size_t)blockIdx.z * CDIM * HWD;
    const size_t boffY = (size_t)blockIdx.z * (size_t)Mdim * HWD;

    const uint32_t* apg = Ap + (size_t)mt * 24 * 1024;
    const int nq = tid & 31;           // B fill: n quad
    const int bk0 = tid >> 5;          // B fill: k row (0..7), second is +8

    uint4 a_r0, a_r1;
    float4 b_r0, b_r1;

    auto ldg_iter = [&](int it) {
        const uint32_t* ap = apg + it * 2048;
        a_r0 = *(const uint4*)(ap + (size_t)tid * 4);
        a_r1 = *(const uint4*)(ap + (size_t)(tid + 256) * 4);
        const float* xb = X + boffX + (size_t)it * 16 * HWD + n0 + nq * 4;
        b_r0 = *(const float4*)(xb + (size_t)bk0 * HWD);
        b_r1 = *(const float4*)(xb + (size_t)(bk0 + 8) * HWD);
    };
    auto sts_iter = [&](int buf) {
        *(uint4*)&As[buf][tid * 4] = a_r0;
        *(uint4*)&As[buf][(tid + 256) * 4] = a_r1;
        uint32_t* r0 = &Bs[buf][bk0 * 132 + nq * 4];
        r0[0] = f2tf32(b_r0.x); r0[1] = f2tf32(b_r0.y);
        r0[2] = f2tf32(b_r0.z); r0[3] = f2tf32(b_r0.w);
        uint32_t* r1 = &Bs[buf][(bk0 + 8) * 132 + nq * 4];
        r1[0] = f2tf32(b_r1.x); r1[1] = f2tf32(b_r1.y);
        r1[2] = f2tf32(b_r1.z); r1[3] = f2tf32(b_r1.w);
    };

    float acc[2][8][4];
#pragma unroll
    for (int f = 0; f < 2; f++)
#pragma unroll
        for (int j = 0; j < 8; j++)
#pragma unroll
            for (int e = 0; e < 4; e++) acc[f][j][e] = 0.f;

    const int m16a = (wid & 3) * 2;
    const int t = lane & 3;
    const int g = lane >> 2;
    const int nwb = (wid >> 2) * 64;

    auto compute = [&](int buf) {
#pragma unroll
        for (int k8s = 0; k8s < 2; k8s++) {
            uint4 a0 = *(const uint4*)&As[buf][((k8s * 8 + m16a) * 32 + lane) * 4];
            uint4 a1 = *(const uint4*)&As[buf][((k8s * 8 + m16a + 1) * 32 + lane) * 4];
            const int br0 = (k8s * 8 + t) * 132 + nwb + g;
            const int br1 = br0 + 4 * 132;
#pragma unroll
            for (int j = 0; j < 8; j++) {
                uint2 b = make_uint2(Bs[buf][br0 + j * 8], Bs[buf][br1 + j * 8]);
                mma_tf32(acc[0][j], a0, b);
                mma_tf32(acc[1][j], a1, b);
            }
        }
    };

    ldg_iter(0);
    sts_iter(0);
    __syncthreads();
#pragma unroll 1
    for (int it = 0; it < 12; it++) {
        if (it + 1 < 12) ldg_iter(it + 1);
        compute(it & 1);
        if (it + 1 < 12) sts_iter((it + 1) & 1);
        __syncthreads();
    }

    // epilogue: c0,c1 -> [m][2t..2t+1], c2,c3 -> [m+8][...]
    const int mw = mt * 128 + (wid & 3) * 32;
#pragma unroll
    for (int f = 0; f < 2; f++) {
        const int m = mw + f * 16 + g;
#pragma unroll
        for (int j = 0; j < 8; j++) {
            float* p = Y + boffY + (size_t)m * HWD + n0 + nwb + j * 8 + 2 * t;
            if (m < Mdim)
                *(float2*)p = make_float2(acc[f][j][0], acc[f][j][1]);
            if (m + 8 < Mdim)
                *(float2*)(p + (size_t)8 * HWD) = make_float2(acc[f][j][2], acc[f][j][3]);
        }
    }
}

// ============================================================
// Depthwise 3x3, pad 1.
// ============================================================
__global__ __launch_bounds__(256) void dw_conv_kernel(
    const float* __restrict__ in, const float* __restrict__ wts,
    float* __restrict__ out)
{
    __shared__ float w[9];
    const size_t base = (size_t)blockIdx.x * 256;
    const int c = (int)((base >> 14) % C3);
    if (threadIdx.x < 9) w[threadIdx.x] = wts[c * 9 + threadIdx.x];
    __syncthreads();

    const size_t idx = base + threadIdx.x;
    const int px = (int)(idx & 127);
    const int py = (int)((idx >> 7) & 127);
    const float* ip = in + (idx & ~(size_t)16383);

    float s = 0.f;
#pragma unroll
    for (int dy = -1; dy <= 1; dy++) {
        int yy = py + dy;
        if (yy < 0 || yy > 127) continue;
#pragma unroll
        for (int dx = -1; dx <= 1; dx++) {
            int xx = px + dx;
            if (xx < 0 || xx > 127) continue;
            s = fmaf(ip[yy * 128 + xx], w[(dy + 1) * 3 + dx + 1], s);
        }
    }
    out[idx] = s;
}

// ============================================================
// Gram partials (f32x2)
// ============================================================
__global__ __launch_bounds__(256) void gram_kernel()
{
    const int chunk = blockIdx.x;
    const int bh = blockIdx.y;
    const int b = bh >> 2, h = bh & 3;
    const float* qb = g_qkv2 + ((size_t)b * C3 + h * CH) * HWD;
    const float* kb = g_qkv2 + ((size_t)b * C3 + CDIM + h * CH) * HWD;
    __shared__ __align__(16) float qs[CH][68];
    __shared__ __align__(16) float ks[CH][68];
    const int tid = threadIdx.x;
    const int tx = tid & 15, ty = tid >> 4;

    ull acc2[3][3];
#pragma unroll
    for (int i = 0; i < 3; i++)
#pragma unroll
        for (int j = 0; j < 3; j++) acc2[i][j] = 0ull;
    ull nacc2 = 0ull;
    const int n0 = chunk * CHUNK;

    for (int t0 = 0; t0 < CHUNK; t0 += 64) {
#pragma unroll
        for (int i = 0; i < 3; i++) {
            int vid = tid + i * 256;
            int row = vid >> 4;
            int col = (vid & 15) << 2;
            *(float4*)&qs[row][col] = *(const float4*)(qb + (size_t)row * HWD + n0 + t0 + col);
            *(float4*)&ks[row][col] = *(const float4*)(kb + (size_t)row * HWD + n0 + t0 + col);
        }
        __syncthreads();
#pragma unroll 4
        for (int n2 = 0; n2 < 32; n2++) {
            ull q0 = *(const ull*)&qs[ty * 3 + 0][2 * n2];
            ull q1 = *(const ull*)&qs[ty * 3 + 1][2 * n2];
            ull q2 = *(const ull*)&qs[ty * 3 + 2][2 * n2];
            ull k0 = *(const ull*)&ks[tx * 3 + 0][2 * n2];
            ull k1 = *(const ull*)&ks[tx * 3 + 1][2 * n2];
            ull k2 = *(const ull*)&ks[tx * 3 + 2][2 * n2];
            acc2[0][0] = fma2(q0, k0, acc2[0][0]); acc2[0][1] = fma2(q0, k1, acc2[0][1]); acc2[0][2] = fma2(q0, k2, acc2[0][2]);
            acc2[1][0] = fma2(q1, k0, acc2[1][0]); acc2[1][1] = fma2(q1, k1, acc2[1][1]); acc2[1][2] = fma2(q1, k2, acc2[1][2]);
            acc2[2][0] = fma2(q2, k0, acc2[2][0]); acc2[2][1] = fma2(q2, k1, acc2[2][1]); acc2[2][2] = fma2(q2, k2, acc2[2][2]);
        }
        if (tid < CH) {
#pragma unroll 8
            for (int n2 = 0; n2 < 32; n2++) {
                ull v = *(const ull*)&qs[tid][2 * n2];
                nacc2 = fma2(v, v, nacc2);
            }
        } else if (tid < 2 * CH) {
#pragma unroll 8
            for (int n2 = 0; n2 < 32; n2++) {
                ull v = *(const ull*)&ks[tid - CH][2 * n2];
                nacc2 = fma2(v, v, nacc2);
            }
        }
        __syncthreads();
    }

    float* gp = g_part_gram + ((size_t)bh * NCHUNK + chunk) * CH * CH;
#pragma unroll
    for (int i = 0; i < 3; i++)
#pragma unroll
        for (int j = 0; j < 3; j++)
            gp[(ty * 3 + i) * CH + tx * 3 + j] = lo2(acc2[i][j]) + hi2(acc2[i][j]);
    float nacc = lo2(nacc2) + hi2(nacc2);
    if (tid < CH)
        g_part_nq[((size_t)bh * NCHUNK + chunk) * CH + tid] = nacc;
    else if (tid < 2 * CH)
        g_part_nk[((size_t)bh * NCHUNK + chunk) * CH + (tid - CH)] = nacc;
}

// ============================================================
// Reduce -> normalize -> temperature -> softmax
// ============================================================
__global__ __launch_bounds__(256) void attn_kernel(const float* __restrict__ temperature)
{
    const int bh = blockIdx.x;
    const int h = bh & 3;
    __shared__ float S[CH * CH];
    __shared__ float rq[CH];
    __shared__ float rk[CH];
    const int tid = threadIdx.x;

    for (int e = tid; e < CH * CH; e += 256) {
        float s = 0.f;
#pragma unroll
        for (int p = 0; p < NCHUNK; p++)
            s += g_part_gram[((size_t)bh * NCHUNK + p) * CH * CH + e];
        S[e] = s;
    }
    if (tid < CH) {
        float s = 0.f;
#pragma unroll
        for (int p = 0; p < NCHUNK; p++) s += g_part_nq[((size_t)bh * NCHUNK + p) * CH + tid];
        rq[tid] = fmaxf(sqrtf(s), 1e-12f);
    } else if (tid < 2 * CH) {
        float s = 0.f;
#pragma unroll
        for (int p = 0; p < NCHUNK; p++) s += g_part_nk[((size_t)bh * NCHUNK + p) * CH + (tid - CH)];
        rk[tid - CH] = fmaxf(sqrtf(s), 1e-12f);
    }
    __syncthreads();

    if (tid < CH) {
        const float t = temperature[h];
        const float fq = t / rq[tid];
        float row[CH];
        float mx = -1e30f;
#pragma unroll
        for (int d = 0; d < CH; d++) {
            float v = S[tid * CH + d] * fq / rk[d];
            row[d] = v;
            mx = fmaxf(mx, v);
        }
        float sum = 0.f;
#pragma unroll
        for (int d = 0; d < CH; d++) { float e = expf(row[d] - mx); row[d] = e; sum += e; }
        float inv = 1.f / sum;
#pragma unroll
        for (int d = 0; d < CH; d++)
            g_attn[(size_t)bh * CH * CH + tid * CH + d] = row[d] * inv;
    }
}

// ============================================================
// attn @ V (f32x2)
// ============================================================
__global__ __launch_bounds__(256) void av_kernel()
{
    const int bh = blockIdx.y;
    const int b = bh >> 2, h = bh & 3;
    __shared__ __align__(16) float at[CH * CH];
    const int tid = threadIdx.x;
    for (int e = tid; e < CH * CH; e += 256)
        at[e] = g_attn[(size_t)bh * CH * CH + e];
    __syncthreads();

    const int p = blockIdx.x * 256 + tid;
    const float* vb = g_qkv2 + ((size_t)b * C3 + 2 * CDIM + h * CH) * HWD + p;
    ull vp[CH / 2];
#pragma unroll
    for (int d2 = 0; d2 < CH / 2; d2++)
        vp[d2] = pack2(vb[(size_t)(2 * d2) * HWD], vb[(size_t)(2 * d2 + 1) * HWD]);

    float* ob = g_av + ((size_t)b * CDIM + h * CH) * HWD + p;
    for (int c = 0; c < CH; c++) {
        ull s2 = 0ull;
#pragma unroll
        for (int d2 = 0; d2 < CH / 2; d2++) {
            ull a = *(const ull*)&at[c * CH + 2 * d2];
            s2 = fma2(a, vp[d2], s2);
        }
        ob[(size_t)c * HWD] = lo2(s2) + hi2(s2);
    }
}

// ============================================================
extern "C" void kernel_launch(void* const* d_in, const int* in_sizes, int n_in,
                              void* d_out, int out_size)
{
    const float* x      = (const float*)d_in[0];
    const float* qkv_w  = (const float*)d_in[1];
    const float* dw_w   = (const float*)d_in[2];
    const float* proj_w = (const float*)d_in[3];
    const float* temp   = (const float*)d_in[4];
    float* out = (float*)d_out;

    float *qkv, *qkv2, *av;
    uint32_t *apq, *app;
    cudaGetSymbolAddress((void**)&qkv,  g_qkv);
    cudaGetSymbolAddress((void**)&qkv2, g_qkv2);
    cudaGetSymbolAddress((void**)&av,   g_av);
    cudaGetSymbolAddress((void**)&apq,  g_apq);
    cudaGetSymbolAddress((void**)&app,  g_app);

    dim3 blk(256);
    // 0) permute + tf32-convert weights
    prep_a<<<120, blk>>>(qkv_w, apq, C3);
    prep_a<<<48,  blk>>>(proj_w, app, CDIM);
    // 1) qkv 1x1 conv (tensor core tf32)
    pw_mma<<<dim3(5, 128, BATCH), blk>>>(apq, x, qkv, C3);
    // 2) depthwise 3x3
    dw_conv_kernel<<<(unsigned)((size_t)BATCH * C3 * HWD / 256), blk>>>(qkv, dw_w, qkv2);
    // 3) gram partials
    gram_kernel<<<dim3(NCHUNK, BATCH * HEADS), blk>>>();
    // 4) softmax
    attn_kernel<<<BATCH * HEADS, blk>>>(temp);
    // 5) attn @ V
    av_kernel<<<dim3(HWD / 256, BATCH * HEADS), blk>>>();
    // 6) proj 1x1 conv (tensor core tf32) -> d_out
    pw_mma<<<dim3(2, 128, BATCH), blk>>>(app, av, out, CDIM);
}

// round 5
// speedup vs baseline: 2.6153x; 1.1717x over previous
#include <cuda_runtime.h>
#include <math.h>
#include <stdint.h>

#define BATCH 8
#define CDIM 192
#define C3 576
#define HWD 16384
#define HEADS 4
#define CH 48
#define NCHUNK 16
#define CHUNK 1024

typedef unsigned long long ull;

// ---- packed f32x2 helpers ----
__device__ __forceinline__ ull fma2(ull a, ull b, ull c) {
    ull d;
    asm("fma.rn.f32x2 %0, %1, %2, %3;" : "=l"(d) : "l"(a), "l"(b), "l"(c));
    return d;
}
__device__ __forceinline__ ull pack2(float x, float y) {
    ull d;
    asm("mov.b64 %0, {%1, %2};" : "=l"(d) : "r"(__float_as_uint(x)), "r"(__float_as_uint(y)));
    return d;
}
__device__ __forceinline__ float lo2(ull a) { return __uint_as_float((unsigned)a); }
__device__ __forceinline__ float hi2(ull a) { return __uint_as_float((unsigned)(a >> 32)); }

// ---- tf32 helpers ----
__device__ __forceinline__ uint32_t f2tf32(float x) {
    uint32_t r;
    asm("cvt.rna.tf32.f32 %0, %1;" : "=r"(r) : "f"(x));
    return r;
}
__device__ __forceinline__ void mma_tf32(float* c, uint4 a, uint2 b) {
    asm volatile(
        "mma.sync.aligned.m16n8k8.row.col.f32.tf32.tf32.f32 "
        "{%0,%1,%2,%3}, {%4,%5,%6,%7}, {%8,%9}, {%0,%1,%2,%3};"
        : "+f"(c[0]), "+f"(c[1]), "+f"(c[2]), "+f"(c[3])
        : "r"(a.x), "r"(a.y), "r"(a.z), "r"(a.w), "r"(b.x), "r"(b.y));
}

// ---- scratch (device globals; no allocations allowed) ----
__device__ float g_qkv [(size_t)BATCH * C3 * HWD];
__device__ float g_qkv2[(size_t)BATCH * C3 * HWD];
__device__ float g_part_gram[(size_t)BATCH * HEADS * NCHUNK * CH * CH];
__device__ float g_part_nq  [(size_t)BATCH * HEADS * NCHUNK * CH];
__device__ float g_part_nk  [(size_t)BATCH * HEADS * NCHUNK * CH];
__device__ float g_attn     [(size_t)BATCH * HEADS * CH * CH];
__device__ float g_av [(size_t)BATCH * CDIM * HWD];
__device__ uint32_t g_apq[5 * 24 * 8 * 32 * 4];  // qkv W, fragment-permuted tf32
__device__ uint32_t g_app[2 * 24 * 8 * 32 * 4];  // proj W

// ============================================================
// Permute W[M,192] into mma fragment order + tf32 convert.
// ============================================================
__global__ __launch_bounds__(256) void prep_a(
    const float* __restrict__ W, uint32_t* __restrict__ Ap, int Mdim)
{
    const int idx = blockIdx.x * 256 + threadIdx.x;
    const int lane = idx & 31;
    int rest = idx >> 5;
    const int m16 = rest & 7; rest >>= 3;
    const int k8 = rest % 24;
    const int mt = rest / 24;
    const int g = lane >> 2, t = lane & 3;
    const int row = mt * 128 + m16 * 16 + g;
    const int k = k8 * 8 + t;
    float v0 = 0.f, v1 = 0.f, v2 = 0.f, v3 = 0.f;
    if (row < Mdim)     { v0 = W[(size_t)row * CDIM + k];       v2 = W[(size_t)row * CDIM + k + 4]; }
    if (row + 8 < Mdim) { v1 = W[(size_t)(row + 8) * CDIM + k]; v3 = W[(size_t)(row + 8) * CDIM + k + 4]; }
    uint4 o;
    o.x = f2tf32(v0); o.y = f2tf32(v1); o.z = f2tf32(v2); o.w = f2tf32(v3);
    *(uint4*)(Ap + (size_t)idx * 4) = o;
}

// ============================================================
// Pointwise 1x1 conv via mma.sync tf32
// ============================================================
__global__ __launch_bounds__(256) void pw_mma(
    const uint32_t* __restrict__ Ap, const float* __restrict__ X,
    float* __restrict__ Y, int Mdim)
{
    __shared__ __align__(16) uint32_t As[2][2048];
    __shared__ __align__(16) uint32_t Bs[2][16 * 132];
    const int tid = threadIdx.x;
    const int lane = tid & 31, wid = tid >> 5;
    const int mt = blockIdx.x;
    const int n0 = blockIdx.y * 128;
    const size_t boffX = (size_t)blockIdx.z * CDIM * HWD;
    const size_t boffY = (size_t)blockIdx.z * (size_t)Mdim * HWD;

    const uint32_t* apg = Ap + (size_t)mt * 24 * 1024;
    const int nq = tid & 31;
    const int bk0 = tid >> 5;

    uint4 a_r0, a_r1;
    float4 b_r0, b_r1;

    auto ldg_iter = [&](int it) {
        const uint32_t* ap = apg + it * 2048;
        a_r0 = *(const uint4*)(ap + (size_t)tid * 4);
        a_r1 = *(const uint4*)(ap + (size_t)(tid + 256) * 4);
        const float* xb = X + boffX + (size_t)it * 16 * HWD + n0 + nq * 4;
        b_r0 = *(const float4*)(xb + (size_t)bk0 * HWD);
        b_r1 = *(const float4*)(xb + (size_t)(bk0 + 8) * HWD);
    };
    auto sts_iter = [&](int buf) {
        *(uint4*)&As[buf][tid * 4] = a_r0;
        *(uint4*)&As[buf][(tid + 256) * 4] = a_r1;
        uint32_t* r0 = &Bs[buf][bk0 * 132 + nq * 4];
        r0[0] = f2tf32(b_r0.x); r0[1] = f2tf32(b_r0.y);
        r0[2] = f2tf32(b_r0.z); r0[3] = f2tf32(b_r0.w);
        uint32_t* r1 = &Bs[buf][(bk0 + 8) * 132 + nq * 4];
        r1[0] = f2tf32(b_r1.x); r1[1] = f2tf32(b_r1.y);
        r1[2] = f2tf32(b_r1.z); r1[3] = f2tf32(b_r1.w);
    };

    float acc[2][8][4];
#pragma unroll
    for (int f = 0; f < 2; f++)
#pragma unroll
        for (int j = 0; j < 8; j++)
#pragma unroll
            for (int e = 0; e < 4; e++) acc[f][j][e] = 0.f;

    const int m16a = (wid & 3) * 2;
    const int t = lane & 3;
    const int g = lane >> 2;
    const int nwb = (wid >> 2) * 64;

    auto compute = [&](int buf) {
#pragma unroll
        for (int k8s = 0; k8s < 2; k8s++) {
            uint4 a0 = *(const uint4*)&As[buf][((k8s * 8 + m16a) * 32 + lane) * 4];
            uint4 a1 = *(const uint4*)&As[buf][((k8s * 8 + m16a + 1) * 32 + lane) * 4];
            const int br0 = (k8s * 8 + t) * 132 + nwb + g;
            const int br1 = br0 + 4 * 132;
#pragma unroll
            for (int j = 0; j < 8; j++) {
                uint2 b = make_uint2(Bs[buf][br0 + j * 8], Bs[buf][br1 + j * 8]);
                mma_tf32(acc[0][j], a0, b);
                mma_tf32(acc[1][j], a1, b);
            }
        }
    };

    ldg_iter(0);
    sts_iter(0);
    __syncthreads();
#pragma unroll 1
    for (int it = 0; it < 12; it++) {
        if (it + 1 < 12) ldg_iter(it + 1);
        compute(it & 1);
        if (it + 1 < 12) sts_iter((it + 1) & 1);
        __syncthreads();
    }

    const int mw = mt * 128 + (wid & 3) * 32;
#pragma unroll
    for (int f = 0; f < 2; f++) {
        const int m = mw + f * 16 + g;
#pragma unroll
        for (int j = 0; j < 8; j++) {
            float* p = Y + boffY + (size_t)m * HWD + n0 + nwb + j * 8 + 2 * t;
            if (m < Mdim)
                *(float2*)p = make_float2(acc[f][j][0], acc[f][j][1]);
            if (m + 8 < Mdim)
                *(float2*)(p + (size_t)8 * HWD) = make_float2(acc[f][j][2], acc[f][j][3]);
        }
    }
}

// ============================================================
// Depthwise 3x3, pad 1 — smem row-tiled, 4 px/thread.
// Block: 8 output rows of one (b,c) image. grid = (BATCH*C3, 16).
// ============================================================
__global__ __launch_bounds__(256) void dw_conv_kernel(
    const float* __restrict__ in, const float* __restrict__ wts,
    float* __restrict__ out)
{
    __shared__ __align__(16) float tile[10][128];
    __shared__ float w[9];
    const int bc = blockIdx.x;
    const int y0 = blockIdx.y * 8;
    const int c = bc % C3;
    const int tid = threadIdx.x;
    if (tid < 9) w[tid] = wts[c * 9 + tid];

    const float* ip = in + (size_t)bc * HWD;
#pragma unroll
    for (int i = 0; i < 5; i++) {
        int idx = tid + i * 256;          // 0..1279
        int r = idx >> 7, col = idx & 127;
        int gy = y0 - 1 + r;
        tile[r][col] = (gy >= 0 && gy < 128) ? ip[gy * 128 + col] : 0.f;
    }
    __syncthreads();

    const int r = tid >> 5;               // 0..7 output row within block
    const int xb = (tid & 31) * 4;        // 0..124
    float a[3][6];
#pragma unroll
    for (int rr = 0; rr < 3; rr++) {
        float4 m4 = *(const float4*)&tile[r + rr][xb];
        a[rr][1] = m4.x; a[rr][2] = m4.y; a[rr][3] = m4.z; a[rr][4] = m4.w;
        a[rr][0] = (xb == 0)   ? 0.f : tile[r + rr][xb - 1];
        a[rr][5] = (xb == 124) ? 0.f : tile[r + rr][xb + 4];
    }
    float o[4];
#pragma unroll
    for (int p = 0; p < 4; p++) {
        float s = 0.f;
#pragma unroll
        for (int rr = 0; rr < 3; rr++)
#pragma unroll
            for (int j = 0; j < 3; j++)
                s = fmaf(a[rr][p + j], w[rr * 3 + j], s);
        o[p] = s;
    }
    *(float4*)(out + (size_t)bc * HWD + (y0 + r) * 128 + xb) =
        make_float4(o[0], o[1], o[2], o[3]);
}

// ============================================================
// Gram partials (f32x2)
// ============================================================
__global__ __launch_bounds__(256) void gram_kernel()
{
    const int chunk = blockIdx.x;
    const int bh = blockIdx.y;
    const int b = bh >> 2, h = bh & 3;
    const float* qb = g_qkv2 + ((size_t)b * C3 + h * CH) * HWD;
    const float* kb = g_qkv2 + ((size_t)b * C3 + CDIM + h * CH) * HWD;
    __shared__ __align__(16) float qs[CH][68];
    __shared__ __align__(16) float ks[CH][68];
    const int tid = threadIdx.x;
    const int tx = tid & 15, ty = tid >> 4;

    ull acc2[3][3];
#pragma unroll
    for (int i = 0; i < 3; i++)
#pragma unroll
        for (int j = 0; j < 3; j++) acc2[i][j] = 0ull;
    ull nacc2 = 0ull;
    const int n0 = chunk * CHUNK;

    for (int t0 = 0; t0 < CHUNK; t0 += 64) {
#pragma unroll
        for (int i = 0; i < 3; i++) {
            int vid = tid + i * 256;
            int row = vid >> 4;
            int col = (vid & 15) << 2;
            *(float4*)&qs[row][col] = *(const float4*)(qb + (size_t)row * HWD + n0 + t0 + col);
            *(float4*)&ks[row][col] = *(const float4*)(kb + (size_t)row * HWD + n0 + t0 + col);
        }
        __syncthreads();
#pragma unroll 4
        for (int n2 = 0; n2 < 32; n2++) {
            ull q0 = *(const ull*)&qs[ty * 3 + 0][2 * n2];
            ull q1 = *(const ull*)&qs[ty * 3 + 1][2 * n2];
            ull q2 = *(const ull*)&qs[ty * 3 + 2][2 * n2];
            ull k0 = *(const ull*)&ks[tx * 3 + 0][2 * n2];
            ull k1 = *(const ull*)&ks[tx * 3 + 1][2 * n2];
            ull k2 = *(const ull*)&ks[tx * 3 + 2][2 * n2];
            acc2[0][0] = fma2(q0, k0, acc2[0][0]); acc2[0][1] = fma2(q0, k1, acc2[0][1]); acc2[0][2] = fma2(q0, k2, acc2[0][2]);
            acc2[1][0] = fma2(q1, k0, acc2[1][0]); acc2[1][1] = fma2(q1, k1, acc2[1][1]); acc2[1][2] = fma2(q1, k2, acc2[1][2]);
            acc2[2][0] = fma2(q2, k0, acc2[2][0]); acc2[2][1] = fma2(q2, k1, acc2[2][1]); acc2[2][2] = fma2(q2, k2, acc2[2][2]);
        }
        if (tid < CH) {
#pragma unroll 8
            for (int n2 = 0; n2 < 32; n2++) {
                ull v = *(const ull*)&qs[tid][2 * n2];
                nacc2 = fma2(v, v, nacc2);
            }
        } else if (tid < 2 * CH) {
#pragma unroll 8
            for (int n2 = 0; n2 < 32; n2++) {
                ull v = *(const ull*)&ks[tid - CH][2 * n2];
                nacc2 = fma2(v, v, nacc2);
            }
        }
        __syncthreads();
    }

    float* gp = g_part_gram + ((size_t)bh * NCHUNK + chunk) * CH * CH;
#pragma unroll
    for (int i = 0; i < 3; i++)
#pragma unroll
        for (int j = 0; j < 3; j++)
            gp[(ty * 3 + i) * CH + tx * 3 + j] = lo2(acc2[i][j]) + hi2(acc2[i][j]);
    float nacc = lo2(nacc2) + hi2(nacc2);
    if (tid < CH)
        g_part_nq[((size_t)bh * NCHUNK + chunk) * CH + tid] = nacc;
    else if (tid < 2 * CH)
        g_part_nk[((size_t)bh * NCHUNK + chunk) * CH + (tid - CH)] = nacc;
}

// ============================================================
// Reduce -> normalize -> temperature -> softmax
// ============================================================
__global__ __launch_bounds__(256) void attn_kernel(const float* __restrict__ temperature)
{
    const int bh = blockIdx.x;
    const int h = bh & 3;
    __shared__ float S[CH * CH];
    __shared__ float rq[CH];
    __shared__ float rk[CH];
    const int tid = threadIdx.x;

    for (int e = tid; e < CH * CH; e += 256) {
        float s = 0.f;
#pragma unroll
        for (int p = 0; p < NCHUNK; p++)
            s += g_part_gram[((size_t)bh * NCHUNK + p) * CH * CH + e];
        S[e] = s;
    }
    if (tid < CH) {
        float s = 0.f;
#pragma unroll
        for (int p = 0; p < NCHUNK; p++) s += g_part_nq[((size_t)bh * NCHUNK + p) * CH + tid];
        rq[tid] = fmaxf(sqrtf(s), 1e-12f);
    } else if (tid < 2 * CH) {
        float s = 0.f;
#pragma unroll
        for (int p = 0; p < NCHUNK; p++) s += g_part_nk[((size_t)bh * NCHUNK + p) * CH + (tid - CH)];
        rk[tid - CH] = fmaxf(sqrtf(s), 1e-12f);
    }
    __syncthreads();

    if (tid < CH) {
        const float t = temperature[h];
        const float fq = t / rq[tid];
        float row[CH];
        float mx = -1e30f;
#pragma unroll
        for (int d = 0; d < CH; d++) {
            float v = S[tid * CH + d] * fq / rk[d];
            row[d] = v;
            mx = fmaxf(mx, v);
        }
        float sum = 0.f;
#pragma unroll
        for (int d = 0; d < CH; d++) { float e = expf(row[d] - mx); row[d] = e; sum += e; }
        float inv = 1.f / sum;
#pragma unroll
        for (int d = 0; d < CH; d++)
            g_attn[(size_t)bh * CH * CH + tid * CH + d] = row[d] * inv;
    }
}

// ============================================================
// attn @ V (f32x2, 128-bit attn LDS)
// ============================================================
__global__ __launch_bounds__(256) void av_kernel()
{
    const int bh = blockIdx.y;
    const int b = bh >> 2, h = bh & 3;
    __shared__ __align__(16) float at[CH * CH];
    const int tid = threadIdx.x;
    for (int e = tid; e < CH * CH; e += 256)
        at[e] = g_attn[(size_t)bh * CH * CH + e];
    __syncthreads();

    const int p = blockIdx.x * 256 + tid;
    const float* vb = g_qkv2 + ((size_t)b * C3 + 2 * CDIM + h * CH) * HWD + p;
    ull vp[CH / 2];
#pragma unroll
    for (int d2 = 0; d2 < CH / 2; d2++)
        vp[d2] = pack2(vb[(size_t)(2 * d2) * HWD], vb[(size_t)(2 * d2 + 1) * HWD]);

    float* ob = g_av + ((size_t)b * CDIM + h * CH) * HWD + p;
    for (int c = 0; c < CH; c++) {
        ull s2 = 0ull;
#pragma unroll
        for (int d4 = 0; d4 < CH / 4; d4++) {
            ulonglong2 a2 = *(const ulonglong2*)&at[c * CH + 4 * d4];
            s2 = fma2(a2.x, vp[2 * d4], s2);
            s2 = fma2(a2.y, vp[2 * d4 + 1], s2);
        }
        ob[(size_t)c * HWD] = lo2(s2) + hi2(s2);
    }
}

// ============================================================
extern "C" void kernel_launch(void* const* d_in, const int* in_sizes, int n_in,
                              void* d_out, int out_size)
{
    const float* x      = (const float*)d_in[0];
    const float* qkv_w  = (const float*)d_in[1];
    const float* dw_w   = (const float*)d_in[2];
    const float* proj_w = (const float*)d_in[3];
    const float* temp   = (const float*)d_in[4];
    float* out = (float*)d_out;

    float *qkv, *qkv2, *av;
    uint32_t *apq, *app;
    cudaGetSymbolAddress((void**)&qkv,  g_qkv);
    cudaGetSymbolAddress((void**)&qkv2, g_qkv2);
    cudaGetSymbolAddress((void**)&av,   g_av);
    cudaGetSymbolAddress((void**)&apq,  g_apq);
    cudaGetSymbolAddress((void**)&app,  g_app);

    dim3 blk(256);
    // 0) permute + tf32-convert weights
    prep_a<<<120, blk>>>(qkv_w, apq, C3);
    prep_a<<<48,  blk>>>(proj_w, app, CDIM);
    // 1) qkv 1x1 conv (tensor core tf32)
    pw_mma<<<dim3(5, 128, BATCH), blk>>>(apq, x, qkv, C3);
    // 2) depthwise 3x3 (smem-tiled)
    dw_conv_kernel<<<dim3(BATCH * C3, 16), blk>>>(qkv, dw_w, qkv2);
    // 3) gram partials
    gram_kernel<<<dim3(NCHUNK, BATCH * HEADS), blk>>>();
    // 4) softmax
    attn_kernel<<<BATCH * HEADS, blk>>>(temp);
    // 5) attn @ V
    av_kernel<<<dim3(HWD / 256, BATCH * HEADS), blk>>>();
    // 6) proj 1x1 conv (tensor core tf32) -> d_out
    pw_mma<<<dim3(2, 128, BATCH), blk>>>(app, av, out, CDIM);
}

// round 6
// speedup vs baseline: 3.1920x; 1.2205x over previous
#include <cuda_runtime.h>
#include <math.h>
#include <stdint.h>

#define BATCH 8
#define CDIM 192
#define C3 576
#define HWD 16384
#define HEADS 4
#define CH 48
#define NCHUNK 16
#define CHUNK 1024

typedef unsigned long long ull;

// ---- packed f32x2 helpers ----
__device__ __forceinline__ ull fma2(ull a, ull b, ull c) {
    ull d;
    asm("fma.rn.f32x2 %0, %1, %2, %3;" : "=l"(d) : "l"(a), "l"(b), "l"(c));
    return d;
}
__device__ __forceinline__ float lo2(ull a) { return __uint_as_float((unsigned)a); }
__device__ __forceinline__ float hi2(ull a) { return __uint_as_float((unsigned)(a >> 32)); }

// ---- tf32 helpers ----
__device__ __forceinline__ uint32_t f2tf32(float x) {
    uint32_t r;
    asm("cvt.rna.tf32.f32 %0, %1;" : "=r"(r) : "f"(x));
    return r;
}
__device__ __forceinline__ void mma_tf32(float* c, uint4 a, uint2 b) {
    asm volatile(
        "mma.sync.aligned.m16n8k8.row.col.f32.tf32.tf32.f32 "
        "{%0,%1,%2,%3}, {%4,%5,%6,%7}, {%8,%9}, {%0,%1,%2,%3};"
        : "+f"(c[0]), "+f"(c[1]), "+f"(c[2]), "+f"(c[3])
        : "r"(a.x), "r"(a.y), "r"(a.z), "r"(a.w), "r"(b.x), "r"(b.y));
}

// ---- scratch (device globals; no allocations allowed) ----
__device__ float g_qkv [(size_t)BATCH * C3 * HWD];
__device__ float g_qkv2[(size_t)BATCH * C3 * HWD];
__device__ float g_part_gram[(size_t)BATCH * HEADS * NCHUNK * CH * CH];
__device__ float g_part_nq  [(size_t)BATCH * HEADS * NCHUNK * CH];
__device__ float g_part_nk  [(size_t)BATCH * HEADS * NCHUNK * CH];
__device__ float g_attn     [(size_t)BATCH * HEADS * CH * CH];
__device__ float g_comb     [(size_t)BATCH * CDIM * CDIM];   // P @ blockdiag(attn)
__device__ uint32_t g_apq[5 * 24576];          // qkv W, fragment-permuted tf32
__device__ uint32_t g_apm[BATCH * 2 * 24576];  // combined proj, per batch

// ============================================================
// Permute W[M,192] (per batch) into mma fragment order + tf32 convert.
// Layout: [b][mt][k8(24)][m16(8)][lane(32)][reg(4)]
// ============================================================
__global__ __launch_bounds__(256) void prep_a(
    const float* __restrict__ W, uint32_t* __restrict__ Ap, int Mdim,
    size_t w_bstride, size_t a_bstride)
{
    const float* Wb = W + blockIdx.y * w_bstride;
    uint32_t* Apb = Ap + blockIdx.y * a_bstride;
    const int idx = blockIdx.x * 256 + threadIdx.x;
    const int lane = idx & 31;
    int rest = idx >> 5;
    const int m16 = rest & 7; rest >>= 3;
    const int k8 = rest % 24;
    const int mt = rest / 24;
    const int g = lane >> 2, t = lane & 3;
    const int row = mt * 128 + m16 * 16 + g;
    const int k = k8 * 8 + t;
    float v0 = 0.f, v1 = 0.f, v2 = 0.f, v3 = 0.f;
    if (row < Mdim)     { v0 = Wb[(size_t)row * CDIM + k];       v2 = Wb[(size_t)row * CDIM + k + 4]; }
    if (row + 8 < Mdim) { v1 = Wb[(size_t)(row + 8) * CDIM + k]; v3 = Wb[(size_t)(row + 8) * CDIM + k + 4]; }
    uint4 o;
    o.x = f2tf32(v0); o.y = f2tf32(v1); o.z = f2tf32(v2); o.w = f2tf32(v3);
    *(uint4*)(Apb + (size_t)idx * 4) = o;
}

// ============================================================
// Pointwise GEMM via mma.sync tf32: Y[b,m,n] = sum_k A[(b),m,k] X[b,k,n]
// ============================================================
__global__ __launch_bounds__(256) void pw_mma(
    const uint32_t* __restrict__ Ap, size_t a_bstride,
    const float* __restrict__ X, size_t x_bstride,
    float* __restrict__ Y, size_t y_bstride, int Mdim)
{
    __shared__ __align__(16) uint32_t As[2][2048];
    __shared__ __align__(16) uint32_t Bs[2][16 * 132];
    const int tid = threadIdx.x;
    const int lane = tid & 31, wid = tid >> 5;
    const int mt = blockIdx.x;
    const int n0 = blockIdx.y * 128;
    const size_t boffX = (size_t)blockIdx.z * x_bstride;
    const size_t boffY = (size_t)blockIdx.z * y_bstride;

    const uint32_t* apg = Ap + (size_t)blockIdx.z * a_bstride + (size_t)mt * 24576;
    const int nq = tid & 31;
    const int bk0 = tid >> 5;

    uint4 a_r0, a_r1;
    float4 b_r0, b_r1;

    auto ldg_iter = [&](int it) {
        const uint32_t* ap = apg + it * 2048;
        a_r0 = *(const uint4*)(ap + (size_t)tid * 4);
        a_r1 = *(const uint4*)(ap + (size_t)(tid + 256) * 4);
        const float* xb = X + boffX + (size_t)it * 16 * HWD + n0 + nq * 4;
        b_r0 = *(const float4*)(xb + (size_t)bk0 * HWD);
        b_r1 = *(const float4*)(xb + (size_t)(bk0 + 8) * HWD);
    };
    auto sts_iter = [&](int buf) {
        *(uint4*)&As[buf][tid * 4] = a_r0;
        *(uint4*)&As[buf][(tid + 256) * 4] = a_r1;
        uint32_t* r0 = &Bs[buf][bk0 * 132 + nq * 4];
        r0[0] = f2tf32(b_r0.x); r0[1] = f2tf32(b_r0.y);
        r0[2] = f2tf32(b_r0.z); r0[3] = f2tf32(b_r0.w);
        uint32_t* r1 = &Bs[buf][(bk0 + 8) * 132 + nq * 4];
        r1[0] = f2tf32(b_r1.x); r1[1] = f2tf32(b_r1.y);
        r1[2] = f2tf32(b_r1.z); r1[3] = f2tf32(b_r1.w);
    };

    float acc[2][8][4];
#pragma unroll
    for (int f = 0; f < 2; f++)
#pragma unroll
        for (int j = 0; j < 8; j++)
#pragma unroll
            for (int e = 0; e < 4; e++) acc[f][j][e] = 0.f;

    const int m16a = (wid & 3) * 2;
    const int t = lane & 3;
    const int g = lane >> 2;
    const int nwb = (wid >> 2) * 64;

    auto compute = [&](int buf) {
#pragma unroll
        for (int k8s = 0; k8s < 2; k8s++) {
            uint4 a0 = *(const uint4*)&As[buf][((k8s * 8 + m16a) * 32 + lane) * 4];
            uint4 a1 = *(const uint4*)&As[buf][((k8s * 8 + m16a + 1) * 32 + lane) * 4];
            const int br0 = (k8s * 8 + t) * 132 + nwb + g;
            const int br1 = br0 + 4 * 132;
#pragma unroll
            for (int j = 0; j < 8; j++) {
                uint2 b = make_uint2(Bs[buf][br0 + j * 8], Bs[buf][br1 + j * 8]);
                mma_tf32(acc[0][j], a0, b);
                mma_tf32(acc[1][j], a1, b);
            }
        }
    };

    ldg_iter(0);
    sts_iter(0);
    __syncthreads();
#pragma unroll 1
    for (int it = 0; it < 12; it++) {
        if (it + 1 < 12) ldg_iter(it + 1);
        compute(it & 1);
        if (it + 1 < 12) sts_iter((it + 1) & 1);
        __syncthreads();
    }

    const int mw = mt * 128 + (wid & 3) * 32;
#pragma unroll
    for (int f = 0; f < 2; f++) {
        const int m = mw + f * 16 + g;
#pragma unroll
        for (int j = 0; j < 8; j++) {
            float* p = Y + boffY + (size_t)m * HWD + n0 + nwb + j * 8 + 2 * t;
            if (m < Mdim)
                *(float2*)p = make_float2(acc[f][j][0], acc[f][j][1]);
            if (m + 8 < Mdim)
                *(float2*)(p + (size_t)8 * HWD) = make_float2(acc[f][j][2], acc[f][j][3]);
        }
    }
}

// ============================================================
// Depthwise 3x3, pad 1 — register sliding window + warp shuffle halos.
// One warp per 8-row strip; lane = float4 column group. No data smem.
// grid = (BATCH*C3, 2), block 256 (8 warps x 8 rows = 64 rows / block).
// ============================================================
__global__ __launch_bounds__(256) void dw_conv_kernel(
    const float* __restrict__ in, const float* __restrict__ wts,
    float* __restrict__ out)
{
    const int bc = blockIdx.x;
    const int c = bc % C3;
    const int warp = threadIdx.x >> 5;
    const int lane = threadIdx.x & 31;
    const int y0 = blockIdx.y * 64 + warp * 8;

    float w[9];
#pragma unroll
    for (int i = 0; i < 9; i++) w[i] = __ldg(wts + c * 9 + i);

    const float* ip = in + (size_t)bc * HWD + lane * 4;
    float win[3][6];

    auto loadrow = [&](int gy, float* row6) {
        float4 v = make_float4(0.f, 0.f, 0.f, 0.f);
        if (gy >= 0 && gy < 128) v = *(const float4*)(ip + (size_t)gy * 128);
        float l = __shfl_up_sync(0xffffffffu, v.w, 1);
        float r = __shfl_down_sync(0xffffffffu, v.x, 1);
        if (lane == 0)  l = 0.f;
        if (lane == 31) r = 0.f;
        row6[0] = l; row6[1] = v.x; row6[2] = v.y;
        row6[3] = v.z; row6[4] = v.w; row6[5] = r;
    };

    loadrow(y0 - 1, win[0]);
    loadrow(y0,     win[1]);
    float* op = out + (size_t)bc * HWD + lane * 4;
#pragma unroll
    for (int r = 0; r < 8; r++) {
        loadrow(y0 + 1 + r, win[(r + 2) % 3]);
        const float* tp = win[r % 3];
        const float* mp = win[(r + 1) % 3];
        const float* bp = win[(r + 2) % 3];
        float o[4];
#pragma unroll
        for (int p = 0; p < 4; p++) {
            float s = 0.f;
            s = fmaf(tp[p], w[0], s); s = fmaf(tp[p + 1], w[1], s); s = fmaf(tp[p + 2], w[2], s);
            s = fmaf(mp[p], w[3], s); s = fmaf(mp[p + 1], w[4], s); s = fmaf(mp[p + 2], w[5], s);
            s = fmaf(bp[p], w[6], s); s = fmaf(bp[p + 1], w[7], s); s = fmaf(bp[p + 2], w[8], s);
            o[p] = s;
        }
        *(float4*)(op + (size_t)(y0 + r) * 128) = make_float4(o[0], o[1], o[2], o[3]);
    }
}

// ============================================================
// Gram partials (f32x2)
// ============================================================
__global__ __launch_bounds__(256) void gram_kernel()
{
    const int chunk = blockIdx.x;
    const int bh = blockIdx.y;
    const int b = bh >> 2, h = bh & 3;
    const float* qb = g_qkv2 + ((size_t)b * C3 + h * CH) * HWD;
    const float* kb = g_qkv2 + ((size_t)b * C3 + CDIM + h * CH) * HWD;
    __shared__ __align__(16) float qs[CH][68];
    __shared__ __align__(16) float ks[CH][68];
    const int tid = threadIdx.x;
    const int tx = tid & 15, ty = tid >> 4;

    ull acc2[3][3];
#pragma unroll
    for (int i = 0; i < 3; i++)
#pragma unroll
        for (int j = 0; j < 3; j++) acc2[i][j] = 0ull;
    ull nacc2 = 0ull;
    const int n0 = chunk * CHUNK;

    for (int t0 = 0; t0 < CHUNK; t0 += 64) {
#pragma unroll
        for (int i = 0; i < 3; i++) {
            int vid = tid + i * 256;
            int row = vid >> 4;
            int col = (vid & 15) << 2;
            *(float4*)&qs[row][col] = *(const float4*)(qb + (size_t)row * HWD + n0 + t0 + col);
            *(float4*)&ks[row][col] = *(const float4*)(kb + (size_t)row * HWD + n0 + t0 + col);
        }
        __syncthreads();
#pragma unroll 4
        for (int n2 = 0; n2 < 32; n2++) {
            ull q0 = *(const ull*)&qs[ty * 3 + 0][2 * n2];
            ull q1 = *(const ull*)&qs[ty * 3 + 1][2 * n2];
            ull q2 = *(const ull*)&qs[ty * 3 + 2][2 * n2];
            ull k0 = *(const ull*)&ks[tx * 3 + 0][2 * n2];
            ull k1 = *(const ull*)&ks[tx * 3 + 1][2 * n2];
            ull k2 = *(const ull*)&ks[tx * 3 + 2][2 * n2];
            acc2[0][0] = fma2(q0, k0, acc2[0][0]); acc2[0][1] = fma2(q0, k1, acc2[0][1]); acc2[0][2] = fma2(q0, k2, acc2[0][2]);
            acc2[1][0] = fma2(q1, k0, acc2[1][0]); acc2[1][1] = fma2(q1, k1, acc2[1][1]); acc2[1][2] = fma2(q1, k2, acc2[1][2]);
            acc2[2][0] = fma2(q2, k0, acc2[2][0]); acc2[2][1] = fma2(q2, k1, acc2[2][1]); acc2[2][2] = fma2(q2, k2, acc2[2][2]);
        }
        if (tid < CH) {
#pragma unroll 8
            for (int n2 = 0; n2 < 32; n2++) {
                ull v = *(const ull*)&qs[tid][2 * n2];
                nacc2 = fma2(v, v, nacc2);
            }
        } else if (tid < 2 * CH) {
#pragma unroll 8
            for (int n2 = 0; n2 < 32; n2++) {
                ull v = *(const ull*)&ks[tid - CH][2 * n2];
                nacc2 = fma2(v, v, nacc2);
            }
        }
        __syncthreads();
    }

    float* gp = g_part_gram + ((size_t)bh * NCHUNK + chunk) * CH * CH;
#pragma unroll
    for (int i = 0; i < 3; i++)
#pragma unroll
        for (int j = 0; j < 3; j++)
            gp[(ty * 3 + i) * CH + tx * 3 + j] = lo2(acc2[i][j]) + hi2(acc2[i][j]);
    float nacc = lo2(nacc2) + hi2(nacc2);
    if (tid < CH)
        g_part_nq[((size_t)bh * NCHUNK + chunk) * CH + tid] = nacc;
    else if (tid < 2 * CH)
        g_part_nk[((size_t)bh * NCHUNK + chunk) * CH + (tid - CH)] = nacc;
}

// ============================================================
// Reduce -> normalize -> temperature -> softmax
// ============================================================
__global__ __launch_bounds__(256) void attn_kernel(const float* __restrict__ temperature)
{
    const int bh = blockIdx.x;
    const int h = bh & 3;
    __shared__ float S[CH * CH];
    __shared__ float rq[CH];
    __shared__ float rk[CH];
    const int tid = threadIdx.x;

    for (int e = tid; e < CH * CH; e += 256) {
        float s = 0.f;
#pragma unroll
        for (int p = 0; p < NCHUNK; p++)
            s += g_part_gram[((size_t)bh * NCHUNK + p) * CH * CH + e];
        S[e] = s;
    }
    if (tid < CH) {
        float s = 0.f;
#pragma unroll
        for (int p = 0; p < NCHUNK; p++) s += g_part_nq[((size_t)bh * NCHUNK + p) * CH + tid];
        rq[tid] = fmaxf(sqrtf(s), 1e-12f);
    } else if (tid < 2 * CH) {
        float s = 0.f;
#pragma unroll
        for (int p = 0; p < NCHUNK; p++) s += g_part_nk[((size_t)bh * NCHUNK + p) * CH + (tid - CH)];
        rk[tid - CH] = fmaxf(sqrtf(s), 1e-12f);
    }
    __syncthreads();

    if (tid < CH) {
        const float t = temperature[h];
        const float fq = t / rq[tid];
        float row[CH];
        float mx = -1e30f;
#pragma unroll
        for (int d = 0; d < CH; d++) {
            float v = S[tid * CH + d] * fq / rk[d];
            row[d] = v;
            mx = fmaxf(mx, v);
        }
        float sum = 0.f;
#pragma unroll
        for (int d = 0; d < CH; d++) { float e = expf(row[d] - mx); row[d] = e; sum += e; }
        float inv = 1.f / sum;
#pragma unroll
        for (int d = 0; d < CH; d++)
            g_attn[(size_t)bh * CH * CH + tid * CH + d] = row[d] * inv;
    }
}

// ============================================================
// Fold attention into proj: Comb[b][m][h*48+d] = sum_c P[m][h*48+c] A[bh][c][d]
// One block per (b,h), 192 threads (one per output row m).
// ============================================================
__global__ __launch_bounds__(192) void combine_kernel(const float* __restrict__ P)
{
    const int bh = blockIdx.x;
    const int b = bh >> 2, h = bh & 3;
    __shared__ float A[CH * CH];
    for (int e = threadIdx.x; e < CH * CH; e += 192)
        A[e] = g_attn[(size_t)bh * CH * CH + e];
    __syncthreads();

    const int m = threadIdx.x;
    float p[CH];
#pragma unroll
    for (int c = 0; c < CH; c++) p[c] = P[(size_t)m * CDIM + h * CH + c];
    float* outp = g_comb + ((size_t)b * CDIM + m) * CDIM + h * CH;
#pragma unroll 4
    for (int d = 0; d < CH; d++) {
        float s = 0.f;
#pragma unroll
        for (int c = 0; c < CH; c++) s = fmaf(p[c], A[c * CH + d], s);
        outp[d] = s;
    }
}

// ============================================================
extern "C" void kernel_launch(void* const* d_in, const int* in_sizes, int n_in,
                              void* d_out, int out_size)
{
    const float* x      = (const float*)d_in[0];
    const float* qkv_w  = (const float*)d_in[1];
    const float* dw_w   = (const float*)d_in[2];
    const float* proj_w = (const float*)d_in[3];
    const float* temp   = (const float*)d_in[4];
    float* out = (float*)d_out;

    float *qkv, *qkv2, *comb;
    uint32_t *apq, *apm;
    cudaGetSymbolAddress((void**)&qkv,  g_qkv);
    cudaGetSymbolAddress((void**)&qkv2, g_qkv2);
    cudaGetSymbolAddress((void**)&comb, g_comb);
    cudaGetSymbolAddress((void**)&apq,  g_apq);
    cudaGetSymbolAddress((void**)&apm,  g_apm);

    dim3 blk(256);
    // 0) permute + tf32-convert qkv weights (5 m-tiles, single "batch")
    prep_a<<<dim3(120, 1), blk>>>(qkv_w, apq, C3, 0, 0);
    // 1) qkv 1x1 conv (tensor core tf32)
    pw_mma<<<dim3(5, 128, BATCH), blk>>>(apq, 0, x, (size_t)CDIM * HWD, qkv, (size_t)C3 * HWD, C3);
    // 2) depthwise 3x3 (register sliding window)
    dw_conv_kernel<<<dim3(BATCH * C3, 2), blk>>>(qkv, dw_w, qkv2);
    // 3) gram partials
    gram_kernel<<<dim3(NCHUNK, BATCH * HEADS), blk>>>();
    // 4) softmax
    attn_kernel<<<BATCH * HEADS, blk>>>(temp);
    // 5) fold attn into proj weights (per batch)
    combine_kernel<<<BATCH * HEADS, 192>>>(proj_w);
    // 6) permute combined weights (2 m-tiles per batch)
    prep_a<<<dim3(48, BATCH), blk>>>(comb, apm, CDIM, (size_t)CDIM * CDIM, 2 * 24576);
    // 7) fused (proj @ attn) @ v -> d_out  (v = rows [384,576) of qkv2)
    pw_mma<<<dim3(2, 128, BATCH), blk>>>(apm, 2 * 24576,
                                         qkv2 + (size_t)2 * CDIM * HWD, (size_t)C3 * HWD,
                                         out, (size_t)CDIM * HWD, CDIM);
}

// round 7
// speedup vs baseline: 3.2616x; 1.0218x over previous
#include <cuda_runtime.h>
#include <math.h>
#include <stdint.h>

#define BATCH 8
#define CDIM 192
#define C3 576
#define HWD 16384
#define HEADS 4
#define CH 48
#define NCHUNK 16

typedef unsigned long long ull;

// ---- tf32 helpers ----
__device__ __forceinline__ uint32_t f2tf32(float x) {
    uint32_t r;
    asm("cvt.rna.tf32.f32 %0, %1;" : "=r"(r) : "f"(x));
    return r;
}
__device__ __forceinline__ void mma_tf32(float* c, uint4 a, uint2 b) {
    asm volatile(
        "mma.sync.aligned.m16n8k8.row.col.f32.tf32.tf32.f32 "
        "{%0,%1,%2,%3}, {%4,%5,%6,%7}, {%8,%9}, {%0,%1,%2,%3};"
        : "+f"(c[0]), "+f"(c[1]), "+f"(c[2]), "+f"(c[3])
        : "r"(a.x), "r"(a.y), "r"(a.z), "r"(a.w), "r"(b.x), "r"(b.y));
}

// ---- scratch (device globals; no allocations allowed) ----
__device__ float g_qkv [(size_t)BATCH * C3 * HWD];
__device__ float g_qkv2[(size_t)BATCH * C3 * HWD];
__device__ float g_part_gram[(size_t)BATCH * HEADS * NCHUNK * 96 * 96];
__device__ float g_attn     [(size_t)BATCH * HEADS * CH * CH];
__device__ float g_comb     [(size_t)BATCH * CDIM * CDIM];   // P @ blockdiag(attn)
__device__ uint32_t g_apq[5 * 24576];          // qkv W, fragment-permuted tf32
__device__ uint32_t g_apm[BATCH * 2 * 24576];  // combined proj, per batch

// ============================================================
// Permute W[M,192] (per batch) into mma fragment order + tf32 convert.
// ============================================================
__global__ __launch_bounds__(256) void prep_a(
    const float* __restrict__ W, uint32_t* __restrict__ Ap, int Mdim,
    size_t w_bstride, size_t a_bstride)
{
    const float* Wb = W + blockIdx.y * w_bstride;
    uint32_t* Apb = Ap + blockIdx.y * a_bstride;
    const int idx = blockIdx.x * 256 + threadIdx.x;
    const int lane = idx & 31;
    int rest = idx >> 5;
    const int m16 = rest & 7; rest >>= 3;
    const int k8 = rest % 24;
    const int mt = rest / 24;
    const int g = lane >> 2, t = lane & 3;
    const int row = mt * 128 + m16 * 16 + g;
    const int k = k8 * 8 + t;
    float v0 = 0.f, v1 = 0.f, v2 = 0.f, v3 = 0.f;
    if (row < Mdim)     { v0 = Wb[(size_t)row * CDIM + k];       v2 = Wb[(size_t)row * CDIM + k + 4]; }
    if (row + 8 < Mdim) { v1 = Wb[(size_t)(row + 8) * CDIM + k]; v3 = Wb[(size_t)(row + 8) * CDIM + k + 4]; }
    uint4 o;
    o.x = f2tf32(v0); o.y = f2tf32(v1); o.z = f2tf32(v2); o.w = f2tf32(v3);
    *(uint4*)(Apb + (size_t)idx * 4) = o;
}

// ============================================================
// Pointwise GEMM via mma.sync tf32: Y[b,m,n] = sum_k A[(b),m,k] X[b,k,n]
// ============================================================
__global__ __launch_bounds__(256) void pw_mma(
    const uint32_t* __restrict__ Ap, size_t a_bstride,
    const float* __restrict__ X, size_t x_bstride,
    float* __restrict__ Y, size_t y_bstride, int Mdim)
{
    __shared__ __align__(16) uint32_t As[2][2048];
    __shared__ __align__(16) uint32_t Bs[2][16 * 132];
    const int tid = threadIdx.x;
    const int lane = tid & 31, wid = tid >> 5;
    const int mt = blockIdx.x;
    const int n0 = blockIdx.y * 128;
    const size_t boffX = (size_t)blockIdx.z * x_bstride;
    const size_t boffY = (size_t)blockIdx.z * y_bstride;

    const uint32_t* apg = Ap + (size_t)blockIdx.z * a_bstride + (size_t)mt * 24576;
    const int nq = tid & 31;
    const int bk0 = tid >> 5;

    uint4 a_r0, a_r1;
    float4 b_r0, b_r1;

    auto ldg_iter = [&](int it) {
        const uint32_t* ap = apg + it * 2048;
        a_r0 = *(const uint4*)(ap + (size_t)tid * 4);
        a_r1 = *(const uint4*)(ap + (size_t)(tid + 256) * 4);
        const float* xb = X + boffX + (size_t)it * 16 * HWD + n0 + nq * 4;
        b_r0 = *(const float4*)(xb + (size_t)bk0 * HWD);
        b_r1 = *(const float4*)(xb + (size_t)(bk0 + 8) * HWD);
    };
    auto sts_iter = [&](int buf) {
        *(uint4*)&As[buf][tid * 4] = a_r0;
        *(uint4*)&As[buf][(tid + 256) * 4] = a_r1;
        uint32_t* r0 = &Bs[buf][bk0 * 132 + nq * 4];
        r0[0] = f2tf32(b_r0.x); r0[1] = f2tf32(b_r0.y);
        r0[2] = f2tf32(b_r0.z); r0[3] = f2tf32(b_r0.w);
        uint32_t* r1 = &Bs[buf][(bk0 + 8) * 132 + nq * 4];
        r1[0] = f2tf32(b_r1.x); r1[1] = f2tf32(b_r1.y);
        r1[2] = f2tf32(b_r1.z); r1[3] = f2tf32(b_r1.w);
    };

    float acc[2][8][4];
#pragma unroll
    for (int f = 0; f < 2; f++)
#pragma unroll
        for (int j = 0; j < 8; j++)
#pragma unroll
            for (int e = 0; e < 4; e++) acc[f][j][e] = 0.f;

    const int m16a = (wid & 3) * 2;
    const int t = lane & 3;
    const int g = lane >> 2;
    const int nwb = (wid >> 2) * 64;

    auto compute = [&](int buf) {
#pragma unroll
        for (int k8s = 0; k8s < 2; k8s++) {
            uint4 a0 = *(const uint4*)&As[buf][((k8s * 8 + m16a) * 32 + lane) * 4];
            uint4 a1 = *(const uint4*)&As[buf][((k8s * 8 + m16a + 1) * 32 + lane) * 4];
            const int br0 = (k8s * 8 + t) * 132 + nwb + g;
            const int br1 = br0 + 4 * 132;
#pragma unroll
            for (int j = 0; j < 8; j++) {
                uint2 b = make_uint2(Bs[buf][br0 + j * 8], Bs[buf][br1 + j * 8]);
                mma_tf32(acc[0][j], a0, b);
                mma_tf32(acc[1][j], a1, b);
            }
        }
    };

    ldg_iter(0);
    sts_iter(0);
    __syncthreads();
#pragma unroll 1
    for (int it = 0; it < 12; it++) {
        if (it + 1 < 12) ldg_iter(it + 1);
        compute(it & 1);
        if (it + 1 < 12) sts_iter((it + 1) & 1);
        __syncthreads();
    }

    const int mw = mt * 128 + (wid & 3) * 32;
#pragma unroll
    for (int f = 0; f < 2; f++) {
        const int m = mw + f * 16 + g;
#pragma unroll
        for (int j = 0; j < 8; j++) {
            float* p = Y + boffY + (size_t)m * HWD + n0 + nwb + j * 8 + 2 * t;
            if (m < Mdim)
                *(float2*)p = make_float2(acc[f][j][0], acc[f][j][1]);
            if (m + 8 < Mdim)
                *(float2*)(p + (size_t)8 * HWD) = make_float2(acc[f][j][2], acc[f][j][3]);
        }
    }
}

// ============================================================
// Depthwise 3x3, pad 1 — register sliding window + warp shuffle halos.
// ============================================================
__global__ __launch_bounds__(256) void dw_conv_kernel(
    const float* __restrict__ in, const float* __restrict__ wts,
    float* __restrict__ out)
{
    const int bc = blockIdx.x;
    const int c = bc % C3;
    const int warp = threadIdx.x >> 5;
    const int lane = threadIdx.x & 31;
    const int y0 = blockIdx.y * 64 + warp * 8;

    float w[9];
#pragma unroll
    for (int i = 0; i < 9; i++) w[i] = __ldg(wts + c * 9 + i);

    const float* ip = in + (size_t)bc * HWD + lane * 4;
    float win[3][6];

    auto loadrow = [&](int gy, float* row6) {
        float4 v = make_float4(0.f, 0.f, 0.f, 0.f);
        if (gy >= 0 && gy < 128) v = *(const float4*)(ip + (size_t)gy * 128);
        float l = __shfl_up_sync(0xffffffffu, v.w, 1);
        float r = __shfl_down_sync(0xffffffffu, v.x, 1);
        if (lane == 0)  l = 0.f;
        if (lane == 31) r = 0.f;
        row6[0] = l; row6[1] = v.x; row6[2] = v.y;
        row6[3] = v.z; row6[4] = v.w; row6[5] = r;
    };

    loadrow(y0 - 1, win[0]);
    loadrow(y0,     win[1]);
    float* op = out + (size_t)bc * HWD + lane * 4;
#pragma unroll
    for (int r = 0; r < 8; r++) {
        loadrow(y0 + 1 + r, win[(r + 2) % 3]);
        const float* tp = win[r % 3];
        const float* mp = win[(r + 1) % 3];
        const float* bp = win[(r + 2) % 3];
        float o[4];
#pragma unroll
        for (int p = 0; p < 4; p++) {
            float s = 0.f;
            s = fmaf(tp[p], w[0], s); s = fmaf(tp[p + 1], w[1], s); s = fmaf(tp[p + 2], w[2], s);
            s = fmaf(mp[p], w[3], s); s = fmaf(mp[p + 1], w[4], s); s = fmaf(mp[p + 2], w[5], s);
            s = fmaf(bp[p], w[6], s); s = fmaf(bp[p + 1], w[7], s); s = fmaf(bp[p + 2], w[8], s);
            o[p] = s;
        }
        *(float4*)(op + (size_t)(y0 + r) * 128) = make_float4(o[0], o[1], o[2], o[3]);
    }
}

// ============================================================
// Unified self-gram on tensor cores: G=[Q;K] (96 rows), partial G@G^T
// per (bh, chunk of 1024 px). Q.K^T block = logits; diag = norms.
// 6 compute warps: warp = (mrow 0..2) x (nhalf 0..1); each 2xm16 x 6xn8.
// ============================================================
__global__ __launch_bounds__(256) void gram_kernel()
{
    const int chunk = blockIdx.x;
    const int bh = blockIdx.y;
    const int b = bh >> 2, h = bh & 3;
    const float* qb = g_qkv2 + ((size_t)b * C3 + h * CH) * HWD;
    const float* kb = g_qkv2 + ((size_t)b * C3 + CDIM + h * CH) * HWD;
    __shared__ __align__(16) uint32_t Gs[96][68];
    const int tid = threadIdx.x;
    const int lane = tid & 31, wid = tid >> 5;
    const int n0 = chunk * 1024;

    float acc[2][6][4];
#pragma unroll
    for (int aa = 0; aa < 2; aa++)
#pragma unroll
        for (int jj = 0; jj < 6; jj++)
#pragma unroll
            for (int e = 0; e < 4; e++) acc[aa][jj][e] = 0.f;

    const int mrow = wid % 3;
    const int nhalf = (wid < 6) ? (wid / 3) : 0;
    const int g = lane >> 2, t = lane & 3;

#pragma unroll 1
    for (int t0 = 0; t0 < 1024; t0 += 64) {
#pragma unroll
        for (int i = 0; i < 6; i++) {
            int idx = tid + i * 256;
            int row = idx >> 4;
            int col = (idx & 15) << 2;
            const float* src = (row < CH ? qb + (size_t)row * HWD
                                         : kb + (size_t)(row - CH) * HWD) + n0 + t0 + col;
            float4 v = *(const float4*)src;
            Gs[row][col + 0] = f2tf32(v.x); Gs[row][col + 1] = f2tf32(v.y);
            Gs[row][col + 2] = f2tf32(v.z); Gs[row][col + 3] = f2tf32(v.w);
        }
        __syncthreads();
        if (wid < 6) {
#pragma unroll
            for (int k8 = 0; k8 < 8; k8++) {
                const int k = k8 * 8;
                uint4 a[2];
#pragma unroll
                for (int aa = 0; aa < 2; aa++) {
                    const int mr = 16 * (mrow + 3 * aa) + g;
                    a[aa].x = Gs[mr][k + t];
                    a[aa].y = Gs[mr + 8][k + t];
                    a[aa].z = Gs[mr][k + t + 4];
                    a[aa].w = Gs[mr + 8][k + t + 4];
                }
#pragma unroll
                for (int jj = 0; jj < 6; jj++) {
                    const int nr = 8 * (6 * nhalf + jj) + g;
                    uint2 bf = make_uint2(Gs[nr][k + t], Gs[nr][k + t + 4]);
                    mma_tf32(acc[0][jj], a[0], bf);
                    mma_tf32(acc[1][jj], a[1], bf);
                }
            }
        }
        __syncthreads();
    }

    if (wid < 6) {
        float* gp = g_part_gram + ((size_t)bh * NCHUNK + chunk) * 9216;
#pragma unroll
        for (int aa = 0; aa < 2; aa++) {
            const int m = 16 * (mrow + 3 * aa) + g;
#pragma unroll
            for (int jj = 0; jj < 6; jj++) {
                const int n = 8 * (6 * nhalf + jj) + 2 * t;
                *(float2*)&gp[m * 96 + n] = make_float2(acc[aa][jj][0], acc[aa][jj][1]);
                *(float2*)&gp[(m + 8) * 96 + n] = make_float2(acc[aa][jj][2], acc[aa][jj][3]);
            }
        }
    }
}

// ============================================================
// Reduce partial 96x96 grams -> normalize -> temperature -> softmax
// ============================================================
__global__ __launch_bounds__(256) void attn_kernel(const float* __restrict__ temperature)
{
    const int bh = blockIdx.x;
    const int h = bh & 3;
    __shared__ float S[CH * CH];
    __shared__ float rq[CH];
    __shared__ float rk[CH];
    const int tid = threadIdx.x;
    const float* base = g_part_gram + (size_t)bh * NCHUNK * 9216;

    for (int e = tid; e < CH * CH; e += 256) {
        const int c = e / CH, d = e % CH;
        float s = 0.f;
#pragma unroll
        for (int p = 0; p < NCHUNK; p++)
            s += base[(size_t)p * 9216 + c * 96 + CH + d];
        S[e] = s;
    }
    if (tid < CH) {
        float s = 0.f;
#pragma unroll
        for (int p = 0; p < NCHUNK; p++) s += base[(size_t)p * 9216 + tid * 96 + tid];
        rq[tid] = fmaxf(sqrtf(s), 1e-12f);
    } else if (tid < 2 * CH) {
        const int d = tid - CH;
        float s = 0.f;
#pragma unroll
        for (int p = 0; p < NCHUNK; p++) s += base[(size_t)p * 9216 + (CH + d) * 96 + CH + d];
        rk[d] = fmaxf(sqrtf(s), 1e-12f);
    }
    __syncthreads();

    if (tid < CH) {
        const float t = temperature[h];
        const float fq = t / rq[tid];
        float row[CH];
        float mx = -1e30f;
#pragma unroll
        for (int d = 0; d < CH; d++) {
            float v = S[tid * CH + d] * fq / rk[d];
            row[d] = v;
            mx = fmaxf(mx, v);
        }
        float sum = 0.f;
#pragma unroll
        for (int d = 0; d < CH; d++) { float e = expf(row[d] - mx); row[d] = e; sum += e; }
        float inv = 1.f / sum;
#pragma unroll
        for (int d = 0; d < CH; d++)
            g_attn[(size_t)bh * CH * CH + tid * CH + d] = row[d] * inv;
    }
}

// ============================================================
// Fold attention into proj: Comb[b][m][h*48+d] = sum_c P[m][h*48+c] A[bh][c][d]
// ============================================================
__global__ __launch_bounds__(192) void combine_kernel(const float* __restrict__ P)
{
    const int bh = blockIdx.x;
    const int b = bh >> 2, h = bh & 3;
    __shared__ float A[CH * CH];
    for (int e = threadIdx.x; e < CH * CH; e += 192)
        A[e] = g_attn[(size_t)bh * CH * CH + e];
    __syncthreads();

    const int m = threadIdx.x;
    float p[CH];
#pragma unroll
    for (int c = 0; c < CH; c++) p[c] = P[(size_t)m * CDIM + h * CH + c];
    float* outp = g_comb + ((size_t)b * CDIM + m) * CDIM + h * CH;
#pragma unroll 4
    for (int d = 0; d < CH; d++) {
        float s = 0.f;
#pragma unroll
        for (int c = 0; c < CH; c++) s = fmaf(p[c], A[c * CH + d], s);
        outp[d] = s;
    }
}

// ============================================================
extern "C" void kernel_launch(void* const* d_in, const int* in_sizes, int n_in,
                              void* d_out, int out_size)
{
    const float* x      = (const float*)d_in[0];
    const float* qkv_w  = (const float*)d_in[1];
    const float* dw_w   = (const float*)d_in[2];
    const float* proj_w = (const float*)d_in[3];
    const float* temp   = (const float*)d_in[4];
    float* out = (float*)d_out;

    float *qkv, *qkv2, *comb;
    uint32_t *apq, *apm;
    cudaGetSymbolAddress((void**)&qkv,  g_qkv);
    cudaGetSymbolAddress((void**)&qkv2, g_qkv2);
    cudaGetSymbolAddress((void**)&comb, g_comb);
    cudaGetSymbolAddress((void**)&apq,  g_apq);
    cudaGetSymbolAddress((void**)&apm,  g_apm);

    dim3 blk(256);
    // 0) permute + tf32-convert qkv weights
    prep_a<<<dim3(120, 1), blk>>>(qkv_w, apq, C3, 0, 0);
    // 1) qkv 1x1 conv (tensor core tf32)
    pw_mma<<<dim3(5, 128, BATCH), blk>>>(apq, 0, x, (size_t)CDIM * HWD, qkv, (size_t)C3 * HWD, C3);
    // 2) depthwise 3x3 (register sliding window)
    dw_conv_kernel<<<dim3(BATCH * C3, 2), blk>>>(qkv, dw_w, qkv2);
    // 3) unified self-gram partials (tensor cores)
    gram_kernel<<<dim3(NCHUNK, BATCH * HEADS), blk>>>();
    // 4) softmax
    attn_kernel<<<BATCH * HEADS, blk>>>(temp);
    // 5) fold attn into proj weights (per batch)
    combine_kernel<<<BATCH * HEADS, 192>>>(proj_w);
    // 6) permute combined weights
    prep_a<<<dim3(48, BATCH), blk>>>(comb, apm, CDIM, (size_t)CDIM * CDIM, 2 * 24576);
    // 7) fused (proj @ attn) @ v -> d_out
    pw_mma<<<dim3(2, 128, BATCH), blk>>>(apm, 2 * 24576,
                                         qkv2 + (size_t)2 * CDIM * HWD, (size_t)C3 * HWD,
                                         out, (size_t)CDIM * HWD, CDIM);
}

// round 8
// speedup vs baseline: 3.5548x; 1.0899x over previous
#include <cuda_runtime.h>
#include <math.h>
#include <stdint.h>

#define BATCH 8
#define CDIM 192
#define C3 576
#define HWD 16384
#define HEADS 4
#define CH 48
#define NCHUNK 16

typedef unsigned long long ull;

// ---- tf32 helpers ----
__device__ __forceinline__ uint32_t f2tf32(float x) {
    uint32_t r;
    asm("cvt.rna.tf32.f32 %0, %1;" : "=r"(r) : "f"(x));
    return r;
}
__device__ __forceinline__ void mma_tf32(float* c, uint4 a, uint2 b) {
    asm volatile(
        "mma.sync.aligned.m16n8k8.row.col.f32.tf32.tf32.f32 "
        "{%0,%1,%2,%3}, {%4,%5,%6,%7}, {%8,%9}, {%0,%1,%2,%3};"
        : "+f"(c[0]), "+f"(c[1]), "+f"(c[2]), "+f"(c[3])
        : "r"(a.x), "r"(a.y), "r"(a.z), "r"(a.w), "r"(b.x), "r"(b.y));
}

// ---- scratch (device globals; no allocations allowed) ----
__device__ float g_qkv [(size_t)BATCH * C3 * HWD];
__device__ float g_qkv2[(size_t)BATCH * C3 * HWD];
__device__ float g_part_gram[(size_t)BATCH * HEADS * NCHUNK * CH * CH];
__device__ float g_part_nq  [(size_t)BATCH * HEADS * NCHUNK * CH];
__device__ float g_part_nk  [(size_t)BATCH * HEADS * NCHUNK * CH];
__device__ float g_attn     [(size_t)BATCH * HEADS * CH * CH];
__device__ float g_comb     [(size_t)BATCH * CDIM * CDIM];   // P @ blockdiag(attn)
__device__ uint32_t g_apq[5 * 24576];          // qkv W, fragment-permuted tf32
__device__ uint32_t g_apm[BATCH * 2 * 24576];  // combined proj, per batch

// ============================================================
// Permute W[M,192] (per batch) into mma fragment order + tf32 convert.
// ============================================================
__global__ __launch_bounds__(256) void prep_a(
    const float* __restrict__ W, uint32_t* __restrict__ Ap, int Mdim,
    size_t w_bstride, size_t a_bstride)
{
    const float* Wb = W + blockIdx.y * w_bstride;
    uint32_t* Apb = Ap + blockIdx.y * a_bstride;
    const int idx = blockIdx.x * 256 + threadIdx.x;
    const int lane = idx & 31;
    int rest = idx >> 5;
    const int m16 = rest & 7; rest >>= 3;
    const int k8 = rest % 24;
    const int mt = rest / 24;
    const int g = lane >> 2, t = lane & 3;
    const int row = mt * 128 + m16 * 16 + g;
    const int k = k8 * 8 + t;
    float v0 = 0.f, v1 = 0.f, v2 = 0.f, v3 = 0.f;
    if (row < Mdim)     { v0 = Wb[(size_t)row * CDIM + k];       v2 = Wb[(size_t)row * CDIM + k + 4]; }
    if (row + 8 < Mdim) { v1 = Wb[(size_t)(row + 8) * CDIM + k]; v3 = Wb[(size_t)(row + 8) * CDIM + k + 4]; }
    uint4 o;
    o.x = f2tf32(v0); o.y = f2tf32(v1); o.z = f2tf32(v2); o.w = f2tf32(v3);
    *(uint4*)(Apb + (size_t)idx * 4) = o;
}

// ============================================================
// Pointwise GEMM via mma.sync tf32: Y[b,m,n] = sum_k A[(b),m,k] X[b,k,n]
// ============================================================
__global__ __launch_bounds__(256) void pw_mma(
    const uint32_t* __restrict__ Ap, size_t a_bstride,
    const float* __restrict__ X, size_t x_bstride,
    float* __restrict__ Y, size_t y_bstride, int Mdim)
{
    __shared__ __align__(16) uint32_t As[2][2048];
    __shared__ __align__(16) uint32_t Bs[2][16 * 132];
    const int tid = threadIdx.x;
    const int lane = tid & 31, wid = tid >> 5;
    const int mt = blockIdx.x;
    const int n0 = blockIdx.y * 128;
    const size_t boffX = (size_t)blockIdx.z * x_bstride;
    const size_t boffY = (size_t)blockIdx.z * y_bstride;

    const uint32_t* apg = Ap + (size_t)blockIdx.z * a_bstride + (size_t)mt * 24576;
    const int nq = tid & 31;
    const int bk0 = tid >> 5;

    uint4 a_r0, a_r1;
    float4 b_r0, b_r1;

    auto ldg_iter = [&](int it) {
        const uint32_t* ap = apg + it * 2048;
        a_r0 = *(const uint4*)(ap + (size_t)tid * 4);
        a_r1 = *(const uint4*)(ap + (size_t)(tid + 256) * 4);
        const float* xb = X + boffX + (size_t)it * 16 * HWD + n0 + nq * 4;
        b_r0 = *(const float4*)(xb + (size_t)bk0 * HWD);
        b_r1 = *(const float4*)(xb + (size_t)(bk0 + 8) * HWD);
    };
    auto sts_iter = [&](int buf) {
        *(uint4*)&As[buf][tid * 4] = a_r0;
        *(uint4*)&As[buf][(tid + 256) * 4] = a_r1;
        uint32_t* r0 = &Bs[buf][bk0 * 132 + nq * 4];
        r0[0] = f2tf32(b_r0.x); r0[1] = f2tf32(b_r0.y);
        r0[2] = f2tf32(b_r0.z); r0[3] = f2tf32(b_r0.w);
        uint32_t* r1 = &Bs[buf][(bk0 + 8) * 132 + nq * 4];
        r1[0] = f2tf32(b_r1.x); r1[1] = f2tf32(b_r1.y);
        r1[2] = f2tf32(b_r1.z); r1[3] = f2tf32(b_r1.w);
    };

    float acc[2][8][4];
#pragma unroll
    for (int f = 0; f < 2; f++)
#pragma unroll
        for (int j = 0; j < 8; j++)
#pragma unroll
            for (int e = 0; e < 4; e++) acc[f][j][e] = 0.f;

    const int m16a = (wid & 3) * 2;
    const int t = lane & 3;
    const int g = lane >> 2;
    const int nwb = (wid >> 2) * 64;

    auto compute = [&](int buf) {
#pragma unroll
        for (int k8s = 0; k8s < 2; k8s++) {
            uint4 a0 = *(const uint4*)&As[buf][((k8s * 8 + m16a) * 32 + lane) * 4];
            uint4 a1 = *(const uint4*)&As[buf][((k8s * 8 + m16a + 1) * 32 + lane) * 4];
            const int br0 = (k8s * 8 + t) * 132 + nwb + g;
            const int br1 = br0 + 4 * 132;
#pragma unroll
            for (int j = 0; j < 8; j++) {
                uint2 b = make_uint2(Bs[buf][br0 + j * 8], Bs[buf][br1 + j * 8]);
                mma_tf32(acc[0][j], a0, b);
                mma_tf32(acc[1][j], a1, b);
            }
        }
    };

    ldg_iter(0);
    sts_iter(0);
    __syncthreads();
#pragma unroll 1
    for (int it = 0; it < 12; it++) {
        if (it + 1 < 12) ldg_iter(it + 1);
        compute(it & 1);
        if (it + 1 < 12) sts_iter((it + 1) & 1);
        __syncthreads();
    }

    const int mw = mt * 128 + (wid & 3) * 32;
#pragma unroll
    for (int f = 0; f < 2; f++) {
        const int m = mw + f * 16 + g;
#pragma unroll
        for (int j = 0; j < 8; j++) {
            float* p = Y + boffY + (size_t)m * HWD + n0 + nwb + j * 8 + 2 * t;
            if (m < Mdim)
                *(float2*)p = make_float2(acc[f][j][0], acc[f][j][1]);
            if (m + 8 < Mdim)
                *(float2*)(p + (size_t)8 * HWD) = make_float2(acc[f][j][2], acc[f][j][3]);
        }
    }
}

// ============================================================
// Depthwise 3x3, pad 1 — register sliding window + warp shuffle halos.
// ============================================================
__global__ __launch_bounds__(256) void dw_conv_kernel(
    const float* __restrict__ in, const float* __restrict__ wts,
    float* __restrict__ out)
{
    const int bc = blockIdx.x;
    const int c = bc % C3;
    const int warp = threadIdx.x >> 5;
    const int lane = threadIdx.x & 31;
    const int y0 = blockIdx.y * 64 + warp * 8;

    float w[9];
#pragma unroll
    for (int i = 0; i < 9; i++) w[i] = __ldg(wts + c * 9 + i);

    const float* ip = in + (size_t)bc * HWD + lane * 4;
    float win[3][6];

    auto loadrow = [&](int gy, float* row6) {
        float4 v = make_float4(0.f, 0.f, 0.f, 0.f);
        if (gy >= 0 && gy < 128) v = *(const float4*)(ip + (size_t)gy * 128);
        float l = __shfl_up_sync(0xffffffffu, v.w, 1);
        float r = __shfl_down_sync(0xffffffffu, v.x, 1);
        if (lane == 0)  l = 0.f;
        if (lane == 31) r = 0.f;
        row6[0] = l; row6[1] = v.x; row6[2] = v.y;
        row6[3] = v.z; row6[4] = v.w; row6[5] = r;
    };

    loadrow(y0 - 1, win[0]);
    loadrow(y0,     win[1]);
    float* op = out + (size_t)bc * HWD + lane * 4;
#pragma unroll
    for (int r = 0; r < 8; r++) {
        loadrow(y0 + 1 + r, win[(r + 2) % 3]);
        const float* tp = win[r % 3];
        const float* mp = win[(r + 1) % 3];
        const float* bp = win[(r + 2) % 3];
        float o[4];
#pragma unroll
        for (int p = 0; p < 4; p++) {
            float s = 0.f;
            s = fmaf(tp[p], w[0], s); s = fmaf(tp[p + 1], w[1], s); s = fmaf(tp[p + 2], w[2], s);
            s = fmaf(mp[p], w[3], s); s = fmaf(mp[p + 1], w[4], s); s = fmaf(mp[p + 2], w[5], s);
            s = fmaf(bp[p], w[6], s); s = fmaf(bp[p + 1], w[7], s); s = fmaf(bp[p + 2], w[8], s);
            o[p] = s;
        }
        *(float4*)(op + (size_t)(y0 + r) * 128) = make_float4(o[0], o[1], o[2], o[3]);
    }
}

// ============================================================
// Gram on tensor cores: only Q@K^T (48x48) per (bh, chunk of 1024 px).
// Norms accumulate for free in registers during the staging loads
// (each thread owns fixed rows r, r+16, r+32), reduced deterministically.
// 6 compute warps: warp = (mrow 0..2) x (nhalf 0..1); each m16 x n24.
// ============================================================
__global__ __launch_bounds__(256) void gram_kernel()
{
    const int chunk = blockIdx.x;
    const int bh = blockIdx.y;
    const int b = bh >> 2, h = bh & 3;
    const float* qb = g_qkv2 + ((size_t)b * C3 + h * CH) * HWD;
    const float* kb = g_qkv2 + ((size_t)b * C3 + CDIM + h * CH) * HWD;
    __shared__ __align__(16) uint32_t Qs[CH][68];
    __shared__ __align__(16) uint32_t Ks[CH][68];
    __shared__ float redq[CH][16];
    __shared__ float redk[CH][16];
    const int tid = threadIdx.x;
    const int lane = tid & 31, wid = tid >> 5;
    const int n0 = chunk * 1024;

    float acc[3][4];
#pragma unroll
    for (int jj = 0; jj < 3; jj++)
#pragma unroll
        for (int e = 0; e < 4; e++) acc[jj][e] = 0.f;
    float nq[3] = {0.f, 0.f, 0.f};
    float nk[3] = {0.f, 0.f, 0.f};

    const int mrow = wid % 3;
    const int nhalf = (wid < 6) ? (wid / 3) : 0;
    const int g = lane >> 2, t = lane & 3;

#pragma unroll 1
    for (int t0 = 0; t0 < 1024; t0 += 64) {
#pragma unroll
        for (int i = 0; i < 3; i++) {
            int idx = tid + i * 256;
            int row = idx >> 4;
            int col = (idx & 15) << 2;
            float4 v = *(const float4*)(qb + (size_t)row * HWD + n0 + t0 + col);
            uint32_t c0 = f2tf32(v.x), c1 = f2tf32(v.y), c2 = f2tf32(v.z), c3 = f2tf32(v.w);
            Qs[row][col + 0] = c0; Qs[row][col + 1] = c1;
            Qs[row][col + 2] = c2; Qs[row][col + 3] = c3;
            float f0 = __uint_as_float(c0), f1 = __uint_as_float(c1);
            float f2 = __uint_as_float(c2), f3 = __uint_as_float(c3);
            nq[i] = fmaf(f0, f0, nq[i]); nq[i] = fmaf(f1, f1, nq[i]);
            nq[i] = fmaf(f2, f2, nq[i]); nq[i] = fmaf(f3, f3, nq[i]);

            float4 u = *(const float4*)(kb + (size_t)row * HWD + n0 + t0 + col);
            uint32_t d0 = f2tf32(u.x), d1 = f2tf32(u.y), d2 = f2tf32(u.z), d3 = f2tf32(u.w);
            Ks[row][col + 0] = d0; Ks[row][col + 1] = d1;
            Ks[row][col + 2] = d2; Ks[row][col + 3] = d3;
            float e0 = __uint_as_float(d0), e1 = __uint_as_float(d1);
            float e2 = __uint_as_float(d2), e3 = __uint_as_float(d3);
            nk[i] = fmaf(e0, e0, nk[i]); nk[i] = fmaf(e1, e1, nk[i]);
            nk[i] = fmaf(e2, e2, nk[i]); nk[i] = fmaf(e3, e3, nk[i]);
        }
        __syncthreads();
        if (wid < 6) {
            const int mr = 16 * mrow + g;
#pragma unroll
            for (int k8 = 0; k8 < 8; k8++) {
                const int k = k8 * 8;
                uint4 a;
                a.x = Qs[mr][k + t];
                a.y = Qs[mr + 8][k + t];
                a.z = Qs[mr][k + t + 4];
                a.w = Qs[mr + 8][k + t + 4];
#pragma unroll
                for (int jj = 0; jj < 3; jj++) {
                    const int nr = 8 * (3 * nhalf + jj) + g;
                    uint2 bf = make_uint2(Ks[nr][k + t], Ks[nr][k + t + 4]);
                    mma_tf32(acc[jj], a, bf);
                }
            }
        }
        __syncthreads();
    }

    // deterministic norm reduction: thread owns rows r0, r0+16, r0+32 / quad col
    const int r0 = tid >> 4, quad = tid & 15;
    redq[r0][quad] = nq[0]; redq[r0 + 16][quad] = nq[1]; redq[r0 + 32][quad] = nq[2];
    redk[r0][quad] = nk[0]; redk[r0 + 16][quad] = nk[1]; redk[r0 + 32][quad] = nk[2];
    __syncthreads();
    if (tid < CH) {
        float s = 0.f;
#pragma unroll
        for (int q = 0; q < 16; q++) s += redq[tid][q];
        g_part_nq[((size_t)bh * NCHUNK + chunk) * CH + tid] = s;
    } else if (tid < 2 * CH) {
        float s = 0.f;
#pragma unroll
        for (int q = 0; q < 16; q++) s += redk[tid - CH][q];
        g_part_nk[((size_t)bh * NCHUNK + chunk) * CH + (tid - CH)] = s;
    }

    if (wid < 6) {
        float* gp = g_part_gram + ((size_t)bh * NCHUNK + chunk) * CH * CH;
        const int m = 16 * mrow + g;
#pragma unroll
        for (int jj = 0; jj < 3; jj++) {
            const int n = 8 * (3 * nhalf + jj) + 2 * t;
            *(float2*)&gp[m * CH + n] = make_float2(acc[jj][0], acc[jj][1]);
            *(float2*)&gp[(m + 8) * CH + n] = make_float2(acc[jj][2], acc[jj][3]);
        }
    }
}

// ============================================================
// Reduce partials -> normalize -> temperature -> softmax
// ============================================================
__global__ __launch_bounds__(256) void attn_kernel(const float* __restrict__ temperature)
{
    const int bh = blockIdx.x;
    const int h = bh & 3;
    __shared__ float S[CH * CH];
    __shared__ float rq[CH];
    __shared__ float rk[CH];
    const int tid = threadIdx.x;

    for (int e = tid; e < CH * CH; e += 256) {
        float s = 0.f;
#pragma unroll
        for (int p = 0; p < NCHUNK; p++)
            s += g_part_gram[((size_t)bh * NCHUNK + p) * CH * CH + e];
        S[e] = s;
    }
    if (tid < CH) {
        float s = 0.f;
#pragma unroll
        for (int p = 0; p < NCHUNK; p++) s += g_part_nq[((size_t)bh * NCHUNK + p) * CH + tid];
        rq[tid] = fmaxf(sqrtf(s), 1e-12f);
    } else if (tid < 2 * CH) {
        float s = 0.f;
#pragma unroll
        for (int p = 0; p < NCHUNK; p++) s += g_part_nk[((size_t)bh * NCHUNK + p) * CH + (tid - CH)];
        rk[tid - CH] = fmaxf(sqrtf(s), 1e-12f);
    }
    __syncthreads();

    if (tid < CH) {
        const float t = temperature[h];
        const float fq = t / rq[tid];
        float row[CH];
        float mx = -1e30f;
#pragma unroll
        for (int d = 0; d < CH; d++) {
            float v = S[tid * CH + d] * fq / rk[d];
            row[d] = v;
            mx = fmaxf(mx, v);
        }
        float sum = 0.f;
#pragma unroll
        for (int d = 0; d < CH; d++) { float e = expf(row[d] - mx); row[d] = e; sum += e; }
        float inv = 1.f / sum;
#pragma unroll
        for (int d = 0; d < CH; d++)
            g_attn[(size_t)bh * CH * CH + tid * CH + d] = row[d] * inv;
    }
}

// ============================================================
// Fold attention into proj: Comb[b][m][h*48+d] = sum_c P[m][h*48+c] A[bh][c][d]
// ============================================================
__global__ __launch_bounds__(192) void combine_kernel(const float* __restrict__ P)
{
    const int bh = blockIdx.x;
    const int b = bh >> 2, h = bh & 3;
    __shared__ float A[CH * CH];
    for (int e = threadIdx.x; e < CH * CH; e += 192)
        A[e] = g_attn[(size_t)bh * CH * CH + e];
    __syncthreads();

    const int m = threadIdx.x;
    float p[CH];
#pragma unroll
    for (int c = 0; c < CH; c++) p[c] = P[(size_t)m * CDIM + h * CH + c];
    float* outp = g_comb + ((size_t)b * CDIM + m) * CDIM + h * CH;
#pragma unroll 4
    for (int d = 0; d < CH; d++) {
        float s = 0.f;
#pragma unroll
        for (int c = 0; c < CH; c++) s = fmaf(p[c], A[c * CH + d], s);
        outp[d] = s;
    }
}

// ============================================================
extern "C" void kernel_launch(void* const* d_in, const int* in_sizes, int n_in,
                              void* d_out, int out_size)
{
    const float* x      = (const float*)d_in[0];
    const float* qkv_w  = (const float*)d_in[1];
    const float* dw_w   = (const float*)d_in[2];
    const float* proj_w = (const float*)d_in[3];
    const float* temp   = (const float*)d_in[4];
    float* out = (float*)d_out;

    float *qkv, *qkv2, *comb;
    uint32_t *apq, *apm;
    cudaGetSymbolAddress((void**)&qkv,  g_qkv);
    cudaGetSymbolAddress((void**)&qkv2, g_qkv2);
    cudaGetSymbolAddress((void**)&comb, g_comb);
    cudaGetSymbolAddress((void**)&apq,  g_apq);
    cudaGetSymbolAddress((void**)&apm,  g_apm);

    dim3 blk(256);
    // 0) permute + tf32-convert qkv weights
    prep_a<<<dim3(120, 1), blk>>>(qkv_w, apq, C3, 0, 0);
    // 1) qkv 1x1 conv (tensor core tf32)
    pw_mma<<<dim3(5, 128, BATCH), blk>>>(apq, 0, x, (size_t)CDIM * HWD, qkv, (size_t)C3 * HWD, C3);
    // 2) depthwise 3x3 (register sliding window)
    dw_conv_kernel<<<dim3(BATCH * C3, 2), blk>>>(qkv, dw_w, qkv2);
    // 3) Q@K^T partials + free norms (tensor cores)
    gram_kernel<<<dim3(NCHUNK, BATCH * HEADS), blk>>>();
    // 4) softmax
    attn_kernel<<<BATCH * HEADS, blk>>>(temp);
    // 5) fold attn into proj weights (per batch)
    combine_kernel<<<BATCH * HEADS, 192>>>(proj_w);
    // 6) permute combined weights
    prep_a<<<dim3(48, BATCH), blk>>>(comb, apm, CDIM, (size_t)CDIM * CDIM, 2 * 24576);
    // 7) fused (proj @ attn) @ v -> d_out
    pw_mma<<<dim3(2, 128, BATCH), blk>>>(apm, 2 * 24576,
                                         qkv2 + (size_t)2 * CDIM * HWD, (size_t)C3 * HWD,
                                         out, (size_t)CDIM * HWD, CDIM);
}

// round 9
// speedup vs baseline: 3.7701x; 1.0606x over previous
#include <cuda_runtime.h>
#include <cuda_fp16.h>
#include <math.h>
#include <stdint.h>

#define BATCH 8
#define CDIM 192
#define C3 576
#define HWD 16384
#define HEADS 4
#define CH 48
#define NCHUNK 16

typedef unsigned long long ull;

// ---- tf32 helpers ----
__device__ __forceinline__ uint32_t f2tf32(float x) {
    uint32_t r;
    asm("cvt.rna.tf32.f32 %0, %1;" : "=r"(r) : "f"(x));
    return r;
}
__device__ __forceinline__ void mma_tf32(float* c, uint4 a, uint2 b) {
    asm volatile(
        "mma.sync.aligned.m16n8k8.row.col.f32.tf32.tf32.f32 "
        "{%0,%1,%2,%3}, {%4,%5,%6,%7}, {%8,%9}, {%0,%1,%2,%3};"
        : "+f"(c[0]), "+f"(c[1]), "+f"(c[2]), "+f"(c[3])
        : "r"(a.x), "r"(a.y), "r"(a.z), "r"(a.w), "r"(b.x), "r"(b.y));
}

// ---- typed 4-element loads / 2-element stores ----
__device__ __forceinline__ float4 load4(const float* p) { return *(const float4*)p; }
__device__ __forceinline__ float4 load4(const __half* p) {
    __half2 h0 = *(const __half2*)p;
    __half2 h1 = *(const __half2*)(p + 2);
    float2 a = __half22float2(h0), b = __half22float2(h1);
    return make_float4(a.x, a.y, b.x, b.y);
}
__device__ __forceinline__ void store2(float* p, float a, float b) {
    *(float2*)p = make_float2(a, b);
}
__device__ __forceinline__ void store2(__half* p, float a, float b) {
    *(__half2*)p = __floats2half2_rn(a, b);
}

// ---- scratch (device globals; no allocations allowed) ----
__device__ __half g_qkv [(size_t)BATCH * C3 * HWD];
__device__ __half g_qkv2[(size_t)BATCH * C3 * HWD];
__device__ float g_part_gram[(size_t)BATCH * HEADS * NCHUNK * CH * CH];
__device__ float g_part_nq  [(size_t)BATCH * HEADS * NCHUNK * CH];
__device__ float g_part_nk  [(size_t)BATCH * HEADS * NCHUNK * CH];
__device__ float g_attn     [(size_t)BATCH * HEADS * CH * CH];
__device__ float g_comb     [(size_t)BATCH * CDIM * CDIM];   // P @ blockdiag(attn)
__device__ uint32_t g_apq[5 * 24576];          // qkv W, fragment-permuted tf32
__device__ uint32_t g_apm[BATCH * 2 * 24576];  // combined proj, per batch

// ============================================================
// Permute W[M,192] (per batch) into mma fragment order + tf32 convert.
// ============================================================
__global__ __launch_bounds__(256) void prep_a(
    const float* __restrict__ W, uint32_t* __restrict__ Ap, int Mdim,
    size_t w_bstride, size_t a_bstride)
{
    const float* Wb = W + blockIdx.y * w_bstride;
    uint32_t* Apb = Ap + blockIdx.y * a_bstride;
    const int idx = blockIdx.x * 256 + threadIdx.x;
    const int lane = idx & 31;
    int rest = idx >> 5;
    const int m16 = rest & 7; rest >>= 3;
    const int k8 = rest % 24;
    const int mt = rest / 24;
    const int g = lane >> 2, t = lane & 3;
    const int row = mt * 128 + m16 * 16 + g;
    const int k = k8 * 8 + t;
    float v0 = 0.f, v1 = 0.f, v2 = 0.f, v3 = 0.f;
    if (row < Mdim)     { v0 = Wb[(size_t)row * CDIM + k];       v2 = Wb[(size_t)row * CDIM + k + 4]; }
    if (row + 8 < Mdim) { v1 = Wb[(size_t)(row + 8) * CDIM + k]; v3 = Wb[(size_t)(row + 8) * CDIM + k + 4]; }
    uint4 o;
    o.x = f2tf32(v0); o.y = f2tf32(v1); o.z = f2tf32(v2); o.w = f2tf32(v3);
    *(uint4*)(Apb + (size_t)idx * 4) = o;
}

// ============================================================
// Pointwise GEMM via mma.sync tf32: Y[b,m,n] = sum_k A[(b),m,k] X[b,k,n]
// Templated on input/output element type (float or __half).
// ============================================================
template <typename InT, typename OutT>
__global__ __launch_bounds__(256) void pw_mma(
    const uint32_t* __restrict__ Ap, size_t a_bstride,
    const InT* __restrict__ X, size_t x_bstride,
    OutT* __restrict__ Y, size_t y_bstride, int Mdim)
{
    __shared__ __align__(16) uint32_t As[2][2048];
    __shared__ __align__(16) uint32_t Bs[2][16 * 132];
    const int tid = threadIdx.x;
    const int lane = tid & 31, wid = tid >> 5;
    const int mt = blockIdx.x;
    const int n0 = blockIdx.y * 128;
    const size_t boffX = (size_t)blockIdx.z * x_bstride;
    const size_t boffY = (size_t)blockIdx.z * y_bstride;

    const uint32_t* apg = Ap + (size_t)blockIdx.z * a_bstride + (size_t)mt * 24576;
    const int nq = tid & 31;
    const int bk0 = tid >> 5;

    uint4 a_r0, a_r1;
    float4 b_r0, b_r1;

    auto ldg_iter = [&](int it) {
        const uint32_t* ap = apg + it * 2048;
        a_r0 = *(const uint4*)(ap + (size_t)tid * 4);
        a_r1 = *(const uint4*)(ap + (size_t)(tid + 256) * 4);
        const InT* xb = X + boffX + (size_t)it * 16 * HWD + n0 + nq * 4;
        b_r0 = load4(xb + (size_t)bk0 * HWD);
        b_r1 = load4(xb + (size_t)(bk0 + 8) * HWD);
    };
    auto sts_iter = [&](int buf) {
        *(uint4*)&As[buf][tid * 4] = a_r0;
        *(uint4*)&As[buf][(tid + 256) * 4] = a_r1;
        uint32_t* r0 = &Bs[buf][bk0 * 132 + nq * 4];
        r0[0] = f2tf32(b_r0.x); r0[1] = f2tf32(b_r0.y);
        r0[2] = f2tf32(b_r0.z); r0[3] = f2tf32(b_r0.w);
        uint32_t* r1 = &Bs[buf][(bk0 + 8) * 132 + nq * 4];
        r1[0] = f2tf32(b_r1.x); r1[1] = f2tf32(b_r1.y);
        r1[2] = f2tf32(b_r1.z); r1[3] = f2tf32(b_r1.w);
    };

    float acc[2][8][4];
#pragma unroll
    for (int f = 0; f < 2; f++)
#pragma unroll
        for (int j = 0; j < 8; j++)
#pragma unroll
            for (int e = 0; e < 4; e++) acc[f][j][e] = 0.f;

    const int m16a = (wid & 3) * 2;
    const int t = lane & 3;
    const int g = lane >> 2;
    const int nwb = (wid >> 2) * 64;

    auto compute = [&](int buf) {
#pragma unroll
        for (int k8s = 0; k8s < 2; k8s++) {
            uint4 a0 = *(const uint4*)&As[buf][((k8s * 8 + m16a) * 32 + lane) * 4];
            uint4 a1 = *(const uint4*)&As[buf][((k8s * 8 + m16a + 1) * 32 + lane) * 4];
            const int br0 = (k8s * 8 + t) * 132 + nwb + g;
            const int br1 = br0 + 4 * 132;
#pragma unroll
            for (int j = 0; j < 8; j++) {
                uint2 b = make_uint2(Bs[buf][br0 + j * 8], Bs[buf][br1 + j * 8]);
                mma_tf32(acc[0][j], a0, b);
                mma_tf32(acc[1][j], a1, b);
            }
        }
    };

    ldg_iter(0);
    sts_iter(0);
    __syncthreads();
#pragma unroll 1
    for (int it = 0; it < 12; it++) {
        if (it + 1 < 12) ldg_iter(it + 1);
        compute(it & 1);
        if (it + 1 < 12) sts_iter((it + 1) & 1);
        __syncthreads();
    }

    const int mw = mt * 128 + (wid & 3) * 32;
#pragma unroll
    for (int f = 0; f < 2; f++) {
        const int m = mw + f * 16 + g;
#pragma unroll
        for (int j = 0; j < 8; j++) {
            OutT* p = Y + boffY + (size_t)m * HWD + n0 + nwb + j * 8 + 2 * t;
            if (m < Mdim)
                store2(p, acc[f][j][0], acc[f][j][1]);
            if (m + 8 < Mdim)
                store2(p + (size_t)8 * HWD, acc[f][j][2], acc[f][j][3]);
        }
    }
}

// ============================================================
// Depthwise 3x3, pad 1 — register sliding window + warp shuffle halos.
// fp16 in/out, fp32 math.
// ============================================================
__global__ __launch_bounds__(256) void dw_conv_kernel(
    const __half* __restrict__ in, const float* __restrict__ wts,
    __half* __restrict__ out)
{
    const int bc = blockIdx.x;
    const int c = bc % C3;
    const int warp = threadIdx.x >> 5;
    const int lane = threadIdx.x & 31;
    const int y0 = blockIdx.y * 64 + warp * 8;

    float w[9];
#pragma unroll
    for (int i = 0; i < 9; i++) w[i] = __ldg(wts + c * 9 + i);

    const __half* ip = in + (size_t)bc * HWD + lane * 4;
    float win[3][6];

    auto loadrow = [&](int gy, float* row6) {
        float4 v = make_float4(0.f, 0.f, 0.f, 0.f);
        if (gy >= 0 && gy < 128) v = load4(ip + (size_t)gy * 128);
        float l = __shfl_up_sync(0xffffffffu, v.w, 1);
        float r = __shfl_down_sync(0xffffffffu, v.x, 1);
        if (lane == 0)  l = 0.f;
        if (lane == 31) r = 0.f;
        row6[0] = l; row6[1] = v.x; row6[2] = v.y;
        row6[3] = v.z; row6[4] = v.w; row6[5] = r;
    };

    loadrow(y0 - 1, win[0]);
    loadrow(y0,     win[1]);
    __half* op = out + (size_t)bc * HWD + lane * 4;
#pragma unroll
    for (int r = 0; r < 8; r++) {
        loadrow(y0 + 1 + r, win[(r + 2) % 3]);
        const float* tp = win[r % 3];
        const float* mp = win[(r + 1) % 3];
        const float* bp = win[(r + 2) % 3];
        float o[4];
#pragma unroll
        for (int p = 0; p < 4; p++) {
            float s = 0.f;
            s = fmaf(tp[p], w[0], s); s = fmaf(tp[p + 1], w[1], s); s = fmaf(tp[p + 2], w[2], s);
            s = fmaf(mp[p], w[3], s); s = fmaf(mp[p + 1], w[4], s); s = fmaf(mp[p + 2], w[5], s);
            s = fmaf(bp[p], w[6], s); s = fmaf(bp[p + 1], w[7], s); s = fmaf(bp[p + 2], w[8], s);
            o[p] = s;
        }
        __half2 h0 = __floats2half2_rn(o[0], o[1]);
        __half2 h1 = __floats2half2_rn(o[2], o[3]);
        __half2* dst = (__half2*)(op + (size_t)(y0 + r) * 128);
        dst[0] = h0; dst[1] = h1;
    }
}

// ============================================================
// Gram on tensor cores: only Q@K^T (48x48) per (bh, chunk of 1024 px).
// fp16 inputs (tf32 conversion exact). Norms ride along in registers.
// ============================================================
__global__ __launch_bounds__(256) void gram_kernel()
{
    const int chunk = blockIdx.x;
    const int bh = blockIdx.y;
    const int b = bh >> 2, h = bh & 3;
    const __half* qb = g_qkv2 + ((size_t)b * C3 + h * CH) * HWD;
    const __half* kb = g_qkv2 + ((size_t)b * C3 + CDIM + h * CH) * HWD;
    __shared__ __align__(16) uint32_t Qs[CH][68];
    __shared__ __align__(16) uint32_t Ks[CH][68];
    __shared__ float redq[CH][16];
    __shared__ float redk[CH][16];
    const int tid = threadIdx.x;
    const int lane = tid & 31, wid = tid >> 5;
    const int n0 = chunk * 1024;

    float acc[3][4];
#pragma unroll
    for (int jj = 0; jj < 3; jj++)
#pragma unroll
        for (int e = 0; e < 4; e++) acc[jj][e] = 0.f;
    float nq[3] = {0.f, 0.f, 0.f};
    float nk[3] = {0.f, 0.f, 0.f};

    const int mrow = wid % 3;
    const int nhalf = (wid < 6) ? (wid / 3) : 0;
    const int g = lane >> 2, t = lane & 3;

#pragma unroll 1
    for (int t0 = 0; t0 < 1024; t0 += 64) {
#pragma unroll
        for (int i = 0; i < 3; i++) {
            int idx = tid + i * 256;
            int row = idx >> 4;
            int col = (idx & 15) << 2;
            float4 v = load4(qb + (size_t)row * HWD + n0 + t0 + col);
            Qs[row][col + 0] = __float_as_uint(v.x); Qs[row][col + 1] = __float_as_uint(v.y);
            Qs[row][col + 2] = __float_as_uint(v.z); Qs[row][col + 3] = __float_as_uint(v.w);
            nq[i] = fmaf(v.x, v.x, nq[i]); nq[i] = fmaf(v.y, v.y, nq[i]);
            nq[i] = fmaf(v.z, v.z, nq[i]); nq[i] = fmaf(v.w, v.w, nq[i]);

            float4 u = load4(kb + (size_t)row * HWD + n0 + t0 + col);
            Ks[row][col + 0] = __float_as_uint(u.x); Ks[row][col + 1] = __float_as_uint(u.y);
            Ks[row][col + 2] = __float_as_uint(u.z); Ks[row][col + 3] = __float_as_uint(u.w);
            nk[i] = fmaf(u.x, u.x, nk[i]); nk[i] = fmaf(u.y, u.y, nk[i]);
            nk[i] = fmaf(u.z, u.z, nk[i]); nk[i] = fmaf(u.w, u.w, nk[i]);
        }
        __syncthreads();
        if (wid < 6) {
            const int mr = 16 * mrow + g;
#pragma unroll
            for (int k8 = 0; k8 < 8; k8++) {
                const int k = k8 * 8;
                uint4 a;
                a.x = Qs[mr][k + t];
                a.y = Qs[mr + 8][k + t];
                a.z = Qs[mr][k + t + 4];
                a.w = Qs[mr + 8][k + t + 4];
#pragma unroll
                for (int jj = 0; jj < 3; jj++) {
                    const int nr = 8 * (3 * nhalf + jj) + g;
                    uint2 bf = make_uint2(Ks[nr][k + t], Ks[nr][k + t + 4]);
                    mma_tf32(acc[jj], a, bf);
                }
            }
        }
        __syncthreads();
    }

    const int r0 = tid >> 4, quad = tid & 15;
    redq[r0][quad] = nq[0]; redq[r0 + 16][quad] = nq[1]; redq[r0 + 32][quad] = nq[2];
    redk[r0][quad] = nk[0]; redk[r0 + 16][quad] = nk[1]; redk[r0 + 32][quad] = nk[2];
    __syncthreads();
    if (tid < CH) {
        float s = 0.f;
#pragma unroll
        for (int q = 0; q < 16; q++) s += redq[tid][q];
        g_part_nq[((size_t)bh * NCHUNK + chunk) * CH + tid] = s;
    } else if (tid < 2 * CH) {
        float s = 0.f;
#pragma unroll
        for (int q = 0; q < 16; q++) s += redk[tid - CH][q];
        g_part_nk[((size_t)bh * NCHUNK + chunk) * CH + (tid - CH)] = s;
    }

    if (wid < 6) {
        float* gp = g_part_gram + ((size_t)bh * NCHUNK + chunk) * CH * CH;
        const int m = 16 * mrow + g;
#pragma unroll
        for (int jj = 0; jj < 3; jj++) {
            const int n = 8 * (3 * nhalf + jj) + 2 * t;
            *(float2*)&gp[m * CH + n] = make_float2(acc[jj][0], acc[jj][1]);
            *(float2*)&gp[(m + 8) * CH + n] = make_float2(acc[jj][2], acc[jj][3]);
        }
    }
}

// ============================================================
// Reduce partials -> normalize -> temperature -> softmax
// ============================================================
__global__ __launch_bounds__(256) void attn_kernel(const float* __restrict__ temperature)
{
    const int bh = blockIdx.x;
    const int h = bh & 3;
    __shared__ float S[CH * CH];
    __shared__ float rq[CH];
    __shared__ float rk[CH];
    const int tid = threadIdx.x;

    for (int e = tid; e < CH * CH; e += 256) {
        float s = 0.f;
#pragma unroll
        for (int p = 0; p < NCHUNK; p++)
            s += g_part_gram[((size_t)bh * NCHUNK + p) * CH * CH + e];
        S[e] = s;
    }
    if (tid < CH) {
        float s = 0.f;
#pragma unroll
        for (int p = 0; p < NCHUNK; p++) s += g_part_nq[((size_t)bh * NCHUNK + p) * CH + tid];
        rq[tid] = fmaxf(sqrtf(s), 1e-12f);
    } else if (tid < 2 * CH) {
        float s = 0.f;
#pragma unroll
        for (int p = 0; p < NCHUNK; p++) s += g_part_nk[((size_t)bh * NCHUNK + p) * CH + (tid - CH)];
        rk[tid - CH] = fmaxf(sqrtf(s), 1e-12f);
    }
    __syncthreads();

    if (tid < CH) {
        const float t = temperature[h];
        const float fq = t / rq[tid];
        float row[CH];
        float mx = -1e30f;
#pragma unroll
        for (int d = 0; d < CH; d++) {
            float v = S[tid * CH + d] * fq / rk[d];
            row[d] = v;
            mx = fmaxf(mx, v);
        }
        float sum = 0.f;
#pragma unroll
        for (int d = 0; d < CH; d++) { float e = expf(row[d] - mx); row[d] = e; sum += e; }
        float inv = 1.f / sum;
#pragma unroll
        for (int d = 0; d < CH; d++)
            g_attn[(size_t)bh * CH * CH + tid * CH + d] = row[d] * inv;
    }
}

// ============================================================
// Fold attention into proj: Comb[b][m][h*48+d] = sum_c P[m][h*48+c] A[bh][c][d]
// ============================================================
__global__ __launch_bounds__(192) void combine_kernel(const float* __restrict__ P)
{
    const int bh = blockIdx.x;
    const int b = bh >> 2, h = bh & 3;
    __shared__ float A[CH * CH];
    for (int e = threadIdx.x; e < CH * CH; e += 192)
        A[e] = g_attn[(size_t)bh * CH * CH + e];
    __syncthreads();

    const int m = threadIdx.x;
    float p[CH];
#pragma unroll
    for (int c = 0; c < CH; c++) p[c] = P[(size_t)m * CDIM + h * CH + c];
    float* outp = g_comb + ((size_t)b * CDIM + m) * CDIM + h * CH;
#pragma unroll 4
    for (int d = 0; d < CH; d++) {
        float s = 0.f;
#pragma unroll
        for (int c = 0; c < CH; c++) s = fmaf(p[c], A[c * CH + d], s);
        outp[d] = s;
    }
}

// ============================================================
extern "C" void kernel_launch(void* const* d_in, const int* in_sizes, int n_in,
                              void* d_out, int out_size)
{
    const float* x      = (const float*)d_in[0];
    const float* qkv_w  = (const float*)d_in[1];
    const float* dw_w   = (const float*)d_in[2];
    const float* proj_w = (const float*)d_in[3];
    const float* temp   = (const float*)d_in[4];
    float* out = (float*)d_out;

    __half *qkv, *qkv2;
    float *comb;
    uint32_t *apq, *apm;
    cudaGetSymbolAddress((void**)&qkv,  g_qkv);
    cudaGetSymbolAddress((void**)&qkv2, g_qkv2);
    cudaGetSymbolAddress((void**)&comb, g_comb);
    cudaGetSymbolAddress((void**)&apq,  g_apq);
    cudaGetSymbolAddress((void**)&apm,  g_apm);

    dim3 blk(256);
    // 0) permute + tf32-convert qkv weights
    prep_a<<<dim3(120, 1), blk>>>(qkv_w, apq, C3, 0, 0);
    // 1) qkv 1x1 conv (tensor core tf32), fp16 output
    pw_mma<float, __half><<<dim3(5, 128, BATCH), blk>>>(
        apq, 0, x, (size_t)CDIM * HWD, qkv, (size_t)C3 * HWD, C3);
    // 2) depthwise 3x3 (register sliding window), fp16 in/out
    dw_conv_kernel<<<dim3(BATCH * C3, 2), blk>>>(qkv, dw_w, qkv2);
    // 3) Q@K^T partials + free norms (tensor cores), fp16 input
    gram_kernel<<<dim3(NCHUNK, BATCH * HEADS), blk>>>();
    // 4) softmax
    attn_kernel<<<BATCH * HEADS, blk>>>(temp);
    // 5) fold attn into proj weights (per batch)
    combine_kernel<<<BATCH * HEADS, 192>>>(proj_w);
    // 6) permute combined weights
    prep_a<<<dim3(48, BATCH), blk>>>(comb, apm, CDIM, (size_t)CDIM * CDIM, 2 * 24576);
    // 7) fused (proj @ attn) @ v -> d_out (fp16 V input, fp32 output)
    pw_mma<__half, float><<<dim3(2, 128, BATCH), blk>>>(
        apm, 2 * 24576, qkv2 + (size_t)2 * CDIM * HWD, (size_t)C3 * HWD,
        out, (size_t)CDIM * HWD, CDIM);
}

// round 10
// speedup vs baseline: 5.0247x; 1.3328x over previous
#include <cuda_runtime.h>
#include <cuda_fp16.h>
#include <math.h>
#include <stdint.h>

#define BATCH 8
#define CDIM 192
#define C3 576
#define HWD 16384
#define HEADS 4
#define CH 48
#define NCHUNK 16

typedef unsigned long long ull;

// ---- fp16 mma m16n8k16, fp32 accumulate ----
__device__ __forceinline__ void mma_f16(float* c, uint4 a, uint2 b) {
    asm volatile(
        "mma.sync.aligned.m16n8k16.row.col.f32.f16.f16.f32 "
        "{%0,%1,%2,%3}, {%4,%5,%6,%7}, {%8,%9}, {%0,%1,%2,%3};"
        : "+f"(c[0]), "+f"(c[1]), "+f"(c[2]), "+f"(c[3])
        : "r"(a.x), "r"(a.y), "r"(a.z), "r"(a.w), "r"(b.x), "r"(b.y));
}
__device__ __forceinline__ uint32_t h2pack(float a, float b) {
    __half2 h = __floats2half2_rn(a, b);
    return *(uint32_t*)&h;
}

// ---- typed 4-element loads / 2-element stores ----
__device__ __forceinline__ float4 load4(const float* p) { return *(const float4*)p; }
__device__ __forceinline__ float4 load4(const __half* p) {
    __half2 h0 = *(const __half2*)p;
    __half2 h1 = *(const __half2*)(p + 2);
    float2 a = __half22float2(h0), b = __half22float2(h1);
    return make_float4(a.x, a.y, b.x, b.y);
}
__device__ __forceinline__ void store2(float* p, float a, float b) {
    *(float2*)p = make_float2(a, b);
}
__device__ __forceinline__ void store2(__half* p, float a, float b) {
    *(__half2*)p = __floats2half2_rn(a, b);
}

// ---- scratch (device globals; no allocations allowed) ----
__device__ __half g_qkv [(size_t)BATCH * C3 * HWD];
__device__ __half g_qkv2[(size_t)BATCH * C3 * HWD];
__device__ float g_part_gram[(size_t)BATCH * HEADS * NCHUNK * CH * CH];
__device__ float g_part_nq  [(size_t)BATCH * HEADS * NCHUNK * CH];
__device__ float g_part_nk  [(size_t)BATCH * HEADS * NCHUNK * CH];
__device__ float g_attn     [(size_t)BATCH * HEADS * CH * CH];
__device__ float g_comb     [(size_t)BATCH * CDIM * CDIM];   // P @ blockdiag(attn)
__device__ uint32_t g_apq[5 * 12288];          // qkv W, fp16 fragment-permuted
__device__ uint32_t g_apm[BATCH * 2 * 12288];  // combined proj, per batch

// ============================================================
// Permute W[M,192] into fp16 m16n8k16 fragment order.
// Layout: [mt][k16(12)][m16(8)][lane(32)][reg(4)] as half2-packed uint32.
// reg0={W[r][k],W[r][k+1]}, reg1=rows+8, reg2=cols+8, reg3=both (k=16*k16+2t).
// ============================================================
__global__ __launch_bounds__(256) void prep_a(
    const float* __restrict__ W, uint32_t* __restrict__ Ap, int Mdim,
    size_t w_bstride, size_t a_bstride)
{
    const float* Wb = W + blockIdx.y * w_bstride;
    uint32_t* Apb = Ap + blockIdx.y * a_bstride;
    const int idx = blockIdx.x * 256 + threadIdx.x;
    const int lane = idx & 31;
    int rest = idx >> 5;
    const int m16 = rest & 7; rest >>= 3;
    const int k16 = rest % 12;
    const int mt = rest / 12;
    const int g = lane >> 2, t = lane & 3;
    const int row = mt * 128 + m16 * 16 + g;
    const int k = k16 * 16 + 2 * t;
    float a00 = 0.f, a01 = 0.f, a10 = 0.f, a11 = 0.f;
    float a20 = 0.f, a21 = 0.f, a30 = 0.f, a31 = 0.f;
    if (row < Mdim) {
        const float* wr = Wb + (size_t)row * CDIM + k;
        a00 = wr[0]; a01 = wr[1]; a20 = wr[8]; a21 = wr[9];
    }
    if (row + 8 < Mdim) {
        const float* wr = Wb + (size_t)(row + 8) * CDIM + k;
        a10 = wr[0]; a11 = wr[1]; a30 = wr[8]; a31 = wr[9];
    }
    uint4 o;
    o.x = h2pack(a00, a01); o.y = h2pack(a10, a11);
    o.z = h2pack(a20, a21); o.w = h2pack(a30, a31);
    *(uint4*)(Apb + (size_t)idx * 4) = o;
}

// ============================================================
// Pointwise GEMM via mma.sync fp16: Y[b,m,n] = sum_k A[(b),m,k] X[b,k,n]
// 128(M) x 128(N) block, BK=16 (one k16 step/iter), double buffered.
// ============================================================
template <typename InT, typename OutT>
__global__ __launch_bounds__(256) void pw_mma(
    const uint32_t* __restrict__ Ap, size_t a_bstride,
    const InT* __restrict__ X, size_t x_bstride,
    OutT* __restrict__ Y, size_t y_bstride, int Mdim)
{
    __shared__ __align__(16) uint32_t As[2][1024];     // [m16][lane][reg]
    __shared__ __align__(16) uint32_t Bs16[2][8 * 136]; // [k2][n + pad8] half2
    const int tid = threadIdx.x;
    const int lane = tid & 31, wid = tid >> 5;
    const int mt = blockIdx.x;
    const int n0 = blockIdx.y * 128;
    const size_t boffX = (size_t)blockIdx.z * x_bstride;
    const size_t boffY = (size_t)blockIdx.z * y_bstride;

    const uint32_t* apg = Ap + (size_t)blockIdx.z * a_bstride + (size_t)mt * 12288;
    const int nq = tid & 31;
    const int bk0 = tid >> 5;           // 0..7 -> k rows 2bk0, 2bk0+1

    uint4 a_r;
    float4 b_r0, b_r1;

    auto ldg_iter = [&](int it) {
        a_r = *(const uint4*)(apg + (size_t)it * 1024 + (size_t)tid * 4);
        const InT* xb = X + boffX + (size_t)(it * 16 + 2 * bk0) * HWD + n0 + nq * 4;
        b_r0 = load4(xb);
        b_r1 = load4(xb + HWD);
    };
    auto sts_iter = [&](int buf) {
        *(uint4*)&As[buf][tid * 4] = a_r;
        uint32_t* r = &Bs16[buf][bk0 * 136 + nq * 4];
        r[0] = h2pack(b_r0.x, b_r1.x);
        r[1] = h2pack(b_r0.y, b_r1.y);
        r[2] = h2pack(b_r0.z, b_r1.z);
        r[3] = h2pack(b_r0.w, b_r1.w);
    };

    float acc[2][8][4];
#pragma unroll
    for (int f = 0; f < 2; f++)
#pragma unroll
        for (int j = 0; j < 8; j++)
#pragma unroll
            for (int e = 0; e < 4; e++) acc[f][j][e] = 0.f;

    const int m16a = (wid & 3) * 2;
    const int t = lane & 3;
    const int g = lane >> 2;
    const int nwb = (wid >> 2) * 64;

    auto compute = [&](int buf) {
        uint4 A0 = *(const uint4*)&As[buf][(m16a * 32 + lane) * 4];
        uint4 A1 = *(const uint4*)&As[buf][((m16a + 1) * 32 + lane) * 4];
        const int br0 = t * 136 + nwb + g;
        const int br1 = (t + 4) * 136 + nwb + g;
#pragma unroll
        for (int j = 0; j < 8; j++) {
            uint2 b = make_uint2(Bs16[buf][br0 + j * 8], Bs16[buf][br1 + j * 8]);
            mma_f16(acc[0][j], A0, b);
            mma_f16(acc[1][j], A1, b);
        }
    };

    ldg_iter(0);
    sts_iter(0);
    __syncthreads();
#pragma unroll 1
    for (int it = 0; it < 12; it++) {
        if (it + 1 < 12) ldg_iter(it + 1);
        compute(it & 1);
        if (it + 1 < 12) sts_iter((it + 1) & 1);
        __syncthreads();
    }

    const int mw = mt * 128 + (wid & 3) * 32;
#pragma unroll
    for (int f = 0; f < 2; f++) {
        const int m = mw + f * 16 + g;
#pragma unroll
        for (int j = 0; j < 8; j++) {
            OutT* p = Y + boffY + (size_t)m * HWD + n0 + nwb + j * 8 + 2 * t;
            if (m < Mdim)
                store2(p, acc[f][j][0], acc[f][j][1]);
            if (m + 8 < Mdim)
                store2(p + (size_t)8 * HWD, acc[f][j][2], acc[f][j][3]);
        }
    }
}

// ============================================================
// Depthwise 3x3, pad 1 — register sliding window + warp shuffle halos.
// ============================================================
__global__ __launch_bounds__(256) void dw_conv_kernel(
    const __half* __restrict__ in, const float* __restrict__ wts,
    __half* __restrict__ out)
{
    const int bc = blockIdx.x;
    const int c = bc % C3;
    const int warp = threadIdx.x >> 5;
    const int lane = threadIdx.x & 31;
    const int y0 = blockIdx.y * 64 + warp * 8;

    float w[9];
#pragma unroll
    for (int i = 0; i < 9; i++) w[i] = __ldg(wts + c * 9 + i);

    const __half* ip = in + (size_t)bc * HWD + lane * 4;
    float win[3][6];

    auto loadrow = [&](int gy, float* row6) {
        float4 v = make_float4(0.f, 0.f, 0.f, 0.f);
        if (gy >= 0 && gy < 128) v = load4(ip + (size_t)gy * 128);
        float l = __shfl_up_sync(0xffffffffu, v.w, 1);
        float r = __shfl_down_sync(0xffffffffu, v.x, 1);
        if (lane == 0)  l = 0.f;
        if (lane == 31) r = 0.f;
        row6[0] = l; row6[1] = v.x; row6[2] = v.y;
        row6[3] = v.z; row6[4] = v.w; row6[5] = r;
    };

    loadrow(y0 - 1, win[0]);
    loadrow(y0,     win[1]);
    __half* op = out + (size_t)bc * HWD + lane * 4;
#pragma unroll
    for (int r = 0; r < 8; r++) {
        loadrow(y0 + 1 + r, win[(r + 2) % 3]);
        const float* tp = win[r % 3];
        const float* mp = win[(r + 1) % 3];
        const float* bp = win[(r + 2) % 3];
        float o[4];
#pragma unroll
        for (int p = 0; p < 4; p++) {
            float s = 0.f;
            s = fmaf(tp[p], w[0], s); s = fmaf(tp[p + 1], w[1], s); s = fmaf(tp[p + 2], w[2], s);
            s = fmaf(mp[p], w[3], s); s = fmaf(mp[p + 1], w[4], s); s = fmaf(mp[p + 2], w[5], s);
            s = fmaf(bp[p], w[6], s); s = fmaf(bp[p + 1], w[7], s); s = fmaf(bp[p + 2], w[8], s);
            o[p] = s;
        }
        __half2 h0 = __floats2half2_rn(o[0], o[1]);
        __half2 h1 = __floats2half2_rn(o[2], o[3]);
        __half2* dst = (__half2*)(op + (size_t)(y0 + r) * 128);
        dst[0] = h0; dst[1] = h1;
    }
}

// ============================================================
// Gram on fp16 tensor cores: Q@K^T (48x48) per (bh, 1024-px chunk).
// Pixels packed as half2 pairs along k; norms ride along in fp32 regs.
// ============================================================
__global__ __launch_bounds__(256) void gram_kernel()
{
    const int chunk = blockIdx.x;
    const int bh = blockIdx.y;
    const int b = bh >> 2, h = bh & 3;
    const __half* qb = g_qkv2 + ((size_t)b * C3 + h * CH) * HWD;
    const __half* kb = g_qkv2 + ((size_t)b * C3 + CDIM + h * CH) * HWD;
    __shared__ __align__(16) uint32_t Qs[CH][36];   // [row][px/2 + pad]
    __shared__ __align__(16) uint32_t Ks[CH][36];
    __shared__ float redq[CH][16];
    __shared__ float redk[CH][16];
    const int tid = threadIdx.x;
    const int lane = tid & 31, wid = tid >> 5;
    const int n0 = chunk * 1024;

    float acc[3][4];
#pragma unroll
    for (int jj = 0; jj < 3; jj++)
#pragma unroll
        for (int e = 0; e < 4; e++) acc[jj][e] = 0.f;
    float nq[3] = {0.f, 0.f, 0.f};
    float nk[3] = {0.f, 0.f, 0.f};

    const int mrow = wid % 3;
    const int nhalf = (wid < 6) ? (wid / 3) : 0;
    const int g = lane >> 2, t = lane & 3;

#pragma unroll 1
    for (int t0 = 0; t0 < 1024; t0 += 64) {
#pragma unroll
        for (int i = 0; i < 3; i++) {
            int idx = tid + i * 256;
            int row = idx >> 4;
            int colq = idx & 15;          // float4 group: pixels 4*colq..+3
            float4 v = load4(qb + (size_t)row * HWD + n0 + t0 + colq * 4);
            Qs[row][colq * 2 + 0] = h2pack(v.x, v.y);
            Qs[row][colq * 2 + 1] = h2pack(v.z, v.w);
            nq[i] = fmaf(v.x, v.x, nq[i]); nq[i] = fmaf(v.y, v.y, nq[i]);
            nq[i] = fmaf(v.z, v.z, nq[i]); nq[i] = fmaf(v.w, v.w, nq[i]);

            float4 u = load4(kb + (size_t)row * HWD + n0 + t0 + colq * 4);
            Ks[row][colq * 2 + 0] = h2pack(u.x, u.y);
            Ks[row][colq * 2 + 1] = h2pack(u.z, u.w);
            nk[i] = fmaf(u.x, u.x, nk[i]); nk[i] = fmaf(u.y, u.y, nk[i]);
            nk[i] = fmaf(u.z, u.z, nk[i]); nk[i] = fmaf(u.w, u.w, nk[i]);
        }
        __syncthreads();
        if (wid < 6) {
            const int mr = 16 * mrow + g;
#pragma unroll
            for (int s = 0; s < 4; s++) {       // 4 k16 steps per 64 px
                const int base = s * 8;
                uint4 a;
                a.x = Qs[mr][base + t];
                a.y = Qs[mr + 8][base + t];
                a.z = Qs[mr][base + t + 4];
                a.w = Qs[mr + 8][base + t + 4];
#pragma unroll
                for (int jj = 0; jj < 3; jj++) {
                    const int nr = 8 * (3 * nhalf + jj) + g;
                    uint2 bf = make_uint2(Ks[nr][base + t], Ks[nr][base + t + 4]);
                    mma_f16(acc[jj], a, bf);
                }
            }
        }
        __syncthreads();
    }

    const int r0 = tid >> 4, quad = tid & 15;
    redq[r0][quad] = nq[0]; redq[r0 + 16][quad] = nq[1]; redq[r0 + 32][quad] = nq[2];
    redk[r0][quad] = nk[0]; redk[r0 + 16][quad] = nk[1]; redk[r0 + 32][quad] = nk[2];
    __syncthreads();
    if (tid < CH) {
        float s = 0.f;
#pragma unroll
        for (int q = 0; q < 16; q++) s += redq[tid][q];
        g_part_nq[((size_t)bh * NCHUNK + chunk) * CH + tid] = s;
    } else if (tid < 2 * CH) {
        float s = 0.f;
#pragma unroll
        for (int q = 0; q < 16; q++) s += redk[tid - CH][q];
        g_part_nk[((size_t)bh * NCHUNK + chunk) * CH + (tid - CH)] = s;
    }

    if (wid < 6) {
        float* gp = g_part_gram + ((size_t)bh * NCHUNK + chunk) * CH * CH;
        const int m = 16 * mrow + g;
#pragma unroll
        for (int jj = 0; jj < 3; jj++) {
            const int n = 8 * (3 * nhalf + jj) + 2 * t;
            *(float2*)&gp[m * CH + n] = make_float2(acc[jj][0], acc[jj][1]);
            *(float2*)&gp[(m + 8) * CH + n] = make_float2(acc[jj][2], acc[jj][3]);
        }
    }
}

// ============================================================
// Reduce partials -> normalize -> temperature -> softmax
// ============================================================
__global__ __launch_bounds__(256) void attn_kernel(const float* __restrict__ temperature)
{
    const int bh = blockIdx.x;
    const int h = bh & 3;
    __shared__ float S[CH * CH];
    __shared__ float rq[CH];
    __shared__ float rk[CH];
    const int tid = threadIdx.x;

    for (int e = tid; e < CH * CH; e += 256) {
        float s = 0.f;
#pragma unroll
        for (int p = 0; p < NCHUNK; p++)
            s += g_part_gram[((size_t)bh * NCHUNK + p) * CH * CH + e];
        S[e] = s;
    }
    if (tid < CH) {
        float s = 0.f;
#pragma unroll
        for (int p = 0; p < NCHUNK; p++) s += g_part_nq[((size_t)bh * NCHUNK + p) * CH + tid];
        rq[tid] = fmaxf(sqrtf(s), 1e-12f);
    } else if (tid < 2 * CH) {
        float s = 0.f;
#pragma unroll
        for (int p = 0; p < NCHUNK; p++) s += g_part_nk[((size_t)bh * NCHUNK + p) * CH + (tid - CH)];
        rk[tid - CH] = fmaxf(sqrtf(s), 1e-12f);
    }
    __syncthreads();

    if (tid < CH) {
        const float t = temperature[h];
        const float fq = t / rq[tid];
        float row[CH];
        float mx = -1e30f;
#pragma unroll
        for (int d = 0; d < CH; d++) {
            float v = S[tid * CH + d] * fq / rk[d];
            row[d] = v;
            mx = fmaxf(mx, v);
        }
        float sum = 0.f;
#pragma unroll
        for (int d = 0; d < CH; d++) { float e = expf(row[d] - mx); row[d] = e; sum += e; }
        float inv = 1.f / sum;
#pragma unroll
        for (int d = 0; d < CH; d++)
            g_attn[(size_t)bh * CH * CH + tid * CH + d] = row[d] * inv;
    }
}

// ============================================================
// Fold attention into proj: Comb[b][m][h*48+d] = sum_c P[m][h*48+c] A[bh][c][d]
// ============================================================
__global__ __launch_bounds__(192) void combine_kernel(const float* __restrict__ P)
{
    const int bh = blockIdx.x;
    const int b = bh >> 2, h = bh & 3;
    __shared__ float A[CH * CH];
    for (int e = threadIdx.x; e < CH * CH; e += 192)
        A[e] = g_attn[(size_t)bh * CH * CH + e];
    __syncthreads();

    const int m = threadIdx.x;
    float p[CH];
#pragma unroll
    for (int c = 0; c < CH; c++) p[c] = P[(size_t)m * CDIM + h * CH + c];
    float* outp = g_comb + ((size_t)b * CDIM + m) * CDIM + h * CH;
#pragma unroll 4
    for (int d = 0; d < CH; d++) {
        float s = 0.f;
#pragma unroll
        for (int c = 0; c < CH; c++) s = fmaf(p[c], A[c * CH + d], s);
        outp[d] = s;
    }
}

// ============================================================
extern "C" void kernel_launch(void* const* d_in, const int* in_sizes, int n_in,
                              void* d_out, int out_size)
{
    const float* x      = (const float*)d_in[0];
    const float* qkv_w  = (const float*)d_in[1];
    const float* dw_w   = (const float*)d_in[2];
    const float* proj_w = (const float*)d_in[3];
    const float* temp   = (const float*)d_in[4];
    float* out = (float*)d_out;

    __half *qkv, *qkv2;
    float *comb;
    uint32_t *apq, *apm;
    cudaGetSymbolAddress((void**)&qkv,  g_qkv);
    cudaGetSymbolAddress((void**)&qkv2, g_qkv2);
    cudaGetSymbolAddress((void**)&comb, g_comb);
    cudaGetSymbolAddress((void**)&apq,  g_apq);
    cudaGetSymbolAddress((void**)&apm,  g_apm);

    dim3 blk(256);
    // 0) permute + fp16-convert qkv weights (5 mt x 12 k16 x 8 m16 x 32 lanes)
    prep_a<<<dim3(60, 1), blk>>>(qkv_w, apq, C3, 0, 0);
    // 1) qkv 1x1 conv (fp16 tensor cores), fp16 output
    pw_mma<float, __half><<<dim3(5, 128, BATCH), blk>>>(
        apq, 0, x, (size_t)CDIM * HWD, qkv, (size_t)C3 * HWD, C3);
    // 2) depthwise 3x3 (register sliding window), fp16 in/out
    dw_conv_kernel<<<dim3(BATCH * C3, 2), blk>>>(qkv, dw_w, qkv2);
    // 3) Q@K^T partials + free norms (fp16 tensor cores)
    gram_kernel<<<dim3(NCHUNK, BATCH * HEADS), blk>>>();
    // 4) softmax
    attn_kernel<<<BATCH * HEADS, blk>>>(temp);
    // 5) fold attn into proj weights (per batch)
    combine_kernel<<<BATCH * HEADS, 192>>>(proj_w);
    // 6) permute combined weights (2 mt per batch)
    prep_a<<<dim3(24, BATCH), blk>>>(comb, apm, CDIM, (size_t)CDIM * CDIM, 2 * 12288);
    // 7) fused (proj @ attn) @ v -> d_out (fp16 V input, fp32 output)
    pw_mma<__half, float><<<dim3(2, 128, BATCH), blk>>>(
        apm, 2 * 12288, qkv2 + (size_t)2 * CDIM * HWD, (size_t)C3 * HWD,
        out, (size_t)CDIM * HWD, CDIM);
}

// round 11
// speedup vs baseline: 5.7279x; 1.1399x over previous
#include <cuda_runtime.h>
#include <cuda_fp16.h>
#include <math.h>
#include <stdint.h>

#define BATCH 8
#define CDIM 192
#define C3 576
#define HWD 16384
#define HEADS 4
#define CH 48
#define NCHUNK 16

typedef unsigned long long ull;

// ---- fp16 mma m16n8k16, fp32 accumulate ----
__device__ __forceinline__ void mma_f16(float* c, uint4 a, uint2 b) {
    asm volatile(
        "mma.sync.aligned.m16n8k16.row.col.f32.f16.f16.f32 "
        "{%0,%1,%2,%3}, {%4,%5,%6,%7}, {%8,%9}, {%0,%1,%2,%3};"
        : "+f"(c[0]), "+f"(c[1]), "+f"(c[2]), "+f"(c[3])
        : "r"(a.x), "r"(a.y), "r"(a.z), "r"(a.w), "r"(b.x), "r"(b.y));
}
__device__ __forceinline__ uint32_t h2pack(float a, float b) {
    __half2 h = __floats2half2_rn(a, b);
    return *(uint32_t*)&h;
}

// ---- typed 4-element loads / 2-element stores ----
__device__ __forceinline__ float4 load4(const float* p) { return *(const float4*)p; }
__device__ __forceinline__ float4 load4(const __half* p) {
    __half2 h0 = *(const __half2*)p;
    __half2 h1 = *(const __half2*)(p + 2);
    float2 a = __half22float2(h0), b = __half22float2(h1);
    return make_float4(a.x, a.y, b.x, b.y);
}
__device__ __forceinline__ void store2(float* p, float a, float b) {
    *(float2*)p = make_float2(a, b);
}
__device__ __forceinline__ void store2(__half* p, float a, float b) {
    *(__half2*)p = __floats2half2_rn(a, b);
}

// ---- scratch (device globals; no allocations allowed) ----
__device__ __half g_qkv [(size_t)BATCH * C3 * HWD];
__device__ __half g_qkv2[(size_t)BATCH * C3 * HWD];
__device__ float g_part_gram[(size_t)BATCH * HEADS * NCHUNK * CH * CH];
__device__ float g_part_nq  [(size_t)BATCH * HEADS * NCHUNK * CH];
__device__ float g_part_nk  [(size_t)BATCH * HEADS * NCHUNK * CH];
__device__ float g_attn     [(size_t)BATCH * HEADS * CH * CH];
__device__ float g_comb     [(size_t)BATCH * CDIM * CDIM];   // P @ blockdiag(attn)
__device__ uint32_t g_apq[5 * 12288];          // qkv W, fp16 fragment-permuted
__device__ uint32_t g_apm[BATCH * 2 * 12288];  // combined proj, per batch

// ============================================================
// Permute W[M,192] into fp16 m16n8k16 fragment order.
// Layout: [mt][k16(12)][m16(8)][lane(32)][reg(4)] as half2-packed uint32.
// ============================================================
__global__ __launch_bounds__(256) void prep_a(
    const float* __restrict__ W, uint32_t* __restrict__ Ap, int Mdim,
    size_t w_bstride, size_t a_bstride)
{
    const float* Wb = W + blockIdx.y * w_bstride;
    uint32_t* Apb = Ap + blockIdx.y * a_bstride;
    const int idx = blockIdx.x * 256 + threadIdx.x;
    const int lane = idx & 31;
    int rest = idx >> 5;
    const int m16 = rest & 7; rest >>= 3;
    const int k16 = rest % 12;
    const int mt = rest / 12;
    const int g = lane >> 2, t = lane & 3;
    const int row = mt * 128 + m16 * 16 + g;
    const int k = k16 * 16 + 2 * t;
    float a00 = 0.f, a01 = 0.f, a10 = 0.f, a11 = 0.f;
    float a20 = 0.f, a21 = 0.f, a30 = 0.f, a31 = 0.f;
    if (row < Mdim) {
        const float* wr = Wb + (size_t)row * CDIM + k;
        a00 = wr[0]; a01 = wr[1]; a20 = wr[8]; a21 = wr[9];
    }
    if (row + 8 < Mdim) {
        const float* wr = Wb + (size_t)(row + 8) * CDIM + k;
        a10 = wr[0]; a11 = wr[1]; a30 = wr[8]; a31 = wr[9];
    }
    uint4 o;
    o.x = h2pack(a00, a01); o.y = h2pack(a10, a11);
    o.z = h2pack(a20, a21); o.w = h2pack(a30, a31);
    *(uint4*)(Apb + (size_t)idx * 4) = o;
}

// ============================================================
// Pointwise GEMM via mma.sync fp16: Y[b,m,n] = sum_k A[(b),m,k] X[b,k,n]
// 128(M) x 128(N) block, BK=32 (two k16 steps/iter), double buffered.
// ============================================================
template <typename InT, typename OutT>
__global__ __launch_bounds__(256) void pw_mma(
    const uint32_t* __restrict__ Ap, size_t a_bstride,
    const InT* __restrict__ X, size_t x_bstride,
    OutT* __restrict__ Y, size_t y_bstride, int Mdim)
{
    __shared__ __align__(16) uint32_t As[2][2048];        // 2 k16 frags
    __shared__ __align__(16) uint32_t Bs16[2][16 * 136];  // [k2(16)][n+pad] half2
    const int tid = threadIdx.x;
    const int lane = tid & 31, wid = tid >> 5;
    const int mt = blockIdx.x;
    const int n0 = blockIdx.y * 128;
    const size_t boffX = (size_t)blockIdx.z * x_bstride;
    const size_t boffY = (size_t)blockIdx.z * y_bstride;

    const uint32_t* apg = Ap + (size_t)blockIdx.z * a_bstride + (size_t)mt * 12288;
    const int nq = tid & 31;
    const int bk0 = tid >> 5;           // 0..7

    uint4 a_r0, a_r1;
    float4 b_r0, b_r1, b_r2, b_r3;

    auto ldg_iter = [&](int it) {
        a_r0 = *(const uint4*)(apg + (size_t)it * 2048 + (size_t)tid * 4);
        a_r1 = *(const uint4*)(apg + (size_t)it * 2048 + 1024 + (size_t)tid * 4);
        const InT* xb = X + boffX + (size_t)(it * 32 + 2 * bk0) * HWD + n0 + nq * 4;
        b_r0 = load4(xb);
        b_r1 = load4(xb + HWD);
        b_r2 = load4(xb + (size_t)16 * HWD);
        b_r3 = load4(xb + (size_t)17 * HWD);
    };
    auto sts_iter = [&](int buf) {
        *(uint4*)&As[buf][tid * 4] = a_r0;
        *(uint4*)&As[buf][(tid + 256) * 4] = a_r1;
        uint4 p0, p1;
        p0.x = h2pack(b_r0.x, b_r1.x); p0.y = h2pack(b_r0.y, b_r1.y);
        p0.z = h2pack(b_r0.z, b_r1.z); p0.w = h2pack(b_r0.w, b_r1.w);
        p1.x = h2pack(b_r2.x, b_r3.x); p1.y = h2pack(b_r2.y, b_r3.y);
        p1.z = h2pack(b_r2.z, b_r3.z); p1.w = h2pack(b_r2.w, b_r3.w);
        *(uint4*)&Bs16[buf][bk0 * 136 + nq * 4] = p0;
        *(uint4*)&Bs16[buf][(8 + bk0) * 136 + nq * 4] = p1;
    };

    float acc[2][8][4];
#pragma unroll
    for (int f = 0; f < 2; f++)
#pragma unroll
        for (int j = 0; j < 8; j++)
#pragma unroll
            for (int e = 0; e < 4; e++) acc[f][j][e] = 0.f;

    const int m16a = (wid & 3) * 2;
    const int t = lane & 3;
    const int g = lane >> 2;
    const int nwb = (wid >> 2) * 64;

    auto compute = [&](int buf) {
#pragma unroll
        for (int s = 0; s < 2; s++) {
            uint4 A0 = *(const uint4*)&As[buf][(s * 256 + m16a * 32 + lane) * 4];
            uint4 A1 = *(const uint4*)&As[buf][(s * 256 + (m16a + 1) * 32 + lane) * 4];
            const int br0 = (s * 8 + t) * 136 + nwb + g;
            const int br1 = (s * 8 + t + 4) * 136 + nwb + g;
#pragma unroll
            for (int j = 0; j < 8; j++) {
                uint2 b = make_uint2(Bs16[buf][br0 + j * 8], Bs16[buf][br1 + j * 8]);
                mma_f16(acc[0][j], A0, b);
                mma_f16(acc[1][j], A1, b);
            }
        }
    };

    ldg_iter(0);
    sts_iter(0);
    __syncthreads();
#pragma unroll 1
    for (int it = 0; it < 6; it++) {
        if (it + 1 < 6) ldg_iter(it + 1);
        compute(it & 1);
        if (it + 1 < 6) sts_iter((it + 1) & 1);
        __syncthreads();
    }

    const int mw = mt * 128 + (wid & 3) * 32;
#pragma unroll
    for (int f = 0; f < 2; f++) {
        const int m = mw + f * 16 + g;
#pragma unroll
        for (int j = 0; j < 8; j++) {
            OutT* p = Y + boffY + (size_t)m * HWD + n0 + nwb + j * 8 + 2 * t;
            if (m < Mdim)
                store2(p, acc[f][j][0], acc[f][j][1]);
            if (m + 8 < Mdim)
                store2(p + (size_t)8 * HWD, acc[f][j][2], acc[f][j][3]);
        }
    }
}

// ============================================================
// Depthwise 3x3, pad 1 — register sliding window + warp shuffle halos.
// ============================================================
__global__ __launch_bounds__(256) void dw_conv_kernel(
    const __half* __restrict__ in, const float* __restrict__ wts,
    __half* __restrict__ out)
{
    const int bc = blockIdx.x;
    const int c = bc % C3;
    const int warp = threadIdx.x >> 5;
    const int lane = threadIdx.x & 31;
    const int y0 = blockIdx.y * 64 + warp * 8;

    float w[9];
#pragma unroll
    for (int i = 0; i < 9; i++) w[i] = __ldg(wts + c * 9 + i);

    const __half* ip = in + (size_t)bc * HWD + lane * 4;
    float win[3][6];

    auto loadrow = [&](int gy, float* row6) {
        float4 v = make_float4(0.f, 0.f, 0.f, 0.f);
        if (gy >= 0 && gy < 128) v = load4(ip + (size_t)gy * 128);
        float l = __shfl_up_sync(0xffffffffu, v.w, 1);
        float r = __shfl_down_sync(0xffffffffu, v.x, 1);
        if (lane == 0)  l = 0.f;
        if (lane == 31) r = 0.f;
        row6[0] = l; row6[1] = v.x; row6[2] = v.y;
        row6[3] = v.z; row6[4] = v.w; row6[5] = r;
    };

    loadrow(y0 - 1, win[0]);
    loadrow(y0,     win[1]);
    __half* op = out + (size_t)bc * HWD + lane * 4;
#pragma unroll
    for (int r = 0; r < 8; r++) {
        loadrow(y0 + 1 + r, win[(r + 2) % 3]);
        const float* tp = win[r % 3];
        const float* mp = win[(r + 1) % 3];
        const float* bp = win[(r + 2) % 3];
        float o[4];
#pragma unroll
        for (int p = 0; p < 4; p++) {
            float s = 0.f;
            s = fmaf(tp[p], w[0], s); s = fmaf(tp[p + 1], w[1], s); s = fmaf(tp[p + 2], w[2], s);
            s = fmaf(mp[p], w[3], s); s = fmaf(mp[p + 1], w[4], s); s = fmaf(mp[p + 2], w[5], s);
            s = fmaf(bp[p], w[6], s); s = fmaf(bp[p + 1], w[7], s); s = fmaf(bp[p + 2], w[8], s);
            o[p] = s;
        }
        __half2 h0 = __floats2half2_rn(o[0], o[1]);
        __half2 h1 = __floats2half2_rn(o[2], o[3]);
        __half2* dst = (__half2*)(op + (size_t)(y0 + r) * 128);
        dst[0] = h0; dst[1] = h1;
    }
}

// ============================================================
// Gram on fp16 tensor cores: Q@K^T (48x48) per (bh, 1024-px chunk).
// Double-buffered smem staging; norms ride along in fp32 regs.
// ============================================================
__global__ __launch_bounds__(256) void gram_kernel()
{
    const int chunk = blockIdx.x;
    const int bh = blockIdx.y;
    const int b = bh >> 2, h = bh & 3;
    const __half* qb = g_qkv2 + ((size_t)b * C3 + h * CH) * HWD;
    const __half* kb = g_qkv2 + ((size_t)b * C3 + CDIM + h * CH) * HWD;
    __shared__ __align__(16) uint32_t Qs[2][CH][36];
    __shared__ __align__(16) uint32_t Ks[2][CH][36];
    __shared__ float redq[CH][16];
    __shared__ float redk[CH][16];
    const int tid = threadIdx.x;
    const int lane = tid & 31, wid = tid >> 5;
    const int n0 = chunk * 1024;

    float acc[3][4];
#pragma unroll
    for (int jj = 0; jj < 3; jj++)
#pragma unroll
        for (int e = 0; e < 4; e++) acc[jj][e] = 0.f;
    float nq[3] = {0.f, 0.f, 0.f};
    float nk[3] = {0.f, 0.f, 0.f};

    const int mrow = wid % 3;
    const int nhalf = (wid < 6) ? (wid / 3) : 0;
    const int g = lane >> 2, t = lane & 3;
    const int lrow0 = tid >> 4;          // staging row base (per i: +16)
    const int lcolq = tid & 15;

    auto loadtile = [&](int t0, int buf) {
#pragma unroll
        for (int i = 0; i < 3; i++) {
            int row = lrow0 + i * 16;
            float4 v = load4(qb + (size_t)row * HWD + n0 + t0 + lcolq * 4);
            *(uint2*)&Qs[buf][row][lcolq * 2] = make_uint2(h2pack(v.x, v.y), h2pack(v.z, v.w));
            nq[i] = fmaf(v.x, v.x, nq[i]); nq[i] = fmaf(v.y, v.y, nq[i]);
            nq[i] = fmaf(v.z, v.z, nq[i]); nq[i] = fmaf(v.w, v.w, nq[i]);
            float4 u = load4(kb + (size_t)row * HWD + n0 + t0 + lcolq * 4);
            *(uint2*)&Ks[buf][row][lcolq * 2] = make_uint2(h2pack(u.x, u.y), h2pack(u.z, u.w));
            nk[i] = fmaf(u.x, u.x, nk[i]); nk[i] = fmaf(u.y, u.y, nk[i]);
            nk[i] = fmaf(u.z, u.z, nk[i]); nk[i] = fmaf(u.w, u.w, nk[i]);
        }
    };

    loadtile(0, 0);
    __syncthreads();
#pragma unroll 1
    for (int ti = 0; ti < 16; ti++) {
        if (ti + 1 < 16) loadtile((ti + 1) * 64, (ti + 1) & 1);
        if (wid < 6) {
            const int buf = ti & 1;
            const int mr = 16 * mrow + g;
#pragma unroll
            for (int s = 0; s < 4; s++) {
                const int base = s * 8;
                uint4 a;
                a.x = Qs[buf][mr][base + t];
                a.y = Qs[buf][mr + 8][base + t];
                a.z = Qs[buf][mr][base + t + 4];
                a.w = Qs[buf][mr + 8][base + t + 4];
#pragma unroll
                for (int jj = 0; jj < 3; jj++) {
                    const int nr = 8 * (3 * nhalf + jj) + g;
                    uint2 bf = make_uint2(Ks[buf][nr][base + t], Ks[buf][nr][base + t + 4]);
                    mma_f16(acc[jj], a, bf);
                }
            }
        }
        __syncthreads();
    }

    const int quad = lcolq;
    redq[lrow0][quad] = nq[0]; redq[lrow0 + 16][quad] = nq[1]; redq[lrow0 + 32][quad] = nq[2];
    redk[lrow0][quad] = nk[0]; redk[lrow0 + 16][quad] = nk[1]; redk[lrow0 + 32][quad] = nk[2];
    __syncthreads();
    if (tid < CH) {
        float s = 0.f;
#pragma unroll
        for (int q = 0; q < 16; q++) s += redq[tid][q];
        g_part_nq[((size_t)bh * NCHUNK + chunk) * CH + tid] = s;
    } else if (tid < 2 * CH) {
        float s = 0.f;
#pragma unroll
        for (int q = 0; q < 16; q++) s += redk[tid - CH][q];
        g_part_nk[((size_t)bh * NCHUNK + chunk) * CH + (tid - CH)] = s;
    }

    if (wid < 6) {
        float* gp = g_part_gram + ((size_t)bh * NCHUNK + chunk) * CH * CH;
        const int m = 16 * mrow + g;
#pragma unroll
        for (int jj = 0; jj < 3; jj++) {
            const int n = 8 * (3 * nhalf + jj) + 2 * t;
            *(float2*)&gp[m * CH + n] = make_float2(acc[jj][0], acc[jj][1]);
            *(float2*)&gp[(m + 8) * CH + n] = make_float2(acc[jj][2], acc[jj][3]);
        }
    }
}

// ============================================================
// Reduce partials -> normalize -> temperature -> warp-parallel softmax
// ============================================================
__global__ __launch_bounds__(256) void attn_kernel(const float* __restrict__ temperature)
{
    const int bh = blockIdx.x;
    const int h = bh & 3;
    __shared__ float S[CH * CH];
    __shared__ float rq[CH];
    __shared__ float rk[CH];
    const int tid = threadIdx.x;
    const int lane = tid & 31, wid = tid >> 5;

    for (int e = tid; e < CH * CH; e += 256) {
        float s = 0.f;
#pragma unroll
        for (int p = 0; p < NCHUNK; p++)
            s += g_part_gram[((size_t)bh * NCHUNK + p) * CH * CH + e];
        S[e] = s;
    }
    if (tid < CH) {
        float s = 0.f;
#pragma unroll
        for (int p = 0; p < NCHUNK; p++) s += g_part_nq[((size_t)bh * NCHUNK + p) * CH + tid];
        rq[tid] = fmaxf(sqrtf(s), 1e-12f);
    } else if (tid < 2 * CH) {
        float s = 0.f;
#pragma unroll
        for (int p = 0; p < NCHUNK; p++) s += g_part_nk[((size_t)bh * NCHUNK + p) * CH + (tid - CH)];
        rk[tid - CH] = fmaxf(sqrtf(s), 1e-12f);
    }
    __syncthreads();

    // warp w handles rows 6w..6w+5; lanes split 48 cols (lane, lane+32)
    const float tmp = temperature[h];
    const int c2 = lane + 32;
#pragma unroll
    for (int rr = 0; rr < 6; rr++) {
        const int r = wid * 6 + rr;
        const float fq = tmp / rq[r];
        float v1 = S[r * CH + lane] * fq / rk[lane];
        float v2 = (c2 < CH) ? S[r * CH + c2] * fq / rk[c2] : -1e30f;
        float mx = fmaxf(v1, v2);
#pragma unroll
        for (int o = 16; o; o >>= 1) mx = fmaxf(mx, __shfl_xor_sync(0xffffffffu, mx, o));
        float e1 = expf(v1 - mx);
        float e2 = (c2 < CH) ? expf(v2 - mx) : 0.f;
        float sm = e1 + e2;
#pragma unroll
        for (int o = 16; o; o >>= 1) sm += __shfl_xor_sync(0xffffffffu, sm, o);
        float inv = 1.f / sm;
        float* arow = g_attn + (size_t)bh * CH * CH + r * CH;
        arow[lane] = e1 * inv;
        if (c2 < CH) arow[c2] = e2 * inv;
    }
}

// ============================================================
// Fold attention into proj: Comb[b][m][h*48+d] = sum_c P[m][h*48+c] A[bh][c][d]
// ============================================================
__global__ __launch_bounds__(192) void combine_kernel(const float* __restrict__ P)
{
    const int bh = blockIdx.x;
    const int b = bh >> 2, h = bh & 3;
    __shared__ float A[CH * CH];
    for (int e = threadIdx.x; e < CH * CH; e += 192)
        A[e] = g_attn[(size_t)bh * CH * CH + e];
    __syncthreads();

    const int m = threadIdx.x;
    float p[CH];
#pragma unroll
    for (int c = 0; c < CH; c++) p[c] = P[(size_t)m * CDIM + h * CH + c];
    float* outp = g_comb + ((size_t)b * CDIM + m) * CDIM + h * CH;
#pragma unroll 4
    for (int d = 0; d < CH; d++) {
        float s = 0.f;
#pragma unroll
        for (int c = 0; c < CH; c++) s = fmaf(p[c], A[c * CH + d], s);
        outp[d] = s;
    }
}

// ============================================================
extern "C" void kernel_launch(void* const* d_in, const int* in_sizes, int n_in,
                              void* d_out, int out_size)
{
    const float* x      = (const float*)d_in[0];
    const float* qkv_w  = (const float*)d_in[1];
    const float* dw_w   = (const float*)d_in[2];
    const float* proj_w = (const float*)d_in[3];
    const float* temp   = (const float*)d_in[4];
    float* out = (float*)d_out;

    __half *qkv, *qkv2;
    float *comb;
    uint32_t *apq, *apm;
    cudaGetSymbolAddress((void**)&qkv,  g_qkv);
    cudaGetSymbolAddress((void**)&qkv2, g_qkv2);
    cudaGetSymbolAddress((void**)&comb, g_comb);
    cudaGetSymbolAddress((void**)&apq,  g_apq);
    cudaGetSymbolAddress((void**)&apm,  g_apm);

    dim3 blk(256);
    // 0) permute + fp16-convert qkv weights
    prep_a<<<dim3(60, 1), blk>>>(qkv_w, apq, C3, 0, 0);
    // 1) qkv 1x1 conv (fp16 tensor cores, BK=32), fp16 output
    pw_mma<float, __half><<<dim3(5, 128, BATCH), blk>>>(
        apq, 0, x, (size_t)CDIM * HWD, qkv, (size_t)C3 * HWD, C3);
    // 2) depthwise 3x3 (register sliding window), fp16 in/out
    dw_conv_kernel<<<dim3(BATCH * C3, 2), blk>>>(qkv, dw_w, qkv2);
    // 3) Q@K^T partials + free norms (fp16 tensor cores, double buffered)
    gram_kernel<<<dim3(NCHUNK, BATCH * HEADS), blk>>>();
    // 4) softmax (warp-parallel)
    attn_kernel<<<BATCH * HEADS, blk>>>(temp);
    // 5) fold attn into proj weights (per batch)
    combine_kernel<<<BATCH * HEADS, 192>>>(proj_w);
    // 6) permute combined weights
    prep_a<<<dim3(24, BATCH), blk>>>(comb, apm, CDIM, (size_t)CDIM * CDIM, 2 * 12288);
    // 7) fused (proj @ attn) @ v -> d_out (fp16 V input, fp32 output)
    pw_mma<__half, float><<<dim3(2, 128, BATCH), blk>>>(
        apm, 2 * 12288, qkv2 + (size_t)2 * CDIM * HWD, (size_t)C3 * HWD,
        out, (size_t)CDIM * HWD, CDIM);
}

// round 12
// speedup vs baseline: 5.8310x; 1.0180x over previous
#include <cuda_runtime.h>
#include <cuda_fp16.h>
#include <math.h>
#include <stdint.h>

#define BATCH 8
#define CDIM 192
#define C3 576
#define HWD 16384
#define HEADS 4
#define CH 48
#define NCHUNK 32
#define CHUNKPX 512

typedef unsigned long long ull;

// ---- fp16 mma m16n8k16, fp32 accumulate ----
__device__ __forceinline__ void mma_f16(float* c, uint4 a, uint2 b) {
    asm volatile(
        "mma.sync.aligned.m16n8k16.row.col.f32.f16.f16.f32 "
        "{%0,%1,%2,%3}, {%4,%5,%6,%7}, {%8,%9}, {%0,%1,%2,%3};"
        : "+f"(c[0]), "+f"(c[1]), "+f"(c[2]), "+f"(c[3])
        : "r"(a.x), "r"(a.y), "r"(a.z), "r"(a.w), "r"(b.x), "r"(b.y));
}
__device__ __forceinline__ uint32_t h2pack(float a, float b) {
    __half2 h = __floats2half2_rn(a, b);
    return *(uint32_t*)&h;
}

// ---- typed 4-element loads / 2-element stores ----
__device__ __forceinline__ float4 load4(const float* p) { return *(const float4*)p; }
__device__ __forceinline__ float4 load4(const __half* p) {
    __half2 h0 = *(const __half2*)p;
    __half2 h1 = *(const __half2*)(p + 2);
    float2 a = __half22float2(h0), b = __half22float2(h1);
    return make_float4(a.x, a.y, b.x, b.y);
}
__device__ __forceinline__ void store2(float* p, float a, float b) {
    *(float2*)p = make_float2(a, b);
}
__device__ __forceinline__ void store2(__half* p, float a, float b) {
    *(__half2*)p = __floats2half2_rn(a, b);
}

// ---- scratch (device globals; no allocations allowed) ----
__device__ __half g_qkv [(size_t)BATCH * C3 * HWD];
__device__ __half g_qkv2[(size_t)BATCH * C3 * HWD];
__device__ float g_part_gram[(size_t)BATCH * HEADS * NCHUNK * CH * CH];
__device__ float g_part_nq  [(size_t)BATCH * HEADS * NCHUNK * CH];
__device__ float g_part_nk  [(size_t)BATCH * HEADS * NCHUNK * CH];
__device__ float g_comb     [(size_t)BATCH * CDIM * CDIM];   // P @ blockdiag(attn)
__device__ uint32_t g_apq[5 * 12288];          // qkv W, fp16 fragment-permuted
__device__ uint32_t g_apm[BATCH * 2 * 12288];  // combined proj, per batch

// ============================================================
// Permute W[M,192] into fp16 m16n8k16 fragment order.
// ============================================================
__global__ __launch_bounds__(256) void prep_a(
    const float* __restrict__ W, uint32_t* __restrict__ Ap, int Mdim,
    size_t w_bstride, size_t a_bstride)
{
    const float* Wb = W + blockIdx.y * w_bstride;
    uint32_t* Apb = Ap + blockIdx.y * a_bstride;
    const int idx = blockIdx.x * 256 + threadIdx.x;
    const int lane = idx & 31;
    int rest = idx >> 5;
    const int m16 = rest & 7; rest >>= 3;
    const int k16 = rest % 12;
    const int mt = rest / 12;
    const int g = lane >> 2, t = lane & 3;
    const int row = mt * 128 + m16 * 16 + g;
    const int k = k16 * 16 + 2 * t;
    float a00 = 0.f, a01 = 0.f, a10 = 0.f, a11 = 0.f;
    float a20 = 0.f, a21 = 0.f, a30 = 0.f, a31 = 0.f;
    if (row < Mdim) {
        const float* wr = Wb + (size_t)row * CDIM + k;
        a00 = wr[0]; a01 = wr[1]; a20 = wr[8]; a21 = wr[9];
    }
    if (row + 8 < Mdim) {
        const float* wr = Wb + (size_t)(row + 8) * CDIM + k;
        a10 = wr[0]; a11 = wr[1]; a30 = wr[8]; a31 = wr[9];
    }
    uint4 o;
    o.x = h2pack(a00, a01); o.y = h2pack(a10, a11);
    o.z = h2pack(a20, a21); o.w = h2pack(a30, a31);
    *(uint4*)(Apb + (size_t)idx * 4) = o;
}

// ============================================================
// Pointwise GEMM via mma.sync fp16: Y[b,m,n] = sum_k A[(b),m,k] X[b,k,n]
// 128(M) x 128(N) block, BK=32 (two k16 steps/iter), double buffered.
// ============================================================
template <typename InT, typename OutT>
__global__ __launch_bounds__(256) void pw_mma(
    const uint32_t* __restrict__ Ap, size_t a_bstride,
    const InT* __restrict__ X, size_t x_bstride,
    OutT* __restrict__ Y, size_t y_bstride, int Mdim)
{
    __shared__ __align__(16) uint32_t As[2][2048];        // 2 k16 frags
    __shared__ __align__(16) uint32_t Bs16[2][16 * 136];  // [k2(16)][n+pad] half2
    const int tid = threadIdx.x;
    const int lane = tid & 31, wid = tid >> 5;
    const int mt = blockIdx.x;
    const int n0 = blockIdx.y * 128;
    const size_t boffX = (size_t)blockIdx.z * x_bstride;
    const size_t boffY = (size_t)blockIdx.z * y_bstride;

    const uint32_t* apg = Ap + (size_t)blockIdx.z * a_bstride + (size_t)mt * 12288;
    const int nq = tid & 31;
    const int bk0 = tid >> 5;           // 0..7

    uint4 a_r0, a_r1;
    float4 b_r0, b_r1, b_r2, b_r3;

    auto ldg_iter = [&](int it) {
        a_r0 = *(const uint4*)(apg + (size_t)it * 2048 + (size_t)tid * 4);
        a_r1 = *(const uint4*)(apg + (size_t)it * 2048 + 1024 + (size_t)tid * 4);
        const InT* xb = X + boffX + (size_t)(it * 32 + 2 * bk0) * HWD + n0 + nq * 4;
        b_r0 = load4(xb);
        b_r1 = load4(xb + HWD);
        b_r2 = load4(xb + (size_t)16 * HWD);
        b_r3 = load4(xb + (size_t)17 * HWD);
    };
    auto sts_iter = [&](int buf) {
        *(uint4*)&As[buf][tid * 4] = a_r0;
        *(uint4*)&As[buf][(tid + 256) * 4] = a_r1;
        uint4 p0, p1;
        p0.x = h2pack(b_r0.x, b_r1.x); p0.y = h2pack(b_r0.y, b_r1.y);
        p0.z = h2pack(b_r0.z, b_r1.z); p0.w = h2pack(b_r0.w, b_r1.w);
        p1.x = h2pack(b_r2.x, b_r3.x); p1.y = h2pack(b_r2.y, b_r3.y);
        p1.z = h2pack(b_r2.z, b_r3.z); p1.w = h2pack(b_r2.w, b_r3.w);
        *(uint4*)&Bs16[buf][bk0 * 136 + nq * 4] = p0;
        *(uint4*)&Bs16[buf][(8 + bk0) * 136 + nq * 4] = p1;
    };

    float acc[2][8][4];
#pragma unroll
    for (int f = 0; f < 2; f++)
#pragma unroll
        for (int j = 0; j < 8; j++)
#pragma unroll
            for (int e = 0; e < 4; e++) acc[f][j][e] = 0.f;

    const int m16a = (wid & 3) * 2;
    const int t = lane & 3;
    const int g = lane >> 2;
    const int nwb = (wid >> 2) * 64;

    auto compute = [&](int buf) {
#pragma unroll
        for (int s = 0; s < 2; s++) {
            uint4 A0 = *(const uint4*)&As[buf][(s * 256 + m16a * 32 + lane) * 4];
            uint4 A1 = *(const uint4*)&As[buf][(s * 256 + (m16a + 1) * 32 + lane) * 4];
            const int br0 = (s * 8 + t) * 136 + nwb + g;
            const int br1 = (s * 8 + t + 4) * 136 + nwb + g;
#pragma unroll
            for (int j = 0; j < 8; j++) {
                uint2 b = make_uint2(Bs16[buf][br0 + j * 8], Bs16[buf][br1 + j * 8]);
                mma_f16(acc[0][j], A0, b);
                mma_f16(acc[1][j], A1, b);
            }
        }
    };

    ldg_iter(0);
    sts_iter(0);
    __syncthreads();
#pragma unroll 1
    for (int it = 0; it < 6; it++) {
        if (it + 1 < 6) ldg_iter(it + 1);
        compute(it & 1);
        if (it + 1 < 6) sts_iter((it + 1) & 1);
        __syncthreads();
    }

    const int mw = mt * 128 + (wid & 3) * 32;
#pragma unroll
    for (int f = 0; f < 2; f++) {
        const int m = mw + f * 16 + g;
#pragma unroll
        for (int j = 0; j < 8; j++) {
            OutT* p = Y + boffY + (size_t)m * HWD + n0 + nwb + j * 8 + 2 * t;
            if (m < Mdim)
                store2(p, acc[f][j][0], acc[f][j][1]);
            if (m + 8 < Mdim)
                store2(p + (size_t)8 * HWD, acc[f][j][2], acc[f][j][3]);
        }
    }
}

// ============================================================
// Depthwise 3x3, pad 1 — register sliding window + warp shuffle halos.
// ============================================================
__global__ __launch_bounds__(256) void dw_conv_kernel(
    const __half* __restrict__ in, const float* __restrict__ wts,
    __half* __restrict__ out)
{
    const int bc = blockIdx.x;
    const int c = bc % C3;
    const int warp = threadIdx.x >> 5;
    const int lane = threadIdx.x & 31;
    const int y0 = blockIdx.y * 64 + warp * 8;

    float w[9];
#pragma unroll
    for (int i = 0; i < 9; i++) w[i] = __ldg(wts + c * 9 + i);

    const __half* ip = in + (size_t)bc * HWD + lane * 4;
    float win[3][6];

    auto loadrow = [&](int gy, float* row6) {
        float4 v = make_float4(0.f, 0.f, 0.f, 0.f);
        if (gy >= 0 && gy < 128) v = load4(ip + (size_t)gy * 128);
        float l = __shfl_up_sync(0xffffffffu, v.w, 1);
        float r = __shfl_down_sync(0xffffffffu, v.x, 1);
        if (lane == 0)  l = 0.f;
        if (lane == 31) r = 0.f;
        row6[0] = l; row6[1] = v.x; row6[2] = v.y;
        row6[3] = v.z; row6[4] = v.w; row6[5] = r;
    };

    loadrow(y0 - 1, win[0]);
    loadrow(y0,     win[1]);
    __half* op = out + (size_t)bc * HWD + lane * 4;
#pragma unroll
    for (int r = 0; r < 8; r++) {
        loadrow(y0 + 1 + r, win[(r + 2) % 3]);
        const float* tp = win[r % 3];
        const float* mp = win[(r + 1) % 3];
        const float* bp = win[(r + 2) % 3];
        float o[4];
#pragma unroll
        for (int p = 0; p < 4; p++) {
            float s = 0.f;
            s = fmaf(tp[p], w[0], s); s = fmaf(tp[p + 1], w[1], s); s = fmaf(tp[p + 2], w[2], s);
            s = fmaf(mp[p], w[3], s); s = fmaf(mp[p + 1], w[4], s); s = fmaf(mp[p + 2], w[5], s);
            s = fmaf(bp[p], w[6], s); s = fmaf(bp[p + 1], w[7], s); s = fmaf(bp[p + 2], w[8], s);
            o[p] = s;
        }
        __half2 h0 = __floats2half2_rn(o[0], o[1]);
        __half2 h1 = __floats2half2_rn(o[2], o[3]);
        __half2* dst = (__half2*)(op + (size_t)(y0 + r) * 128);
        dst[0] = h0; dst[1] = h1;
    }
}

// ============================================================
// Gram on fp16 tensor cores: Q@K^T (48x48) per (bh, 512-px chunk).
// Single-buffered (R10 structure); 1024 blocks for occupancy.
// Norms ride along in fp32 regs during staging.
// ============================================================
__global__ __launch_bounds__(256) void gram_kernel()
{
    const int chunk = blockIdx.x;
    const int bh = blockIdx.y;
    const int b = bh >> 2, h = bh & 3;
    const __half* qb = g_qkv2 + ((size_t)b * C3 + h * CH) * HWD;
    const __half* kb = g_qkv2 + ((size_t)b * C3 + CDIM + h * CH) * HWD;
    __shared__ __align__(16) uint32_t Qs[CH][36];   // [row][px/2 + pad]
    __shared__ __align__(16) uint32_t Ks[CH][36];
    __shared__ float redq[CH][16];
    __shared__ float redk[CH][16];
    const int tid = threadIdx.x;
    const int lane = tid & 31, wid = tid >> 5;
    const int n0 = chunk * CHUNKPX;

    float acc[3][4];
#pragma unroll
    for (int jj = 0; jj < 3; jj++)
#pragma unroll
        for (int e = 0; e < 4; e++) acc[jj][e] = 0.f;
    float nq[3] = {0.f, 0.f, 0.f};
    float nk[3] = {0.f, 0.f, 0.f};

    const int mrow = wid % 3;
    const int nhalf = (wid < 6) ? (wid / 3) : 0;
    const int g = lane >> 2, t = lane & 3;

#pragma unroll 1
    for (int t0 = 0; t0 < CHUNKPX; t0 += 64) {
#pragma unroll
        for (int i = 0; i < 3; i++) {
            int idx = tid + i * 256;
            int row = idx >> 4;
            int colq = idx & 15;
            float4 v = load4(qb + (size_t)row * HWD + n0 + t0 + colq * 4);
            Qs[row][colq * 2 + 0] = h2pack(v.x, v.y);
            Qs[row][colq * 2 + 1] = h2pack(v.z, v.w);
            nq[i] = fmaf(v.x, v.x, nq[i]); nq[i] = fmaf(v.y, v.y, nq[i]);
            nq[i] = fmaf(v.z, v.z, nq[i]); nq[i] = fmaf(v.w, v.w, nq[i]);

            float4 u = load4(kb + (size_t)row * HWD + n0 + t0 + colq * 4);
            Ks[row][colq * 2 + 0] = h2pack(u.x, u.y);
            Ks[row][colq * 2 + 1] = h2pack(u.z, u.w);
            nk[i] = fmaf(u.x, u.x, nk[i]); nk[i] = fmaf(u.y, u.y, nk[i]);
            nk[i] = fmaf(u.z, u.z, nk[i]); nk[i] = fmaf(u.w, u.w, nk[i]);
        }
        __syncthreads();
        if (wid < 6) {
            const int mr = 16 * mrow + g;
#pragma unroll
            for (int s = 0; s < 4; s++) {
                const int base = s * 8;
                uint4 a;
                a.x = Qs[mr][base + t];
                a.y = Qs[mr + 8][base + t];
                a.z = Qs[mr][base + t + 4];
                a.w = Qs[mr + 8][base + t + 4];
#pragma unroll
                for (int jj = 0; jj < 3; jj++) {
                    const int nr = 8 * (3 * nhalf + jj) + g;
                    uint2 bf = make_uint2(Ks[nr][base + t], Ks[nr][base + t + 4]);
                    mma_f16(acc[jj], a, bf);
                }
            }
        }
        __syncthreads();
    }

    const int r0 = tid >> 4, quad = tid & 15;
    redq[r0][quad] = nq[0]; redq[r0 + 16][quad] = nq[1]; redq[r0 + 32][quad] = nq[2];
    redk[r0][quad] = nk[0]; redk[r0 + 16][quad] = nk[1]; redk[r0 + 32][quad] = nk[2];
    __syncthreads();
    if (tid < CH) {
        float s = 0.f;
#pragma unroll
        for (int q = 0; q < 16; q++) s += redq[tid][q];
        g_part_nq[((size_t)bh * NCHUNK + chunk) * CH + tid] = s;
    } else if (tid < 2 * CH) {
        float s = 0.f;
#pragma unroll
        for (int q = 0; q < 16; q++) s += redk[tid - CH][q];
        g_part_nk[((size_t)bh * NCHUNK + chunk) * CH + (tid - CH)] = s;
    }

    if (wid < 6) {
        float* gp = g_part_gram + ((size_t)bh * NCHUNK + chunk) * CH * CH;
        const int m = 16 * mrow + g;
#pragma unroll
        for (int jj = 0; jj < 3; jj++) {
            const int n = 8 * (3 * nhalf + jj) + 2 * t;
            *(float2*)&gp[m * CH + n] = make_float2(acc[jj][0], acc[jj][1]);
            *(float2*)&gp[(m + 8) * CH + n] = make_float2(acc[jj][2], acc[jj][3]);
        }
    }
}

// ============================================================
// Fused: reduce partials -> normalize -> softmax (smem) -> combine w/ proj
// Block = (b,h); Comb[b][m][h*48+d] = sum_c P[m][h*48+c] A[c][d]
// ============================================================
__global__ __launch_bounds__(256) void attn_combine_kernel(
    const float* __restrict__ temperature, const float* __restrict__ P)
{
    const int bh = blockIdx.x;
    const int b = bh >> 2, h = bh & 3;
    __shared__ float S[CH * CH];
    __shared__ float A[CH * CH];
    __shared__ float rq[CH];
    __shared__ float rk[CH];
    const int tid = threadIdx.x;
    const int lane = tid & 31, wid = tid >> 5;

    for (int e = tid; e < CH * CH; e += 256) {
        float s = 0.f;
#pragma unroll
        for (int p = 0; p < NCHUNK; p++)
            s += g_part_gram[((size_t)bh * NCHUNK + p) * CH * CH + e];
        S[e] = s;
    }
    if (tid < CH) {
        float s = 0.f;
#pragma unroll
        for (int p = 0; p < NCHUNK; p++) s += g_part_nq[((size_t)bh * NCHUNK + p) * CH + tid];
        rq[tid] = fmaxf(sqrtf(s), 1e-12f);
    } else if (tid < 2 * CH) {
        float s = 0.f;
#pragma unroll
        for (int p = 0; p < NCHUNK; p++) s += g_part_nk[((size_t)bh * NCHUNK + p) * CH + (tid - CH)];
        rk[tid - CH] = fmaxf(sqrtf(s), 1e-12f);
    }
    __syncthreads();

    // warp w handles rows 6w..6w+5; lanes split 48 cols (lane, lane+32)
    const float tmp = temperature[h];
    const int c2 = lane + 32;
#pragma unroll
    for (int rr = 0; rr < 6; rr++) {
        const int r = wid * 6 + rr;
        const float fq = tmp / rq[r];
        float v1 = S[r * CH + lane] * fq / rk[lane];
        float v2 = (c2 < CH) ? S[r * CH + c2] * fq / rk[c2] : -1e30f;
        float mx = fmaxf(v1, v2);
#pragma unroll
        for (int o = 16; o; o >>= 1) mx = fmaxf(mx, __shfl_xor_sync(0xffffffffu, mx, o));
        float e1 = expf(v1 - mx);
        float e2 = (c2 < CH) ? expf(v2 - mx) : 0.f;
        float sm = e1 + e2;
#pragma unroll
        for (int o = 16; o; o >>= 1) sm += __shfl_xor_sync(0xffffffffu, sm, o);
        float inv = 1.f / sm;
        A[r * CH + lane] = e1 * inv;
        if (c2 < CH) A[r * CH + c2] = e2 * inv;
    }
    __syncthreads();

    // combine: thread m (0..191) computes Comb row m for this head's 48 cols
    if (tid < CDIM) {
        const int m = tid;
        float p[CH];
#pragma unroll
        for (int c = 0; c < CH; c++) p[c] = P[(size_t)m * CDIM + h * CH + c];
        float* outp = g_comb + ((size_t)b * CDIM + m) * CDIM + h * CH;
#pragma unroll 4
        for (int d = 0; d < CH; d++) {
            float s = 0.f;
#pragma unroll
            for (int c = 0; c < CH; c++) s = fmaf(p[c], A[c * CH + d], s);
            outp[d] = s;
        }
    }
}

// ============================================================
extern "C" void kernel_launch(void* const* d_in, const int* in_sizes, int n_in,
                              void* d_out, int out_size)
{
    const float* x      = (const float*)d_in[0];
    const float* qkv_w  = (const float*)d_in[1];
    const float* dw_w   = (const float*)d_in[2];
    const float* proj_w = (const float*)d_in[3];
    const float* temp   = (const float*)d_in[4];
    float* out = (float*)d_out;

    __half *qkv, *qkv2;
    float *comb;
    uint32_t *apq, *apm;
    cudaGetSymbolAddress((void**)&qkv,  g_qkv);
    cudaGetSymbolAddress((void**)&qkv2, g_qkv2);
    cudaGetSymbolAddress((void**)&comb, g_comb);
    cudaGetSymbolAddress((void**)&apq,  g_apq);
    cudaGetSymbolAddress((void**)&apm,  g_apm);

    dim3 blk(256);
    // 0) permute + fp16-convert qkv weights
    prep_a<<<dim3(60, 1), blk>>>(qkv_w, apq, C3, 0, 0);
    // 1) qkv 1x1 conv (fp16 tensor cores, BK=32), fp16 output
    pw_mma<float, __half><<<dim3(5, 128, BATCH), blk>>>(
        apq, 0, x, (size_t)CDIM * HWD, qkv, (size_t)C3 * HWD, C3);
    // 2) depthwise 3x3 (register sliding window), fp16 in/out
    dw_conv_kernel<<<dim3(BATCH * C3, 2), blk>>>(qkv, dw_w, qkv2);
    // 3) Q@K^T partials + free norms (fp16 tensor cores, 1024 blocks)
    gram_kernel<<<dim3(NCHUNK, BATCH * HEADS), blk>>>();
    // 4) softmax + fold into proj weights (fused)
    attn_combine_kernel<<<BATCH * HEADS, blk>>>(temp, proj_w);
    // 5) permute combined weights
    prep_a<<<dim3(24, BATCH), blk>>>(comb, apm, CDIM, (size_t)CDIM * CDIM, 2 * 12288);
    // 6) fused (proj @ attn) @ v -> d_out (fp16 V input, fp32 output)
    pw_mma<__half, float><<<dim3(2, 128, BATCH), blk>>>(
        apm, 2 * 12288, qkv2 + (size_t)2 * CDIM * HWD, (size_t)C3 * HWD,
        out, (size_t)CDIM * HWD, CDIM);
}

// round 13
// speedup vs baseline: 6.0079x; 1.0303x over previous
#include <cuda_runtime.h>
#include <cuda_fp16.h>
#include <math.h>
#include <stdint.h>

#define BATCH 8
#define CDIM 192
#define C3 576
#define HWD 16384
#define HEADS 4
#define CH 48
#define NCHUNK 32
#define CHUNKPX 512

typedef unsigned long long ull;

// ---- fp16 mma m16n8k16, fp32 accumulate ----
__device__ __forceinline__ void mma_f16(float* c, uint4 a, uint2 b) {
    asm volatile(
        "mma.sync.aligned.m16n8k16.row.col.f32.f16.f16.f32 "
        "{%0,%1,%2,%3}, {%4,%5,%6,%7}, {%8,%9}, {%0,%1,%2,%3};"
        : "+f"(c[0]), "+f"(c[1]), "+f"(c[2]), "+f"(c[3])
        : "r"(a.x), "r"(a.y), "r"(a.z), "r"(a.w), "r"(b.x), "r"(b.y));
}
__device__ __forceinline__ uint32_t h2pack(float a, float b) {
    __half2 h = __floats2half2_rn(a, b);
    return *(uint32_t*)&h;
}

// ---- typed 4-element loads / 2-element stores ----
__device__ __forceinline__ float4 load4(const float* p) { return *(const float4*)p; }
__device__ __forceinline__ float4 load4(const __half* p) {
    __half2 h0 = *(const __half2*)p;
    __half2 h1 = *(const __half2*)(p + 2);
    float2 a = __half22float2(h0), b = __half22float2(h1);
    return make_float4(a.x, a.y, b.x, b.y);
}
__device__ __forceinline__ void store2(float* p, float a, float b) {
    *(float2*)p = make_float2(a, b);
}
__device__ __forceinline__ void store2(__half* p, float a, float b) {
    *(__half2*)p = __floats2half2_rn(a, b);
}

// ---- scratch (device globals; no allocations allowed) ----
__device__ __half g_qkv [(size_t)BATCH * C3 * HWD];
__device__ __half g_qkv2[(size_t)BATCH * C3 * HWD];
__device__ float g_part_gram[(size_t)BATCH * HEADS * NCHUNK * CH * CH];
__device__ float g_part_nq  [(size_t)BATCH * HEADS * NCHUNK * CH];
__device__ float g_part_nk  [(size_t)BATCH * HEADS * NCHUNK * CH];
__device__ uint32_t g_apq[5 * 12288];          // qkv W, fp16 fragment-permuted
__device__ uint32_t g_apm[BATCH * 2 * 12288];  // combined proj@attn, per batch

// ============================================================
// Permute W[M,192] into fp16 m16n8k16 fragment order.
// Layout: [mt][k16(12)][m16(8)][lane(32)][reg(4)] half2-packed.
// ============================================================
__global__ __launch_bounds__(256) void prep_a(
    const float* __restrict__ W, uint32_t* __restrict__ Ap, int Mdim)
{
    const int idx = blockIdx.x * 256 + threadIdx.x;
    const int lane = idx & 31;
    int rest = idx >> 5;
    const int m16 = rest & 7; rest >>= 3;
    const int k16 = rest % 12;
    const int mt = rest / 12;
    const int g = lane >> 2, t = lane & 3;
    const int row = mt * 128 + m16 * 16 + g;
    const int k = k16 * 16 + 2 * t;
    float a00 = 0.f, a01 = 0.f, a10 = 0.f, a11 = 0.f;
    float a20 = 0.f, a21 = 0.f, a30 = 0.f, a31 = 0.f;
    if (row < Mdim) {
        const float* wr = W + (size_t)row * CDIM + k;
        a00 = wr[0]; a01 = wr[1]; a20 = wr[8]; a21 = wr[9];
    }
    if (row + 8 < Mdim) {
        const float* wr = W + (size_t)(row + 8) * CDIM + k;
        a10 = wr[0]; a11 = wr[1]; a30 = wr[8]; a31 = wr[9];
    }
    uint4 o;
    o.x = h2pack(a00, a01); o.y = h2pack(a10, a11);
    o.z = h2pack(a20, a21); o.w = h2pack(a30, a31);
    *(uint4*)(Ap + (size_t)idx * 4) = o;
}

// ============================================================
// Pointwise GEMM via mma.sync fp16: Y[b,m,n] = sum_k A[(b),m,k] X[b,k,n]
// 128(M) x 128(N) block, BK=32, double buffered, reg prefetch.
// ============================================================
template <typename InT, typename OutT>
__global__ __launch_bounds__(256) void pw_mma(
    const uint32_t* __restrict__ Ap, size_t a_bstride,
    const InT* __restrict__ X, size_t x_bstride,
    OutT* __restrict__ Y, size_t y_bstride, int Mdim)
{
    __shared__ __align__(16) uint32_t As[2][2048];
    __shared__ __align__(16) uint32_t Bs16[2][16 * 136];
    const int tid = threadIdx.x;
    const int lane = tid & 31, wid = tid >> 5;
    const int mt = blockIdx.x;
    const int n0 = blockIdx.y * 128;
    const size_t boffX = (size_t)blockIdx.z * x_bstride;
    const size_t boffY = (size_t)blockIdx.z * y_bstride;

    const uint32_t* apg = Ap + (size_t)blockIdx.z * a_bstride + (size_t)mt * 12288;
    const int nq = tid & 31;
    const int bk0 = tid >> 5;

    uint4 a_r0, a_r1;
    float4 b_r0, b_r1, b_r2, b_r3;

    auto ldg_iter = [&](int it) {
        a_r0 = *(const uint4*)(apg + (size_t)it * 2048 + (size_t)tid * 4);
        a_r1 = *(const uint4*)(apg + (size_t)it * 2048 + 1024 + (size_t)tid * 4);
        const InT* xb = X + boffX + (size_t)(it * 32 + 2 * bk0) * HWD + n0 + nq * 4;
        b_r0 = load4(xb);
        b_r1 = load4(xb + HWD);
        b_r2 = load4(xb + (size_t)16 * HWD);
        b_r3 = load4(xb + (size_t)17 * HWD);
    };
    auto sts_iter = [&](int buf) {
        *(uint4*)&As[buf][tid * 4] = a_r0;
        *(uint4*)&As[buf][(tid + 256) * 4] = a_r1;
        uint4 p0, p1;
        p0.x = h2pack(b_r0.x, b_r1.x); p0.y = h2pack(b_r0.y, b_r1.y);
        p0.z = h2pack(b_r0.z, b_r1.z); p0.w = h2pack(b_r0.w, b_r1.w);
        p1.x = h2pack(b_r2.x, b_r3.x); p1.y = h2pack(b_r2.y, b_r3.y);
        p1.z = h2pack(b_r2.z, b_r3.z); p1.w = h2pack(b_r2.w, b_r3.w);
        *(uint4*)&Bs16[buf][bk0 * 136 + nq * 4] = p0;
        *(uint4*)&Bs16[buf][(8 + bk0) * 136 + nq * 4] = p1;
    };

    float acc[2][8][4];
#pragma unroll
    for (int f = 0; f < 2; f++)
#pragma unroll
        for (int j = 0; j < 8; j++)
#pragma unroll
            for (int e = 0; e < 4; e++) acc[f][j][e] = 0.f;

    const int m16a = (wid & 3) * 2;
    const int t = lane & 3;
    const int g = lane >> 2;
    const int nwb = (wid >> 2) * 64;

    auto compute = [&](int buf) {
#pragma unroll
        for (int s = 0; s < 2; s++) {
            uint4 A0 = *(const uint4*)&As[buf][(s * 256 + m16a * 32 + lane) * 4];
            uint4 A1 = *(const uint4*)&As[buf][(s * 256 + (m16a + 1) * 32 + lane) * 4];
            const int br0 = (s * 8 + t) * 136 + nwb + g;
            const int br1 = (s * 8 + t + 4) * 136 + nwb + g;
#pragma unroll
            for (int j = 0; j < 8; j++) {
                uint2 b = make_uint2(Bs16[buf][br0 + j * 8], Bs16[buf][br1 + j * 8]);
                mma_f16(acc[0][j], A0, b);
                mma_f16(acc[1][j], A1, b);
            }
        }
    };

    ldg_iter(0);
    sts_iter(0);
    __syncthreads();
#pragma unroll 1
    for (int it = 0; it < 6; it++) {
        if (it + 1 < 6) ldg_iter(it + 1);
        compute(it & 1);
        if (it + 1 < 6) sts_iter((it + 1) & 1);
        __syncthreads();
    }

    const int mw = mt * 128 + (wid & 3) * 32;
#pragma unroll
    for (int f = 0; f < 2; f++) {
        const int m = mw + f * 16 + g;
#pragma unroll
        for (int j = 0; j < 8; j++) {
            OutT* p = Y + boffY + (size_t)m * HWD + n0 + nwb + j * 8 + 2 * t;
            if (m < Mdim)
                store2(p, acc[f][j][0], acc[f][j][1]);
            if (m + 8 < Mdim)
                store2(p + (size_t)8 * HWD, acc[f][j][2], acc[f][j][3]);
        }
    }
}

// ============================================================
// Depthwise 3x3, pad 1 — register sliding window + warp shuffle halos.
// ============================================================
__global__ __launch_bounds__(256) void dw_conv_kernel(
    const __half* __restrict__ in, const float* __restrict__ wts,
    __half* __restrict__ out)
{
    const int bc = blockIdx.x;
    const int c = bc % C3;
    const int warp = threadIdx.x >> 5;
    const int lane = threadIdx.x & 31;
    const int y0 = blockIdx.y * 64 + warp * 8;

    float w[9];
#pragma unroll
    for (int i = 0; i < 9; i++) w[i] = __ldg(wts + c * 9 + i);

    const __half* ip = in + (size_t)bc * HWD + lane * 4;
    float win[3][6];

    auto loadrow = [&](int gy, float* row6) {
        float4 v = make_float4(0.f, 0.f, 0.f, 0.f);
        if (gy >= 0 && gy < 128) v = load4(ip + (size_t)gy * 128);
        float l = __shfl_up_sync(0xffffffffu, v.w, 1);
        float r = __shfl_down_sync(0xffffffffu, v.x, 1);
        if (lane == 0)  l = 0.f;
        if (lane == 31) r = 0.f;
        row6[0] = l; row6[1] = v.x; row6[2] = v.y;
        row6[3] = v.z; row6[4] = v.w; row6[5] = r;
    };

    loadrow(y0 - 1, win[0]);
    loadrow(y0,     win[1]);
    __half* op = out + (size_t)bc * HWD + lane * 4;
#pragma unroll
    for (int r = 0; r < 8; r++) {
        loadrow(y0 + 1 + r, win[(r + 2) % 3]);
        const float* tp = win[r % 3];
        const float* mp = win[(r + 1) % 3];
        const float* bp = win[(r + 2) % 3];
        float o[4];
#pragma unroll
        for (int p = 0; p < 4; p++) {
            float s = 0.f;
            s = fmaf(tp[p], w[0], s); s = fmaf(tp[p + 1], w[1], s); s = fmaf(tp[p + 2], w[2], s);
            s = fmaf(mp[p], w[3], s); s = fmaf(mp[p + 1], w[4], s); s = fmaf(mp[p + 2], w[5], s);
            s = fmaf(bp[p], w[6], s); s = fmaf(bp[p + 1], w[7], s); s = fmaf(bp[p + 2], w[8], s);
            o[p] = s;
        }
        __half2 h0 = __floats2half2_rn(o[0], o[1]);
        __half2 h1 = __floats2half2_rn(o[2], o[3]);
        __half2* dst = (__half2*)(op + (size_t)(y0 + r) * 128);
        dst[0] = h0; dst[1] = h1;
    }
}

// ============================================================
// Gram on fp16 tensor cores: Q@K^T (48x48) per (bh, 512-px chunk).
// Reg-prefetch software pipeline + double-buffered smem.
// Norms accumulate in fp32 regs during the STS phase.
// ============================================================
__global__ __launch_bounds__(256) void gram_kernel()
{
    const int chunk = blockIdx.x;
    const int bh = blockIdx.y;
    const int b = bh >> 2, h = bh & 3;
    const __half* qb = g_qkv2 + ((size_t)b * C3 + h * CH) * HWD;
    const __half* kb = g_qkv2 + ((size_t)b * C3 + CDIM + h * CH) * HWD;
    __shared__ __align__(16) uint32_t Qs[2][CH][36];
    __shared__ __align__(16) uint32_t Ks[2][CH][36];
    __shared__ float redq[CH][16];
    __shared__ float redk[CH][16];
    const int tid = threadIdx.x;
    const int lane = tid & 31, wid = tid >> 5;
    const int n0 = chunk * CHUNKPX;

    float acc[3][4];
#pragma unroll
    for (int jj = 0; jj < 3; jj++)
#pragma unroll
        for (int e = 0; e < 4; e++) acc[jj][e] = 0.f;
    float nq[3] = {0.f, 0.f, 0.f};
    float nk[3] = {0.f, 0.f, 0.f};

    const int mrow = wid % 3;
    const int nhalf = (wid < 6) ? (wid / 3) : 0;
    const int g = lane >> 2, t = lane & 3;
    const int lrow0 = tid >> 4;
    const int lcolq = tid & 15;

    float4 qv[3], kv[3];
    auto ldg_tile = [&](int t0) {
#pragma unroll
        for (int i = 0; i < 3; i++) {
            const int row = lrow0 + i * 16;
            qv[i] = load4(qb + (size_t)row * HWD + n0 + t0 + lcolq * 4);
            kv[i] = load4(kb + (size_t)row * HWD + n0 + t0 + lcolq * 4);
        }
    };
    auto sts_tile = [&](int buf) {
#pragma unroll
        for (int i = 0; i < 3; i++) {
            const int row = lrow0 + i * 16;
            *(uint2*)&Qs[buf][row][lcolq * 2] =
                make_uint2(h2pack(qv[i].x, qv[i].y), h2pack(qv[i].z, qv[i].w));
            nq[i] = fmaf(qv[i].x, qv[i].x, nq[i]); nq[i] = fmaf(qv[i].y, qv[i].y, nq[i]);
            nq[i] = fmaf(qv[i].z, qv[i].z, nq[i]); nq[i] = fmaf(qv[i].w, qv[i].w, nq[i]);
            *(uint2*)&Ks[buf][row][lcolq * 2] =
                make_uint2(h2pack(kv[i].x, kv[i].y), h2pack(kv[i].z, kv[i].w));
            nk[i] = fmaf(kv[i].x, kv[i].x, nk[i]); nk[i] = fmaf(kv[i].y, kv[i].y, nk[i]);
            nk[i] = fmaf(kv[i].z, kv[i].z, nk[i]); nk[i] = fmaf(kv[i].w, kv[i].w, nk[i]);
        }
    };

    const int NTILE = CHUNKPX / 64;
    ldg_tile(0);
    sts_tile(0);
    __syncthreads();
#pragma unroll 1
    for (int ti = 0; ti < NTILE; ti++) {
        if (ti + 1 < NTILE) ldg_tile((ti + 1) * 64);
        if (wid < 6) {
            const int buf = ti & 1;
            const int mr = 16 * mrow + g;
#pragma unroll
            for (int s = 0; s < 4; s++) {
                const int base = s * 8;
                uint4 a;
                a.x = Qs[buf][mr][base + t];
                a.y = Qs[buf][mr + 8][base + t];
                a.z = Qs[buf][mr][base + t + 4];
                a.w = Qs[buf][mr + 8][base + t + 4];
#pragma unroll
                for (int jj = 0; jj < 3; jj++) {
                    const int nr = 8 * (3 * nhalf + jj) + g;
                    uint2 bf = make_uint2(Ks[buf][nr][base + t], Ks[buf][nr][base + t + 4]);
                    mma_f16(acc[jj], a, bf);
                }
            }
        }
        if (ti + 1 < NTILE) sts_tile((ti + 1) & 1);
        __syncthreads();
    }

    redq[lrow0][lcolq] = nq[0]; redq[lrow0 + 16][lcolq] = nq[1]; redq[lrow0 + 32][lcolq] = nq[2];
    redk[lrow0][lcolq] = nk[0]; redk[lrow0 + 16][lcolq] = nk[1]; redk[lrow0 + 32][lcolq] = nk[2];
    __syncthreads();
    if (tid < CH) {
        float s = 0.f;
#pragma unroll
        for (int q = 0; q < 16; q++) s += redq[tid][q];
        g_part_nq[((size_t)bh * NCHUNK + chunk) * CH + tid] = s;
    } else if (tid < 2 * CH) {
        float s = 0.f;
#pragma unroll
        for (int q = 0; q < 16; q++) s += redk[tid - CH][q];
        g_part_nk[((size_t)bh * NCHUNK + chunk) * CH + (tid - CH)] = s;
    }

    if (wid < 6) {
        float* gp = g_part_gram + ((size_t)bh * NCHUNK + chunk) * CH * CH;
        const int m = 16 * mrow + g;
#pragma unroll
        for (int jj = 0; jj < 3; jj++) {
            const int n = 8 * (3 * nhalf + jj) + 2 * t;
            *(float2*)&gp[m * CH + n] = make_float2(acc[jj][0], acc[jj][1]);
            *(float2*)&gp[(m + 8) * CH + n] = make_float2(acc[jj][2], acc[jj][3]);
        }
    }
}

// ============================================================
// Fused: reduce partials -> normalize -> softmax -> combine with proj
// -> emit fragment-permuted fp16 apm DIRECTLY (no g_comb, no prep pass).
// Block = (b,h). apm layout: [b][mt][k16][m16][lane][reg] half2 k-pairs.
// ============================================================
__global__ __launch_bounds__(256) void attn_combine_kernel(
    const float* __restrict__ temperature, const float* __restrict__ P,
    uint32_t* __restrict__ apm)
{
    const int bh = blockIdx.x;
    const int b = bh >> 2, h = bh & 3;
    __shared__ float S[CH * CH];
    __shared__ float A[CH * CH];
    __shared__ float rq[CH];
    __shared__ float rk[CH];
    const int tid = threadIdx.x;
    const int lane = tid & 31, wid = tid >> 5;

    for (int e = tid; e < CH * CH; e += 256) {
        float s = 0.f;
#pragma unroll
        for (int p = 0; p < NCHUNK; p++)
            s += g_part_gram[((size_t)bh * NCHUNK + p) * CH * CH + e];
        S[e] = s;
    }
    if (tid < CH) {
        float s = 0.f;
#pragma unroll
        for (int p = 0; p < NCHUNK; p++) s += g_part_nq[((size_t)bh * NCHUNK + p) * CH + tid];
        rq[tid] = fmaxf(sqrtf(s), 1e-12f);
    } else if (tid < 2 * CH) {
        float s = 0.f;
#pragma unroll
        for (int p = 0; p < NCHUNK; p++) s += g_part_nk[((size_t)bh * NCHUNK + p) * CH + (tid - CH)];
        rk[tid - CH] = fmaxf(sqrtf(s), 1e-12f);
    }
    __syncthreads();

    // warp-parallel softmax: warp w -> rows 6w..6w+5, lanes split 48 cols
    const float tmp = temperature[h];
    const int c2 = lane + 32;
#pragma unroll
    for (int rr = 0; rr < 6; rr++) {
        const int r = wid * 6 + rr;
        const float fq = tmp / rq[r];
        float v1 = S[r * CH + lane] * fq / rk[lane];
        float v2 = (c2 < CH) ? S[r * CH + c2] * fq / rk[c2] : -1e30f;
        float mx = fmaxf(v1, v2);
#pragma unroll
        for (int o = 16; o; o >>= 1) mx = fmaxf(mx, __shfl_xor_sync(0xffffffffu, mx, o));
        float e1 = expf(v1 - mx);
        float e2 = (c2 < CH) ? expf(v2 - mx) : 0.f;
        float sm = e1 + e2;
#pragma unroll
        for (int o = 16; o; o >>= 1) sm += __shfl_xor_sync(0xffffffffu, sm, o);
        float inv = 1.f / sm;
        A[r * CH + lane] = e1 * inv;
        if (c2 < CH) A[r * CH + c2] = e2 * inv;
    }
    __syncthreads();

    // combine + permute: thread m computes Comb row m for head h's 48 cols,
    // packs k-pairs to fp16 and scatters into mma fragment layout.
    if (tid < CDIM) {
        const int m = tid;
        float p[CH];
#pragma unroll
        for (int c = 0; c < CH; c++) p[c] = P[(size_t)m * CDIM + h * CH + c];
        float o[CH];
#pragma unroll 4
        for (int d = 0; d < CH; d++) {
            float s = 0.f;
#pragma unroll
            for (int c = 0; c < CH; c++) s = fmaf(p[c], A[c * CH + d], s);
            o[d] = s;
        }
        const int mt = m >> 7;
        const int m16 = (m & 127) >> 4;
        const int gg = m & 7;
        const int hi = (m & 15) >> 3;          // 0 -> regs x/z, 1 -> regs y/w
        uint32_t* base = apm + (size_t)b * 24576 + mt * 12288 + m16 * 128;
#pragma unroll
        for (int d2 = 0; d2 < CH / 2; d2++) {
            const int k = h * CH + 2 * d2;
            const int k16 = k >> 4;
            const int rem = k & 15;
            const int t = (rem & 7) >> 1;
            const int reg = (rem >> 3) * 2 + hi;
            base[k16 * 1024 + (gg * 4 + t) * 4 + reg] = h2pack(o[2 * d2], o[2 * d2 + 1]);
        }
    }
}

// ============================================================
extern "C" void kernel_launch(void* const* d_in, const int* in_sizes, int n_in,
                              void* d_out, int out_size)
{
    const float* x      = (const float*)d_in[0];
    const float* qkv_w  = (const float*)d_in[1];
    const float* dw_w   = (const float*)d_in[2];
    const float* proj_w = (const float*)d_in[3];
    const float* temp   = (const float*)d_in[4];
    float* out = (float*)d_out;

    __half *qkv, *qkv2;
    uint32_t *apq, *apm;
    cudaGetSymbolAddress((void**)&qkv,  g_qkv);
    cudaGetSymbolAddress((void**)&qkv2, g_qkv2);
    cudaGetSymbolAddress((void**)&apq,  g_apq);
    cudaGetSymbolAddress((void**)&apm,  g_apm);

    dim3 blk(256);
    // 0) permute + fp16-convert qkv weights
    prep_a<<<60, blk>>>(qkv_w, apq, C3);
    // 1) qkv 1x1 conv (fp16 tensor cores, BK=32), fp16 output
    pw_mma<float, __half><<<dim3(5, 128, BATCH), blk>>>(
        apq, 0, x, (size_t)CDIM * HWD, qkv, (size_t)C3 * HWD, C3);
    // 2) depthwise 3x3 (register sliding window), fp16 in/out
    dw_conv_kernel<<<dim3(BATCH * C3, 2), blk>>>(qkv, dw_w, qkv2);
    // 3) Q@K^T partials + norms (fp16 tensor cores, pipelined)
    gram_kernel<<<dim3(NCHUNK, BATCH * HEADS), blk>>>();
    // 4) softmax + fold into proj weights + fragment-permute (fused)
    attn_combine_kernel<<<BATCH * HEADS, blk>>>(temp, proj_w, apm);
    // 5) fused (proj @ attn) @ v -> d_out (fp16 V input, fp32 output)
    pw_mma<__half, float><<<dim3(2, 128, BATCH), blk>>>(
        apm, 24576, qkv2 + (size_t)2 * CDIM * HWD, (size_t)C3 * HWD,
        out, (size_t)CDIM * HWD, CDIM);
}

// round 14
// speedup vs baseline: 6.2272x; 1.0365x over previous
#include <cuda_runtime.h>
#include <cuda_fp16.h>
#include <math.h>
#include <stdint.h>

#define BATCH 8
#define CDIM 192
#define C3 576
#define HWD 16384
#define HEADS 4
#define CH 48
#define NCHUNK 32
#define CHUNKPX 512

typedef unsigned long long ull;

// ---- fp16 mma m16n8k16, fp32 accumulate ----
__device__ __forceinline__ void mma_f16(float* c, uint4 a, uint2 b) {
    asm volatile(
        "mma.sync.aligned.m16n8k16.row.col.f32.f16.f16.f32 "
        "{%0,%1,%2,%3}, {%4,%5,%6,%7}, {%8,%9}, {%0,%1,%2,%3};"
        : "+f"(c[0]), "+f"(c[1]), "+f"(c[2]), "+f"(c[3])
        : "r"(a.x), "r"(a.y), "r"(a.z), "r"(a.w), "r"(b.x), "r"(b.y));
}
__device__ __forceinline__ uint32_t h2pack(float a, float b) {
    __half2 h = __floats2half2_rn(a, b);
    return *(uint32_t*)&h;
}

// ---- cp.async helpers (sm_80 baseline; fine on compute_103) ----
__device__ __forceinline__ void cp16(void* dst, const void* src) {
    uint32_t d;
    asm("{ .reg .u64 t; cvta.to.shared.u64 t, %1; cvt.u32.u64 %0, t; }" : "=r"(d) : "l"(dst));
    asm volatile("cp.async.cg.shared.global [%0], [%1], 16;" :: "r"(d), "l"(src) : "memory");
}
#define CP_COMMIT() asm volatile("cp.async.commit_group;" ::: "memory")
#define CP_WAIT(n)  asm volatile("cp.async.wait_group %0;" :: "n"(n) : "memory")

// ---- typed 4-element loads / 2-element stores ----
__device__ __forceinline__ float4 load4(const float* p) { return *(const float4*)p; }
__device__ __forceinline__ float4 load4(const __half* p) {
    __half2 h0 = *(const __half2*)p;
    __half2 h1 = *(const __half2*)(p + 2);
    float2 a = __half22float2(h0), b = __half22float2(h1);
    return make_float4(a.x, a.y, b.x, b.y);
}
__device__ __forceinline__ void store2(float* p, float a, float b) {
    *(float2*)p = make_float2(a, b);
}
__device__ __forceinline__ void store2(__half* p, float a, float b) {
    *(__half2*)p = __floats2half2_rn(a, b);
}

// ---- scratch (device globals; no allocations allowed) ----
__device__ __half g_qkv [(size_t)BATCH * C3 * HWD];
__device__ __half g_qkv2[(size_t)BATCH * C3 * HWD];
__device__ float g_part_gram[(size_t)BATCH * HEADS * NCHUNK * CH * CH];
__device__ float g_norm_part[(size_t)BATCH * C3 * 2];   // per (b,c): 2 block partials
__device__ uint32_t g_apq[5 * 12288];          // qkv W, fp16 fragment-permuted
__device__ uint32_t g_apm[BATCH * 2 * 12288];  // combined proj@attn, per batch

// ============================================================
// Permute W[M,192] into fp16 m16n8k16 fragment order.
// ============================================================
__global__ __launch_bounds__(256) void prep_a(
    const float* __restrict__ W, uint32_t* __restrict__ Ap, int Mdim)
{
    const int idx = blockIdx.x * 256 + threadIdx.x;
    const int lane = idx & 31;
    int rest = idx >> 5;
    const int m16 = rest & 7; rest >>= 3;
    const int k16 = rest % 12;
    const int mt = rest / 12;
    const int g = lane >> 2, t = lane & 3;
    const int row = mt * 128 + m16 * 16 + g;
    const int k = k16 * 16 + 2 * t;
    float a00 = 0.f, a01 = 0.f, a10 = 0.f, a11 = 0.f;
    float a20 = 0.f, a21 = 0.f, a30 = 0.f, a31 = 0.f;
    if (row < Mdim) {
        const float* wr = W + (size_t)row * CDIM + k;
        a00 = wr[0]; a01 = wr[1]; a20 = wr[8]; a21 = wr[9];
    }
    if (row + 8 < Mdim) {
        const float* wr = W + (size_t)(row + 8) * CDIM + k;
        a10 = wr[0]; a11 = wr[1]; a30 = wr[8]; a31 = wr[9];
    }
    uint4 o;
    o.x = h2pack(a00, a01); o.y = h2pack(a10, a11);
    o.z = h2pack(a20, a21); o.w = h2pack(a30, a31);
    *(uint4*)(Ap + (size_t)idx * 4) = o;
}

// ============================================================
// Pointwise GEMM via mma.sync fp16: Y[b,m,n] = sum_k A[(b),m,k] X[b,k,n]
// 128x128 block, BK=32, double buffered; A tile staged via cp.async.
// ============================================================
template <typename InT, typename OutT>
__global__ __launch_bounds__(256) void pw_mma(
    const uint32_t* __restrict__ Ap, size_t a_bstride,
    const InT* __restrict__ X, size_t x_bstride,
    OutT* __restrict__ Y, size_t y_bstride, int Mdim)
{
    __shared__ __align__(16) uint32_t As[2][2048];
    __shared__ __align__(16) uint32_t Bs16[2][16 * 136];
    const int tid = threadIdx.x;
    const int lane = tid & 31, wid = tid >> 5;
    const int mt = blockIdx.x;
    const int n0 = blockIdx.y * 128;
    const size_t boffX = (size_t)blockIdx.z * x_bstride;
    const size_t boffY = (size_t)blockIdx.z * y_bstride;

    const uint32_t* apg = Ap + (size_t)blockIdx.z * a_bstride + (size_t)mt * 12288;
    const int nq = tid & 31;
    const int bk0 = tid >> 5;

    float4 b_r0, b_r1, b_r2, b_r3;

    auto cpa_iter = [&](int it, int buf) {
        const uint32_t* ap = apg + (size_t)it * 2048 + tid * 8;
        cp16(&As[buf][tid * 8], ap);
        cp16(&As[buf][tid * 8 + 4], ap + 4);
    };
    auto ldgb_iter = [&](int it) {
        const InT* xb = X + boffX + (size_t)(it * 32 + 2 * bk0) * HWD + n0 + nq * 4;
        b_r0 = load4(xb);
        b_r1 = load4(xb + HWD);
        b_r2 = load4(xb + (size_t)16 * HWD);
        b_r3 = load4(xb + (size_t)17 * HWD);
    };
    auto stsb_iter = [&](int buf) {
        uint4 p0, p1;
        p0.x = h2pack(b_r0.x, b_r1.x); p0.y = h2pack(b_r0.y, b_r1.y);
        p0.z = h2pack(b_r0.z, b_r1.z); p0.w = h2pack(b_r0.w, b_r1.w);
        p1.x = h2pack(b_r2.x, b_r3.x); p1.y = h2pack(b_r2.y, b_r3.y);
        p1.z = h2pack(b_r2.z, b_r3.z); p1.w = h2pack(b_r2.w, b_r3.w);
        *(uint4*)&Bs16[buf][bk0 * 136 + nq * 4] = p0;
        *(uint4*)&Bs16[buf][(8 + bk0) * 136 + nq * 4] = p1;
    };

    float acc[2][8][4];
#pragma unroll
    for (int f = 0; f < 2; f++)
#pragma unroll
        for (int j = 0; j < 8; j++)
#pragma unroll
            for (int e = 0; e < 4; e++) acc[f][j][e] = 0.f;

    const int m16a = (wid & 3) * 2;
    const int t = lane & 3;
    const int g = lane >> 2;
    const int nwb = (wid >> 2) * 64;

    auto compute = [&](int buf) {
#pragma unroll
        for (int s = 0; s < 2; s++) {
            uint4 A0 = *(const uint4*)&As[buf][(s * 256 + m16a * 32 + lane) * 4];
            uint4 A1 = *(const uint4*)&As[buf][(s * 256 + (m16a + 1) * 32 + lane) * 4];
            const int br0 = (s * 8 + t) * 136 + nwb + g;
            const int br1 = (s * 8 + t + 4) * 136 + nwb + g;
#pragma unroll
            for (int j = 0; j < 8; j++) {
                uint2 b = make_uint2(Bs16[buf][br0 + j * 8], Bs16[buf][br1 + j * 8]);
                mma_f16(acc[0][j], A0, b);
                mma_f16(acc[1][j], A1, b);
            }
        }
    };

    cpa_iter(0, 0);
    ldgb_iter(0);
    CP_COMMIT();
    stsb_iter(0);
    CP_WAIT(0);
    __syncthreads();
#pragma unroll 1
    for (int it = 0; it < 6; it++) {
        if (it + 1 < 6) {
            cpa_iter(it + 1, (it + 1) & 1);
            ldgb_iter(it + 1);
            CP_COMMIT();
        }
        compute(it & 1);
        if (it + 1 < 6) stsb_iter((it + 1) & 1);
        CP_WAIT(0);
        __syncthreads();
    }

    const int mw = mt * 128 + (wid & 3) * 32;
#pragma unroll
    for (int f = 0; f < 2; f++) {
        const int m = mw + f * 16 + g;
#pragma unroll
        for (int j = 0; j < 8; j++) {
            OutT* p = Y + boffY + (size_t)m * HWD + n0 + nwb + j * 8 + 2 * t;
            if (m < Mdim)
                store2(p, acc[f][j][0], acc[f][j][1]);
            if (m + 8 < Mdim)
                store2(p + (size_t)8 * HWD, acc[f][j][2], acc[f][j][3]);
        }
    }
}

// ============================================================
// Depthwise 3x3, pad 1 — register sliding window + shuffle halos.
// Also emits per-channel sum-of-squares partials (fp32, deterministic)
// for the L2 norms of Q/K channels (c < 384).
// ============================================================
__global__ __launch_bounds__(256) void dw_conv_kernel(
    const __half* __restrict__ in, const float* __restrict__ wts,
    __half* __restrict__ out)
{
    const int bc = blockIdx.x;
    const int c = bc % C3;
    const int warp = threadIdx.x >> 5;
    const int lane = threadIdx.x & 31;
    const int y0 = blockIdx.y * 64 + warp * 8;

    float w[9];
#pragma unroll
    for (int i = 0; i < 9; i++) w[i] = __ldg(wts + c * 9 + i);

    const __half* ip = in + (size_t)bc * HWD + lane * 4;
    float win[3][6];

    auto loadrow = [&](int gy, float* row6) {
        float4 v = make_float4(0.f, 0.f, 0.f, 0.f);
        if (gy >= 0 && gy < 128) v = load4(ip + (size_t)gy * 128);
        float l = __shfl_up_sync(0xffffffffu, v.w, 1);
        float r = __shfl_down_sync(0xffffffffu, v.x, 1);
        if (lane == 0)  l = 0.f;
        if (lane == 31) r = 0.f;
        row6[0] = l; row6[1] = v.x; row6[2] = v.y;
        row6[3] = v.z; row6[4] = v.w; row6[5] = r;
    };

    loadrow(y0 - 1, win[0]);
    loadrow(y0,     win[1]);
    __half* op = out + (size_t)bc * HWD + lane * 4;
    float ns = 0.f;
#pragma unroll
    for (int r = 0; r < 8; r++) {
        loadrow(y0 + 1 + r, win[(r + 2) % 3]);
        const float* tp = win[r % 3];
        const float* mp = win[(r + 1) % 3];
        const float* bp = win[(r + 2) % 3];
        float o[4];
#pragma unroll
        for (int p = 0; p < 4; p++) {
            float s = 0.f;
            s = fmaf(tp[p], w[0], s); s = fmaf(tp[p + 1], w[1], s); s = fmaf(tp[p + 2], w[2], s);
            s = fmaf(mp[p], w[3], s); s = fmaf(mp[p + 1], w[4], s); s = fmaf(mp[p + 2], w[5], s);
            s = fmaf(bp[p], w[6], s); s = fmaf(bp[p + 1], w[7], s); s = fmaf(bp[p + 2], w[8], s);
            o[p] = s;
            ns = fmaf(s, s, ns);
        }
        __half2 h0 = __floats2half2_rn(o[0], o[1]);
        __half2 h1 = __floats2half2_rn(o[2], o[3]);
        __half2* dst = (__half2*)(op + (size_t)(y0 + r) * 128);
        dst[0] = h0; dst[1] = h1;
    }

    // deterministic block reduction of sum-of-squares (Q/K channels only)
    if (c < 2 * CDIM) {
        __shared__ float red[8];
#pragma unroll
        for (int o = 16; o; o >>= 1) ns += __shfl_xor_sync(0xffffffffu, ns, o);
        if (lane == 0) red[warp] = ns;
        __syncthreads();
        if (threadIdx.x == 0) {
            float s = 0.f;
#pragma unroll
            for (int i = 0; i < 8; i++) s += red[i];
            g_norm_part[(size_t)bc * 2 + blockIdx.y] = s;
        }
    }
}

// ============================================================
// Gram on fp16 tensor cores: Q@K^T (48x48) per (bh, 512-px chunk).
// k = pixel dim -> half2 pairs contiguous in gmem: cp.async raw copies,
// zero registers, double-buffered. No norm work (lives in dw_conv).
// ============================================================
__global__ __launch_bounds__(256) void gram_kernel()
{
    const int chunk = blockIdx.x;
    const int bh = blockIdx.y;
    const int b = bh >> 2, h = bh & 3;
    const __half* qb = g_qkv2 + ((size_t)b * C3 + h * CH) * HWD;
    const __half* kb = g_qkv2 + ((size_t)b * C3 + CDIM + h * CH) * HWD;
    __shared__ __align__(16) __half Qs[2][CH][72];   // 64 px + 8 pad halfs
    __shared__ __align__(16) __half Ks[2][CH][72];
    const int tid = threadIdx.x;
    const int lane = tid & 31, wid = tid >> 5;
    const int n0 = chunk * CHUNKPX;

    float acc[3][4];
#pragma unroll
    for (int jj = 0; jj < 3; jj++)
#pragma unroll
        for (int e = 0; e < 4; e++) acc[jj][e] = 0.f;

    const int mrow = wid % 3;
    const int nhalf = (wid < 6) ? (wid / 3) : 0;
    const int g = lane >> 2, t = lane & 3;

    const __half* sbase = (tid < 128) ? qb : kb;
    const int st = tid & 127;

    auto stage = [&](int t0, int buf) {
        __half (*dst)[72] = (tid < 128) ? Qs[buf] : Ks[buf];
#pragma unroll
        for (int i = 0; i < 3; i++) {
            int idx = i * 128 + st;
            int row = idx >> 3, cg = idx & 7;
            cp16(&dst[row][cg * 8], sbase + (size_t)row * HWD + n0 + t0 + cg * 8);
        }
    };

    const int NTILE = CHUNKPX / 64;
    stage(0, 0);
    CP_COMMIT();
#pragma unroll 1
    for (int ti = 0; ti < NTILE; ti++) {
        if (ti + 1 < NTILE) {
            stage((ti + 1) * 64, (ti + 1) & 1);
            CP_COMMIT();
            CP_WAIT(1);
        } else {
            CP_WAIT(0);
        }
        __syncthreads();
        if (wid < 6) {
            const int buf = ti & 1;
            const int mr = 16 * mrow + g;
#pragma unroll
            for (int s = 0; s < 4; s++) {
                const int kh = s * 16 + 2 * t;       // half index within tile
                uint4 a;
                a.x = *(const uint32_t*)&Qs[buf][mr][kh];
                a.y = *(const uint32_t*)&Qs[buf][mr + 8][kh];
                a.z = *(const uint32_t*)&Qs[buf][mr][kh + 8];
                a.w = *(const uint32_t*)&Qs[buf][mr + 8][kh + 8];
#pragma unroll
                for (int jj = 0; jj < 3; jj++) {
                    const int nr = 8 * (3 * nhalf + jj) + g;
                    uint2 bf = make_uint2(*(const uint32_t*)&Ks[buf][nr][kh],
                                          *(const uint32_t*)&Ks[buf][nr][kh + 8]);
                    mma_f16(acc[jj], a, bf);
                }
            }
        }
        __syncthreads();
    }

    if (wid < 6) {
        float* gp = g_part_gram + ((size_t)bh * NCHUNK + chunk) * CH * CH;
        const int m = 16 * mrow + g;
#pragma unroll
        for (int jj = 0; jj < 3; jj++) {
            const int n = 8 * (3 * nhalf + jj) + 2 * t;
            *(float2*)&gp[m * CH + n] = make_float2(acc[jj][0], acc[jj][1]);
            *(float2*)&gp[(m + 8) * CH + n] = make_float2(acc[jj][2], acc[jj][3]);
        }
    }
}

// ============================================================
// Fused: reduce partials -> normalize -> softmax -> combine with proj
// -> emit fragment-permuted fp16 apm directly.
// ============================================================
__global__ __launch_bounds__(256) void attn_combine_kernel(
    const float* __restrict__ temperature, const float* __restrict__ P,
    uint32_t* __restrict__ apm)
{
    const int bh = blockIdx.x;
    const int b = bh >> 2, h = bh & 3;
    __shared__ float S[CH * CH];
    __shared__ float A[CH * CH];
    __shared__ float rq[CH];
    __shared__ float rk[CH];
    const int tid = threadIdx.x;
    const int lane = tid & 31, wid = tid >> 5;

    for (int e = tid; e < CH * CH; e += 256) {
        float s = 0.f;
#pragma unroll
        for (int p = 0; p < NCHUNK; p++)
            s += g_part_gram[((size_t)bh * NCHUNK + p) * CH * CH + e];
        S[e] = s;
    }
    if (tid < CH) {
        const size_t cc = (size_t)(b * C3 + h * CH + tid) * 2;
        rq[tid] = fmaxf(sqrtf(g_norm_part[cc] + g_norm_part[cc + 1]), 1e-12f);
    } else if (tid < 2 * CH) {
        const size_t cc = (size_t)(b * C3 + CDIM + h * CH + (tid - CH)) * 2;
        rk[tid - CH] = fmaxf(sqrtf(g_norm_part[cc] + g_norm_part[cc + 1]), 1e-12f);
    }
    __syncthreads();

    // warp-parallel softmax: warp w -> rows 6w..6w+5, lanes split 48 cols
    const float tmp = temperature[h];
    const int c2 = lane + 32;
#pragma unroll
    for (int rr = 0; rr < 6; rr++) {
        const int r = wid * 6 + rr;
        const float fq = tmp / rq[r];
        float v1 = S[r * CH + lane] * fq / rk[lane];
        float v2 = (c2 < CH) ? S[r * CH + c2] * fq / rk[c2] : -1e30f;
        float mx = fmaxf(v1, v2);
#pragma unroll
        for (int o = 16; o; o >>= 1) mx = fmaxf(mx, __shfl_xor_sync(0xffffffffu, mx, o));
        float e1 = expf(v1 - mx);
        float e2 = (c2 < CH) ? expf(v2 - mx) : 0.f;
        float sm = e1 + e2;
#pragma unroll
        for (int o = 16; o; o >>= 1) sm += __shfl_xor_sync(0xffffffffu, sm, o);
        float inv = 1.f / sm;
        A[r * CH + lane] = e1 * inv;
        if (c2 < CH) A[r * CH + c2] = e2 * inv;
    }
    __syncthreads();

    // combine + permute: thread m computes Comb row m for head h's 48 cols,
    // packs k-pairs to fp16 and scatters into mma fragment layout.
    if (tid < CDIM) {
        const int m = tid;
        float p[CH];
#pragma unroll
        for (int c = 0; c < CH; c++) p[c] = P[(size_t)m * CDIM + h * CH + c];
        float o[CH];
#pragma unroll 4
        for (int d = 0; d < CH; d++) {
            float s = 0.f;
#pragma unroll
            for (int c = 0; c < CH; c++) s = fmaf(p[c], A[c * CH + d], s);
            o[d] = s;
        }
        const int mt = m >> 7;
        const int m16 = (m & 127) >> 4;
        const int gg = m & 7;
        const int hi = (m & 15) >> 3;
        uint32_t* base = apm + (size_t)b * 24576 + mt * 12288 + m16 * 128;
#pragma unroll
        for (int d2 = 0; d2 < CH / 2; d2++) {
            const int k = h * CH + 2 * d2;
            const int k16 = k >> 4;
            const int rem = k & 15;
            const int t = (rem & 7) >> 1;
            const int reg = (rem >> 3) * 2 + hi;
            base[k16 * 1024 + (gg * 4 + t) * 4 + reg] = h2pack(o[2 * d2], o[2 * d2 + 1]);
        }
    }
}

// ============================================================
extern "C" void kernel_launch(void* const* d_in, const int* in_sizes, int n_in,
                              void* d_out, int out_size)
{
    const float* x      = (const float*)d_in[0];
    const float* qkv_w  = (const float*)d_in[1];
    const float* dw_w   = (const float*)d_in[2];
    const float* proj_w = (const float*)d_in[3];
    const float* temp   = (const float*)d_in[4];
    float* out = (float*)d_out;

    __half *qkv, *qkv2;
    uint32_t *apq, *apm;
    cudaGetSymbolAddress((void**)&qkv,  g_qkv);
    cudaGetSymbolAddress((void**)&qkv2, g_qkv2);
    cudaGetSymbolAddress((void**)&apq,  g_apq);
    cudaGetSymbolAddress((void**)&apm,  g_apm);

    dim3 blk(256);
    // 0) permute + fp16-convert qkv weights
    prep_a<<<60, blk>>>(qkv_w, apq, C3);
    // 1) qkv 1x1 conv (fp16 tensor cores, cp.async A)
    pw_mma<float, __half><<<dim3(5, 128, BATCH), blk>>>(
        apq, 0, x, (size_t)CDIM * HWD, qkv, (size_t)C3 * HWD, C3);
    // 2) depthwise 3x3 + Q/K norm partials
    dw_conv_kernel<<<dim3(BATCH * C3, 2), blk>>>(qkv, dw_w, qkv2);
    // 3) Q@K^T partials (fp16 tensor cores, cp.async staging)
    gram_kernel<<<dim3(NCHUNK, BATCH * HEADS), blk>>>();
    // 4) softmax + fold into proj weights + fragment-permute (fused)
    attn_combine_kernel<<<BATCH * HEADS, blk>>>(temp, proj_w, apm);
    // 5) fused (proj @ attn) @ v -> d_out
    pw_mma<__half, float><<<dim3(2, 128, BATCH), blk>>>(
        apm, 24576, qkv2 + (size_t)2 * CDIM * HWD, (size_t)C3 * HWD,
        out, (size_t)CDIM * HWD, CDIM);
}